// round 2
// baseline (speedup 1.0000x reference)
#include <cuda_runtime.h>
#include <cuda_bf16.h>
#include <cstdint>

// Problem constants (fixed shapes from reference)
#define BATCH 2
#define SEQ 2048
#define IN_DIM 1024
#define HID_DIM 1024
#define NHEAD 16
#define HDIM 64

// Scratch (allocation-free rule: __device__ globals)
__device__ float g_Q[BATCH * SEQ * HID_DIM];   // 16 MB
__device__ float g_K[BATCH * SEQ * HDIM];      // 1 MB
__device__ float g_V[BATCH * SEQ * HDIM];      // 1 MB
__device__ float g_O[BATCH * SEQ * HID_DIM];   // 16 MB

// ---------------------------------------------------------------------------
// Generic tiled fp32 GEMM with bias: C[M,N] = A[M,K] @ B[K,N] + bias[N]
// A row-major, B row-major. M%BM==0, N%BN==0, K%BK==0 (true for our shapes).
// ---------------------------------------------------------------------------
template <int BM, int BN, int BK, int TM, int TN>
__global__ __launch_bounds__(256) void gemm_bias_kernel(
    const float* __restrict__ A, const float* __restrict__ B,
    const float* __restrict__ bias, float* __restrict__ C,
    int M, int N, int K)
{
    static_assert((BM / TM) * (BN / TN) == 256, "256 threads");
    __shared__ float As[BK][BM + 4];
    __shared__ float Bs[BK][BN];

    const int tid = threadIdx.x;
    const int tx = tid % (BN / TN);
    const int ty = tid / (BN / TN);
    const int m0 = blockIdx.y * BM;
    const int n0 = blockIdx.x * BN;

    // A tile loading: BM*BK floats as float4 along K
    constexpr int A_THREADS = BM * BK / 4;
    const int ar = tid / (BK / 4);
    const int ac = (tid % (BK / 4)) * 4;
    // B tile loading: BK*BN floats as float4 along N
    constexpr int B_THREADS = BK * BN / 4;
    const int br = tid / (BN / 4);
    const int bc = (tid % (BN / 4)) * 4;

    float acc[TM][TN] = {};

    for (int k0 = 0; k0 < K; k0 += BK) {
        if (tid < A_THREADS) {
            float4 v = *(const float4*)(A + (size_t)(m0 + ar) * K + k0 + ac);
            As[ac + 0][ar] = v.x;
            As[ac + 1][ar] = v.y;
            As[ac + 2][ar] = v.z;
            As[ac + 3][ar] = v.w;
        }
        if (tid < B_THREADS) {
            *(float4*)&Bs[br][bc] = *(const float4*)(B + (size_t)(k0 + br) * N + n0 + bc);
        }
        __syncthreads();

#pragma unroll
        for (int kk = 0; kk < BK; kk++) {
            float a[TM], b[TN];
#pragma unroll
            for (int i = 0; i < TM; i++) a[i] = As[kk][ty * TM + i];
#pragma unroll
            for (int j = 0; j < TN; j++) b[j] = Bs[kk][tx * TN + j];
#pragma unroll
            for (int i = 0; i < TM; i++)
#pragma unroll
                for (int j = 0; j < TN; j++)
                    acc[i][j] = fmaf(a[i], b[j], acc[i][j]);
        }
        __syncthreads();
    }

#pragma unroll
    for (int i = 0; i < TM; i++) {
        const int row = m0 + ty * TM + i;
#pragma unroll
        for (int j = 0; j < TN; j += 4) {
            const int col = n0 + tx * TN + j;
            float4 o;
            o.x = acc[i][j + 0] + bias[col + 0];
            o.y = acc[i][j + 1] + bias[col + 1];
            o.z = acc[i][j + 2] + bias[col + 2];
            o.w = acc[i][j + 3] + bias[col + 3];
            *(float4*)(C + (size_t)row * N + col) = o;
        }
    }
}

// ---------------------------------------------------------------------------
// Fused MQA attention (flash-style, fp32).
// Q: [B,S,H*D] (head h at cols h*64..), K/V: [B,S,D], O: [B,S,H*D].
// Block = (q-tile 64, head, batch), 256 threads, 32 keys per inner iter.
// ---------------------------------------------------------------------------
__global__ __launch_bounds__(256) void mqa_attn_kernel(
    const float* __restrict__ Q, const float* __restrict__ Kp,
    const float* __restrict__ Vp, float* __restrict__ O)
{
    constexpr int QB = 64;
    constexpr int KBLK = 32;
    constexpr int D = HDIM;

    __shared__ float q_s[D][QB + 1];      // transposed: [dim][query]
    __shared__ float k_s[D][KBLK + 1];    // transposed: [dim][key]
    __shared__ float v_s[KBLK][D + 4];    // [key][dim]
    __shared__ float s_s[QB][KBLK + 1];   // scores / probabilities
    __shared__ float m_s[QB], l_s[QB], alpha_s[QB];

    const int tid = threadIdx.x;
    const int qb = blockIdx.x;
    const int h = blockIdx.y;
    const int b = blockIdx.z;
    const int q0 = qb * QB;
    const float scale = 1.0f / 32.0f;  // 1/sqrt(HID_DIM)

    // Load Q tile (scaled, transposed)
    {
        const float* qbase = Q + ((size_t)b * SEQ + q0) * HID_DIM + h * HDIM;
        const int r = tid / 16;
        const int c = (tid % 16) * 4;
        for (int rr = r; rr < QB; rr += 16) {
            float4 v = *(const float4*)(qbase + (size_t)rr * HID_DIM + c);
            q_s[c + 0][rr] = v.x * scale;
            q_s[c + 1][rr] = v.y * scale;
            q_s[c + 2][rr] = v.z * scale;
            q_s[c + 3][rr] = v.w * scale;
        }
    }
    if (tid < QB) { m_s[tid] = -1e30f; l_s[tid] = 0.0f; }

    float acc[4][4] = {};
    const int sy = tid / 16, sx = tid % 16;  // scores: rows sy*4+i, cols sx*2+j
    const int oy = tid / 16, ox = tid % 16;  // pv: rows oy*4+i, dims ox*4+j

    for (int k0 = 0; k0 < SEQ; k0 += KBLK) {
        __syncthreads();  // prior PV done reading k_s/v_s/s_s
        // Load K (transposed) + V tile
        {
            const float* kp = Kp + ((size_t)b * SEQ + k0) * D;
            const float* vp = Vp + ((size_t)b * SEQ + k0) * D;
            const int r = tid / 16;
            const int c = (tid % 16) * 4;
            for (int rr = r; rr < KBLK; rr += 16) {
                float4 kv = *(const float4*)(kp + (size_t)rr * D + c);
                k_s[c + 0][rr] = kv.x;
                k_s[c + 1][rr] = kv.y;
                k_s[c + 2][rr] = kv.z;
                k_s[c + 3][rr] = kv.w;
                *(float4*)&v_s[rr][c] = *(const float4*)(vp + (size_t)rr * D + c);
            }
        }
        __syncthreads();

        // Scores: S(64x32) = Qs^T(64xD) @ Ks(DxKBLK)
        float sc[4][2] = {};
#pragma unroll 16
        for (int kk = 0; kk < D; kk++) {
            float a[4], bb[2];
#pragma unroll
            for (int i = 0; i < 4; i++) a[i] = q_s[kk][sy * 4 + i];
#pragma unroll
            for (int j = 0; j < 2; j++) bb[j] = k_s[kk][sx * 2 + j];
#pragma unroll
            for (int i = 0; i < 4; i++)
#pragma unroll
                for (int j = 0; j < 2; j++)
                    sc[i][j] = fmaf(a[i], bb[j], sc[i][j]);
        }
#pragma unroll
        for (int i = 0; i < 4; i++)
#pragma unroll
            for (int j = 0; j < 2; j++)
                s_s[sy * 4 + i][sx * 2 + j] = sc[i][j];
        __syncthreads();

        // Online softmax: one thread per query row
        if (tid < QB) {
            const float m_old = m_s[tid];
            float mx = m_old;
#pragma unroll
            for (int j = 0; j < KBLK; j++) mx = fmaxf(mx, s_s[tid][j]);
            const float alpha = expf(m_old - mx);
            float sum = 0.0f;
#pragma unroll
            for (int j = 0; j < KBLK; j++) {
                const float p = expf(s_s[tid][j] - mx);
                s_s[tid][j] = p;
                sum += p;
            }
            m_s[tid] = mx;
            l_s[tid] = l_s[tid] * alpha + sum;
            alpha_s[tid] = alpha;
        }
        __syncthreads();

        // acc = acc * alpha + P @ V
        float al[4];
#pragma unroll
        for (int i = 0; i < 4; i++) al[i] = alpha_s[oy * 4 + i];
#pragma unroll
        for (int i = 0; i < 4; i++)
#pragma unroll
            for (int j = 0; j < 4; j++)
                acc[i][j] *= al[i];

#pragma unroll 8
        for (int kk = 0; kk < KBLK; kk++) {
            float p[4], vv[4];
#pragma unroll
            for (int i = 0; i < 4; i++) p[i] = s_s[oy * 4 + i][kk];
#pragma unroll
            for (int j = 0; j < 4; j++) vv[j] = v_s[kk][ox * 4 + j];
#pragma unroll
            for (int i = 0; i < 4; i++)
#pragma unroll
                for (int j = 0; j < 4; j++)
                    acc[i][j] = fmaf(p[i], vv[j], acc[i][j]);
        }
    }
    __syncthreads();

    // Write normalized output
    float* obase = O + ((size_t)b * SEQ + q0) * HID_DIM + h * HDIM;
#pragma unroll
    for (int i = 0; i < 4; i++) {
        const int row = oy * 4 + i;
        const float inv = 1.0f / l_s[row];
        float4 o;
        o.x = acc[i][0] * inv;
        o.y = acc[i][1] * inv;
        o.z = acc[i][2] * inv;
        o.w = acc[i][3] * inv;
        *(float4*)(obase + (size_t)row * HID_DIM + ox * 4) = o;
    }
}

// ---------------------------------------------------------------------------
// Launch
// ---------------------------------------------------------------------------
extern "C" void kernel_launch(void* const* d_in, const int* in_sizes, int n_in,
                              void* d_out, int out_size)
{
    const float* query = (const float*)d_in[0];
    const float* key   = (const float*)d_in[1];
    const float* value = (const float*)d_in[2];
    const float* Wq    = (const float*)d_in[3];
    const float* bq    = (const float*)d_in[4];
    const float* Wk    = (const float*)d_in[5];
    const float* bk    = (const float*)d_in[6];
    const float* Wv    = (const float*)d_in[7];
    const float* bv    = (const float*)d_in[8];
    const float* Wo    = (const float*)d_in[9];
    const float* bo    = (const float*)d_in[10];
    float* out = (float*)d_out;

    void *pQ, *pK, *pV, *pO;
    cudaGetSymbolAddress(&pQ, g_Q);
    cudaGetSymbolAddress(&pK, g_K);
    cudaGetSymbolAddress(&pV, g_V);
    cudaGetSymbolAddress(&pO, g_O);

    const int M = BATCH * SEQ;  // 4096

    // Q projection: [4096,1024] @ [1024,1024]
    {
        dim3 grid(HID_DIM / 128, M / 128);
        gemm_bias_kernel<128, 128, 8, 8, 8><<<grid, 256>>>(
            query, Wq, bq, (float*)pQ, M, HID_DIM, IN_DIM);
    }
    // K projection: [4096,1024] @ [1024,64]
    {
        dim3 grid(HDIM / 64, M / 64);
        gemm_bias_kernel<64, 64, 8, 4, 4><<<grid, 256>>>(
            key, Wk, bk, (float*)pK, M, HDIM, IN_DIM);
    }
    // V projection
    {
        dim3 grid(HDIM / 64, M / 64);
        gemm_bias_kernel<64, 64, 8, 4, 4><<<grid, 256>>>(
            value, Wv, bv, (float*)pV, M, HDIM, IN_DIM);
    }
    // Fused MQA attention
    {
        dim3 grid(SEQ / 64, NHEAD, BATCH);
        mqa_attn_kernel<<<grid, 256>>>((const float*)pQ, (const float*)pK,
                                       (const float*)pV, (float*)pO);
    }
    // Output projection: [4096,1024] @ [1024,1024] -> d_out
    {
        dim3 grid(IN_DIM / 128, M / 128);
        gemm_bias_kernel<128, 128, 8, 8, 8><<<grid, 256>>>(
            (const float*)pO, Wo, bo, out, M, IN_DIM, HID_DIM);
    }
}

// round 3
// speedup vs baseline: 1.2453x; 1.2453x over previous
#include <cuda_runtime.h>
#include <cuda_bf16.h>
#include <cstdint>

// Problem constants (fixed shapes from reference)
#define BATCH 2
#define SEQ 2048
#define IN_DIM 1024
#define HID_DIM 1024
#define NHEAD 16
#define HDIM 64

// Scratch (allocation-free rule: __device__ globals)
__device__ float g_Q[BATCH * SEQ * HID_DIM];   // 16 MB
__device__ float g_K[BATCH * SEQ * HDIM];      // 1 MB
__device__ float g_V[BATCH * SEQ * HDIM];      // 1 MB
__device__ float g_O[BATCH * SEQ * HID_DIM];   // 16 MB

// ---------------------------------------------------------------------------
// Generic tiled fp32 GEMM with bias: C[M,N] = A[M,K] @ B[K,N] + bias[N]
// A row-major, B row-major. M%BM==0, N%BN==0, K%BK==0 (true for our shapes).
// ---------------------------------------------------------------------------
template <int BM, int BN, int BK, int TM, int TN>
__global__ __launch_bounds__(256) void gemm_bias_kernel(
    const float* __restrict__ A, const float* __restrict__ B,
    const float* __restrict__ bias, float* __restrict__ C,
    int M, int N, int K)
{
    static_assert((BM / TM) * (BN / TN) == 256, "256 threads");
    __shared__ float As[BK][BM + 4];
    __shared__ float Bs[BK][BN];

    const int tid = threadIdx.x;
    const int tx = tid % (BN / TN);
    const int ty = tid / (BN / TN);
    const int m0 = blockIdx.y * BM;
    const int n0 = blockIdx.x * BN;

    float acc[TM][TN] = {};

    for (int k0 = 0; k0 < K; k0 += BK) {
        // A tile: BM*BK/4 float4 loads (vector along K, store transposed)
#pragma unroll
        for (int i = tid; i < BM * BK / 4; i += 256) {
            const int ar = i / (BK / 4);
            const int ac = (i % (BK / 4)) * 4;
            float4 v = *(const float4*)(A + (size_t)(m0 + ar) * K + k0 + ac);
            As[ac + 0][ar] = v.x;
            As[ac + 1][ar] = v.y;
            As[ac + 2][ar] = v.z;
            As[ac + 3][ar] = v.w;
        }
        // B tile: BK*BN/4 float4 loads (vector along N)
#pragma unroll
        for (int i = tid; i < BK * BN / 4; i += 256) {
            const int br = i / (BN / 4);
            const int bc = (i % (BN / 4)) * 4;
            *(float4*)&Bs[br][bc] = *(const float4*)(B + (size_t)(k0 + br) * N + n0 + bc);
        }
        __syncthreads();

#pragma unroll
        for (int kk = 0; kk < BK; kk++) {
            float a[TM], b[TN];
#pragma unroll
            for (int i = 0; i < TM; i++) a[i] = As[kk][ty * TM + i];
#pragma unroll
            for (int j = 0; j < TN; j++) b[j] = Bs[kk][tx * TN + j];
#pragma unroll
            for (int i = 0; i < TM; i++)
#pragma unroll
                for (int j = 0; j < TN; j++)
                    acc[i][j] = fmaf(a[i], b[j], acc[i][j]);
        }
        __syncthreads();
    }

#pragma unroll
    for (int i = 0; i < TM; i++) {
        const int row = m0 + ty * TM + i;
#pragma unroll
        for (int j = 0; j < TN; j += 4) {
            const int col = n0 + tx * TN + j;
            float4 o;
            o.x = acc[i][j + 0] + bias[col + 0];
            o.y = acc[i][j + 1] + bias[col + 1];
            o.z = acc[i][j + 2] + bias[col + 2];
            o.w = acc[i][j + 3] + bias[col + 3];
            *(float4*)(C + (size_t)row * N + col) = o;
        }
    }
}

// ---------------------------------------------------------------------------
// Fused MQA attention (flash-style, fp32), v2.
// QB=128 queries/block, KBLK=64 keys/iter, 256 threads, 8x4 register tiles.
// P stored transposed (sT[key][query]) so PV loads are vector+broadcast.
// Dynamic smem ~104KB, 2 CTAs/SM for cross-CTA overlap.
// ---------------------------------------------------------------------------
#define QB 128
#define KBLK 64
#define QS (QB + 4)    // 132: row stride for [d][q] and [k][q] arrays
#define KS (KBLK + 4)  // 68:  row stride for [d][k] and [k][d] arrays

__global__ __launch_bounds__(256, 2) void mqa_attn_kernel(
    const float* __restrict__ Q, const float* __restrict__ Kp,
    const float* __restrict__ Vp, float* __restrict__ O)
{
    extern __shared__ float sm[];
    float* q_s = sm;                       // [64][QS]   Q transposed (scaled)
    float* k_s = q_s + 64 * QS;            // [64][KS]   K transposed
    float* v_s = k_s + 64 * KS;            // [KBLK][KS] V row-major
    float* sT  = v_s + KBLK * KS;          // [KBLK][QS] scores/probs transposed
    float* m_s = sT + KBLK * QS;           // [QB]
    float* l_s = m_s + QB;                 // [QB]
    float* al_s = l_s + QB;                // [QB]

    const int tid = threadIdx.x;
    const int ty = tid / 16;               // 0..15 -> 8 query rows each
    const int tx = tid % 16;               // 0..15 -> 4 cols each
    const int h = blockIdx.y;
    const int b = blockIdx.z;
    const int q0 = blockIdx.x * QB;
    const float scale = 1.0f / 32.0f;      // 1/sqrt(HID_DIM)

    // Load Q tile (scaled, transposed): 128 rows x 64 dims
    {
        const float* qbase = Q + ((size_t)b * SEQ + q0) * HID_DIM + h * HDIM;
#pragma unroll
        for (int i = tid; i < QB * 16; i += 256) {
            const int rr = i / 16;
            const int c4 = (i % 16) * 4;
            float4 v = *(const float4*)(qbase + (size_t)rr * HID_DIM + c4);
            q_s[(c4 + 0) * QS + rr] = v.x * scale;
            q_s[(c4 + 1) * QS + rr] = v.y * scale;
            q_s[(c4 + 2) * QS + rr] = v.z * scale;
            q_s[(c4 + 3) * QS + rr] = v.w * scale;
        }
    }
    if (tid < QB) { m_s[tid] = -1e30f; l_s[tid] = 0.0f; }

    float acc[8][4] = {};

    for (int k0 = 0; k0 < SEQ; k0 += KBLK) {
        __syncthreads();  // previous iter done with k_s/v_s/sT
        // Load K (transposed) + V tile: KBLK rows x 64 dims
        {
            const float* kp = Kp + ((size_t)b * SEQ + k0) * HDIM;
            const float* vp = Vp + ((size_t)b * SEQ + k0) * HDIM;
#pragma unroll
            for (int i = tid; i < KBLK * 16; i += 256) {
                const int rr = i / 16;
                const int c4 = (i % 16) * 4;
                float4 kv = *(const float4*)(kp + (size_t)rr * HDIM + c4);
                k_s[(c4 + 0) * KS + rr] = kv.x;
                k_s[(c4 + 1) * KS + rr] = kv.y;
                k_s[(c4 + 2) * KS + rr] = kv.z;
                k_s[(c4 + 3) * KS + rr] = kv.w;
                *(float4*)&v_s[rr * KS + c4] = *(const float4*)(vp + (size_t)rr * HDIM + c4);
            }
        }
        __syncthreads();

        // Scores: S(128x64) = Qs^T @ Ks ; thread tile 8 rows x 4 cols
        float sc[8][4] = {};
#pragma unroll 8
        for (int kk = 0; kk < 64; kk++) {
            const float4 b4 = *(const float4*)&k_s[kk * KS + tx * 4];
            const float4 a0 = *(const float4*)&q_s[kk * QS + ty * 8];
            const float4 a1 = *(const float4*)&q_s[kk * QS + ty * 8 + 4];
            const float a[8] = {a0.x, a0.y, a0.z, a0.w, a1.x, a1.y, a1.z, a1.w};
            const float bb[4] = {b4.x, b4.y, b4.z, b4.w};
#pragma unroll
            for (int i = 0; i < 8; i++)
#pragma unroll
                for (int j = 0; j < 4; j++)
                    sc[i][j] = fmaf(a[i], bb[j], sc[i][j]);
        }
        // Write transposed: sT[col][row]
#pragma unroll
        for (int j = 0; j < 4; j++) {
            float* dst = &sT[(tx * 4 + j) * QS + ty * 8];
            *(float4*)dst       = make_float4(sc[0][j], sc[1][j], sc[2][j], sc[3][j]);
            *(float4*)(dst + 4) = make_float4(sc[4][j], sc[5][j], sc[6][j], sc[7][j]);
        }
        __syncthreads();

        // Online softmax: 2 threads per query row, 32 keys each
        {
            const int r = tid >> 1;
            const int hh = tid & 1;
            float mloc = -1e30f;
#pragma unroll
            for (int j = 0; j < 32; j++)
                mloc = fmaxf(mloc, sT[(hh * 32 + j) * QS + r]);
            mloc = fmaxf(mloc, __shfl_xor_sync(0xffffffffu, mloc, 1));
            const float m_old = m_s[r];
            const float mx = fmaxf(m_old, mloc);
            float sum = 0.0f;
#pragma unroll
            for (int j = 0; j < 32; j++) {
                float* p = &sT[(hh * 32 + j) * QS + r];
                const float e = __expf(*p - mx);
                *p = e;
                sum += e;
            }
            sum += __shfl_xor_sync(0xffffffffu, sum, 1);
            if (hh == 0) {
                const float alpha = __expf(m_old - mx);
                m_s[r] = mx;
                l_s[r] = l_s[r] * alpha + sum;
                al_s[r] = alpha;
            }
        }
        __syncthreads();

        // acc = acc*alpha + P @ V ; thread tile 8 rows x 4 dims
        float al[8];
#pragma unroll
        for (int i = 0; i < 8; i++) al[i] = al_s[ty * 8 + i];
#pragma unroll
        for (int i = 0; i < 8; i++)
#pragma unroll
            for (int j = 0; j < 4; j++)
                acc[i][j] *= al[i];

#pragma unroll 8
        for (int kk = 0; kk < KBLK; kk++) {
            const float4 v4 = *(const float4*)&v_s[kk * KS + tx * 4];
            const float4 p0 = *(const float4*)&sT[kk * QS + ty * 8];
            const float4 p1 = *(const float4*)&sT[kk * QS + ty * 8 + 4];
            const float p[8] = {p0.x, p0.y, p0.z, p0.w, p1.x, p1.y, p1.z, p1.w};
            const float vv[4] = {v4.x, v4.y, v4.z, v4.w};
#pragma unroll
            for (int i = 0; i < 8; i++)
#pragma unroll
                for (int j = 0; j < 4; j++)
                    acc[i][j] = fmaf(p[i], vv[j], acc[i][j]);
        }
    }

    // Write normalized output: rows ty*8.., dims tx*4..
    float* obase = O + ((size_t)b * SEQ + q0) * HID_DIM + h * HDIM;
#pragma unroll
    for (int i = 0; i < 8; i++) {
        const int row = ty * 8 + i;
        const float inv = 1.0f / l_s[row];
        float4 o;
        o.x = acc[i][0] * inv;
        o.y = acc[i][1] * inv;
        o.z = acc[i][2] * inv;
        o.w = acc[i][3] * inv;
        *(float4*)(obase + (size_t)row * HID_DIM + tx * 4) = o;
    }
}

static const int MQA_SMEM_BYTES =
    (64 * QS + 64 * KS + KBLK * KS + KBLK * QS + 3 * QB) * (int)sizeof(float);

// ---------------------------------------------------------------------------
// Launch
// ---------------------------------------------------------------------------
extern "C" void kernel_launch(void* const* d_in, const int* in_sizes, int n_in,
                              void* d_out, int out_size)
{
    const float* query = (const float*)d_in[0];
    const float* key   = (const float*)d_in[1];
    const float* value = (const float*)d_in[2];
    const float* Wq    = (const float*)d_in[3];
    const float* bq    = (const float*)d_in[4];
    const float* Wk    = (const float*)d_in[5];
    const float* bk    = (const float*)d_in[6];
    const float* Wv    = (const float*)d_in[7];
    const float* bv    = (const float*)d_in[8];
    const float* Wo    = (const float*)d_in[9];
    const float* bo    = (const float*)d_in[10];
    float* out = (float*)d_out;

    void *pQ, *pK, *pV, *pO;
    cudaGetSymbolAddress(&pQ, g_Q);
    cudaGetSymbolAddress(&pK, g_K);
    cudaGetSymbolAddress(&pV, g_V);
    cudaGetSymbolAddress(&pO, g_O);

    cudaFuncSetAttribute(mqa_attn_kernel,
                         cudaFuncAttributeMaxDynamicSharedMemorySize,
                         MQA_SMEM_BYTES);

    const int M = BATCH * SEQ;  // 4096

    // Q projection: [4096,1024] @ [1024,1024]
    {
        dim3 grid(HID_DIM / 128, M / 128);
        gemm_bias_kernel<128, 128, 16, 8, 8><<<grid, 256>>>(
            query, Wq, bq, (float*)pQ, M, HID_DIM, IN_DIM);
    }
    // K projection: [4096,1024] @ [1024,64]
    {
        dim3 grid(HDIM / 64, M / 64);
        gemm_bias_kernel<64, 64, 16, 4, 4><<<grid, 256>>>(
            key, Wk, bk, (float*)pK, M, HDIM, IN_DIM);
    }
    // V projection
    {
        dim3 grid(HDIM / 64, M / 64);
        gemm_bias_kernel<64, 64, 16, 4, 4><<<grid, 256>>>(
            value, Wv, bv, (float*)pV, M, HDIM, IN_DIM);
    }
    // Fused MQA attention
    {
        dim3 grid(SEQ / QB, NHEAD, BATCH);
        mqa_attn_kernel<<<grid, 256, MQA_SMEM_BYTES>>>(
            (const float*)pQ, (const float*)pK, (const float*)pV, (float*)pO);
    }
    // Output projection: [4096,1024] @ [1024,1024] -> d_out
    {
        dim3 grid(IN_DIM / 128, M / 128);
        gemm_bias_kernel<128, 128, 16, 8, 8><<<grid, 256>>>(
            (const float*)pO, Wo, bo, out, M, IN_DIM, HID_DIM);
    }
}

// round 5
// speedup vs baseline: 1.5027x; 1.2067x over previous
#include <cuda_runtime.h>
#include <cuda_bf16.h>
#include <cstdint>

typedef __nv_bfloat16 bf16;

// Problem constants (fixed shapes from reference)
#define BATCH 2
#define SEQ 2048
#define IN_DIM 1024
#define HID_DIM 1024
#define NHEAD 16
#define HDIM 64
#define KDIM 1024           // K of all projection GEMMs
#define MROWS 4096          // BATCH*SEQ

// ---------------------------------------------------------------------------
// Scratch (allocation-free rule: __device__ globals)
// ---------------------------------------------------------------------------
__device__ float g_Q[MROWS * HID_DIM];   // 16 MB fp32
__device__ float g_K[MROWS * HDIM];      // 1 MB
__device__ float g_V[MROWS * HDIM];      // 1 MB
__device__ float g_O[MROWS * HID_DIM];   // 16 MB

// bf16 hi/lo splits of GEMM A-operands
__device__ bf16 g_qhi[MROWS * KDIM], g_qlo[MROWS * KDIM];
__device__ bf16 g_khi[MROWS * KDIM], g_klo[MROWS * KDIM];
__device__ bf16 g_vhi[MROWS * KDIM], g_vlo[MROWS * KDIM];
__device__ bf16 g_ohi[MROWS * KDIM], g_olo[MROWS * KDIM];
// transposed+split weights: [N, K] bf16, K contiguous
__device__ bf16 g_WqThi[HID_DIM * KDIM], g_WqTlo[HID_DIM * KDIM];
__device__ bf16 g_WkThi[HDIM * KDIM],   g_WkTlo[HDIM * KDIM];
__device__ bf16 g_WvThi[HDIM * KDIM],   g_WvTlo[HDIM * KDIM];
__device__ bf16 g_WoThi[IN_DIM * KDIM], g_WoTlo[IN_DIM * KDIM];

// ---------------------------------------------------------------------------
// mma.sync / ldmatrix helpers (sm_80-era PTX; legal in family-generic PTX)
// ---------------------------------------------------------------------------
__device__ __forceinline__ uint32_t smem_u32(const void* p) {
    uint32_t a;
    asm("{ .reg .u64 t; cvta.to.shared.u64 t, %1; cvt.u32.u64 %0, t; }"
        : "=r"(a) : "l"(p));
    return a;
}
__device__ __forceinline__ void ldsm_x4(uint32_t* r, uint32_t addr) {
    asm volatile("ldmatrix.sync.aligned.m8n8.x4.shared.b16 {%0,%1,%2,%3}, [%4];"
                 : "=r"(r[0]), "=r"(r[1]), "=r"(r[2]), "=r"(r[3]) : "r"(addr));
}
__device__ __forceinline__ void mma_bf16(float* d, const uint32_t* a,
                                         const uint32_t* b) {
    asm volatile(
        "mma.sync.aligned.m16n8k16.row.col.f32.bf16.bf16.f32 "
        "{%0,%1,%2,%3}, {%4,%5,%6,%7}, {%8,%9}, {%0,%1,%2,%3};"
        : "+f"(d[0]), "+f"(d[1]), "+f"(d[2]), "+f"(d[3])
        : "r"(a[0]), "r"(a[1]), "r"(a[2]), "r"(a[3]), "r"(b[0]), "r"(b[1]));
}

// ---------------------------------------------------------------------------
// Prep: transpose + hi/lo split weights  W[K,N] fp32 -> T{hi,lo}[N,K] bf16
// ---------------------------------------------------------------------------
__global__ void transpose_split_w(const float* __restrict__ W,
                                  bf16* __restrict__ Thi, bf16* __restrict__ Tlo,
                                  int K, int N)
{
    __shared__ float t[32][33];
    const int n0 = blockIdx.x * 32, k0 = blockIdx.y * 32;
    const int tx = threadIdx.x, ty = threadIdx.y;  // 32 x 8
#pragma unroll
    for (int i = 0; i < 32; i += 8)
        t[ty + i][tx] = W[(size_t)(k0 + ty + i) * N + n0 + tx];
    __syncthreads();
#pragma unroll
    for (int i = 0; i < 32; i += 8) {
        const float v = t[tx][ty + i];
        const bf16 h = __float2bfloat16(v);
        const bf16 l = __float2bfloat16(v - __bfloat162float(h));
        const size_t idx = (size_t)(n0 + ty + i) * K + k0 + tx;
        Thi[idx] = h;
        Tlo[idx] = l;
    }
}

// elementwise hi/lo split of fp32 rows (K already contiguous)
__global__ void split_rows(const float2* __restrict__ X,
                           __nv_bfloat162* __restrict__ hi,
                           __nv_bfloat162* __restrict__ lo, int n2)
{
    const int i = blockIdx.x * blockDim.x + threadIdx.x;
    if (i < n2) {
        const float2 v = X[i];
        const bf16 hx = __float2bfloat16(v.x);
        const bf16 hy = __float2bfloat16(v.y);
        const bf16 lx = __float2bfloat16(v.x - __bfloat162float(hx));
        const bf16 ly = __float2bfloat16(v.y - __bfloat162float(hy));
        hi[i] = __nv_bfloat162(hx, hy);
        lo[i] = __nv_bfloat162(lx, ly);
    }
}

// ---------------------------------------------------------------------------
// mma.sync bf16 split GEMM:
//   C[M,Ntot] fp32 = (Ahi+Alo)[M,K] @ (Bhi+Blo)[Ntot,K]^T + bias
// Block tile: 128 x BN, K chunk 64. 8 warps: 4 (m) x 2 (n); warp = 32 x BN/2.
// Terms: Ah*Bh + Ah*Bl + Al*Bh.
// ---------------------------------------------------------------------------
template <int BN>
__global__ __launch_bounds__(256) void gemm_mma(
    const bf16* __restrict__ Ahi, const bf16* __restrict__ Alo,
    const bf16* __restrict__ Bhi, const bf16* __restrict__ Blo,
    const float* __restrict__ bias, float* __restrict__ C, int Ntot)
{
    constexpr int LDS_ = 72;            // bf16 row stride (144B, conflict-free)
    constexpr int WN = BN / 2;          // warp n-extent
    constexpr int NF = WN / 8;          // n-fragments per warp
    extern __shared__ bf16 smem[];
    bf16* sAh = smem;                   // [128][72]
    bf16* sAl = sAh + 128 * LDS_;
    bf16* sBh = sAl + 128 * LDS_;       // [BN][72]
    bf16* sBl = sBh + BN * LDS_;

    const int tid = threadIdx.x;
    const int wid = tid >> 5, lane = tid & 31;
    const int warp_m = wid & 3, warp_n = wid >> 2;
    const int m0 = blockIdx.y * 128;
    const int n0 = blockIdx.x * BN;

    const uint32_t uAh = smem_u32(sAh), uAl = smem_u32(sAl);
    const uint32_t uBh = smem_u32(sBh), uBl = smem_u32(sBl);

    // per-lane ldmatrix row/col pieces
    const int lrow = (lane & 7) + ((lane >> 3) & 1) * 8;  // row within 16
    const int lcol = (lane >> 4) * 8;                     // 0 or 8

    const bf16* a_hi = Ahi + (size_t)m0 * KDIM;
    const bf16* a_lo = Alo + (size_t)m0 * KDIM;
    const bf16* b_hi = Bhi + (size_t)n0 * KDIM;
    const bf16* b_lo = Blo + (size_t)n0 * KDIM;

    float acc[2][NF][4] = {};

    for (int ch = 0; ch < KDIM / 64; ch++) {
        const int k0 = ch * 64;
        // global -> smem (8 bf16 per uint4)
#pragma unroll
        for (int i = tid; i < 128 * 8; i += 256) {
            const int r = i >> 3, c8 = (i & 7) * 8;
            const int so = r * LDS_ + c8;
            *(uint4*)(sAh + so) = *(const uint4*)(a_hi + (size_t)r * KDIM + k0 + c8);
            *(uint4*)(sAl + so) = *(const uint4*)(a_lo + (size_t)r * KDIM + k0 + c8);
        }
#pragma unroll
        for (int i = tid; i < BN * 8; i += 256) {
            const int r = i >> 3, c8 = (i & 7) * 8;
            const int so = r * LDS_ + c8;
            *(uint4*)(sBh + so) = *(const uint4*)(b_hi + (size_t)r * KDIM + k0 + c8);
            *(uint4*)(sBl + so) = *(const uint4*)(b_lo + (size_t)r * KDIM + k0 + c8);
        }
        __syncthreads();

#pragma unroll
        for (int ks = 0; ks < 4; ks++) {
            const int kk = ks * 16 + lcol;
            // A fragments (hi & lo), 2 m-frags
            uint32_t ah[2][4], al[2][4];
#pragma unroll
            for (int mf = 0; mf < 2; mf++) {
                const int row = warp_m * 32 + mf * 16 + lrow;
                const uint32_t off = (uint32_t)(row * LDS_ + kk) * 2;
                ldsm_x4(ah[mf], uAh + off);
                ldsm_x4(al[mf], uAl + off);
            }
            // B fragments (hi & lo), NF n-frags loaded in pairs
            uint32_t bh[NF][2], bl[NF][2];
#pragma unroll
            for (int p = 0; p < NF / 2; p++) {
                const int row = warp_n * WN + p * 16 + lrow;
                const uint32_t off = (uint32_t)(row * LDS_ + kk) * 2;
                uint32_t r4[4];
                ldsm_x4(r4, uBh + off);
                bh[2 * p][0] = r4[0]; bh[2 * p][1] = r4[2];
                bh[2 * p + 1][0] = r4[1]; bh[2 * p + 1][1] = r4[3];
                ldsm_x4(r4, uBl + off);
                bl[2 * p][0] = r4[0]; bl[2 * p][1] = r4[2];
                bl[2 * p + 1][0] = r4[1]; bl[2 * p + 1][1] = r4[3];
            }
            // 3-term split MMA
#pragma unroll
            for (int mf = 0; mf < 2; mf++)
#pragma unroll
                for (int nf = 0; nf < NF; nf++) {
                    mma_bf16(acc[mf][nf], ah[mf], bh[nf]);
                    mma_bf16(acc[mf][nf], ah[mf], bl[nf]);
                    mma_bf16(acc[mf][nf], al[mf], bh[nf]);
                }
        }
        __syncthreads();
    }

    // Epilogue: fragment -> global with bias
    const int gid = lane >> 2, t4 = lane & 3;
#pragma unroll
    for (int mf = 0; mf < 2; mf++) {
        const int row = m0 + warp_m * 32 + mf * 16 + gid;
#pragma unroll
        for (int nf = 0; nf < NF; nf++) {
            const int col = n0 + warp_n * WN + nf * 8 + t4 * 2;
            const float2 bs = make_float2(bias[col], bias[col + 1]);
            float2 o0 = make_float2(acc[mf][nf][0] + bs.x, acc[mf][nf][1] + bs.y);
            float2 o1 = make_float2(acc[mf][nf][2] + bs.x, acc[mf][nf][3] + bs.y);
            *(float2*)(C + (size_t)row * Ntot + col) = o0;
            *(float2*)(C + (size_t)(row + 8) * Ntot + col) = o1;
        }
    }
}

// ---------------------------------------------------------------------------
// Fused MQA attention (flash-style, fp32) — unchanged (920us, passing).
// ---------------------------------------------------------------------------
#define QB 128
#define KBLK 64
#define QS (QB + 4)
#define KS (KBLK + 4)

__global__ __launch_bounds__(256, 2) void mqa_attn_kernel(
    const float* __restrict__ Q, const float* __restrict__ Kp,
    const float* __restrict__ Vp, float* __restrict__ O)
{
    extern __shared__ float sm[];
    float* q_s = sm;
    float* k_s = q_s + 64 * QS;
    float* v_s = k_s + 64 * KS;
    float* sT  = v_s + KBLK * KS;
    float* m_s = sT + KBLK * QS;
    float* l_s = m_s + QB;
    float* al_s = l_s + QB;

    const int tid = threadIdx.x;
    const int ty = tid / 16;
    const int tx = tid % 16;
    const int h = blockIdx.y;
    const int b = blockIdx.z;
    const int q0 = blockIdx.x * QB;
    const float scale = 1.0f / 32.0f;

    {
        const float* qbase = Q + ((size_t)b * SEQ + q0) * HID_DIM + h * HDIM;
#pragma unroll
        for (int i = tid; i < QB * 16; i += 256) {
            const int rr = i / 16;
            const int c4 = (i % 16) * 4;
            float4 v = *(const float4*)(qbase + (size_t)rr * HID_DIM + c4);
            q_s[(c4 + 0) * QS + rr] = v.x * scale;
            q_s[(c4 + 1) * QS + rr] = v.y * scale;
            q_s[(c4 + 2) * QS + rr] = v.z * scale;
            q_s[(c4 + 3) * QS + rr] = v.w * scale;
        }
    }
    if (tid < QB) { m_s[tid] = -1e30f; l_s[tid] = 0.0f; }

    float acc[8][4] = {};

    for (int k0 = 0; k0 < SEQ; k0 += KBLK) {
        __syncthreads();
        {
            const float* kp = Kp + ((size_t)b * SEQ + k0) * HDIM;
            const float* vp = Vp + ((size_t)b * SEQ + k0) * HDIM;
#pragma unroll
            for (int i = tid; i < KBLK * 16; i += 256) {
                const int rr = i / 16;
                const int c4 = (i % 16) * 4;
                float4 kv = *(const float4*)(kp + (size_t)rr * HDIM + c4);
                k_s[(c4 + 0) * KS + rr] = kv.x;
                k_s[(c4 + 1) * KS + rr] = kv.y;
                k_s[(c4 + 2) * KS + rr] = kv.z;
                k_s[(c4 + 3) * KS + rr] = kv.w;
                *(float4*)&v_s[rr * KS + c4] = *(const float4*)(vp + (size_t)rr * HDIM + c4);
            }
        }
        __syncthreads();

        float sc[8][4] = {};
#pragma unroll 8
        for (int kk = 0; kk < 64; kk++) {
            const float4 b4 = *(const float4*)&k_s[kk * KS + tx * 4];
            const float4 a0 = *(const float4*)&q_s[kk * QS + ty * 8];
            const float4 a1 = *(const float4*)&q_s[kk * QS + ty * 8 + 4];
            const float a[8] = {a0.x, a0.y, a0.z, a0.w, a1.x, a1.y, a1.z, a1.w};
            const float bb[4] = {b4.x, b4.y, b4.z, b4.w};
#pragma unroll
            for (int i = 0; i < 8; i++)
#pragma unroll
                for (int j = 0; j < 4; j++)
                    sc[i][j] = fmaf(a[i], bb[j], sc[i][j]);
        }
#pragma unroll
        for (int j = 0; j < 4; j++) {
            float* dst = &sT[(tx * 4 + j) * QS + ty * 8];
            *(float4*)dst       = make_float4(sc[0][j], sc[1][j], sc[2][j], sc[3][j]);
            *(float4*)(dst + 4) = make_float4(sc[4][j], sc[5][j], sc[6][j], sc[7][j]);
        }
        __syncthreads();

        {
            const int r = tid >> 1;
            const int hh = tid & 1;
            float mloc = -1e30f;
#pragma unroll
            for (int j = 0; j < 32; j++)
                mloc = fmaxf(mloc, sT[(hh * 32 + j) * QS + r]);
            mloc = fmaxf(mloc, __shfl_xor_sync(0xffffffffu, mloc, 1));
            const float m_old = m_s[r];
            const float mx = fmaxf(m_old, mloc);
            float sum = 0.0f;
#pragma unroll
            for (int j = 0; j < 32; j++) {
                float* p = &sT[(hh * 32 + j) * QS + r];
                const float e = __expf(*p - mx);
                *p = e;
                sum += e;
            }
            sum += __shfl_xor_sync(0xffffffffu, sum, 1);
            if (hh == 0) {
                const float alpha = __expf(m_old - mx);
                m_s[r] = mx;
                l_s[r] = l_s[r] * alpha + sum;
                al_s[r] = alpha;
            }
        }
        __syncthreads();

        float al[8];
#pragma unroll
        for (int i = 0; i < 8; i++) al[i] = al_s[ty * 8 + i];
#pragma unroll
        for (int i = 0; i < 8; i++)
#pragma unroll
            for (int j = 0; j < 4; j++)
                acc[i][j] *= al[i];

#pragma unroll 8
        for (int kk = 0; kk < KBLK; kk++) {
            const float4 v4 = *(const float4*)&v_s[kk * KS + tx * 4];
            const float4 p0 = *(const float4*)&sT[kk * QS + ty * 8];
            const float4 p1 = *(const float4*)&sT[kk * QS + ty * 8 + 4];
            const float p[8] = {p0.x, p0.y, p0.z, p0.w, p1.x, p1.y, p1.z, p1.w};
            const float vv[4] = {v4.x, v4.y, v4.z, v4.w};
#pragma unroll
            for (int i = 0; i < 8; i++)
#pragma unroll
                for (int j = 0; j < 4; j++)
                    acc[i][j] = fmaf(p[i], vv[j], acc[i][j]);
        }
    }

    float* obase = O + ((size_t)b * SEQ + q0) * HID_DIM + h * HDIM;
#pragma unroll
    for (int i = 0; i < 8; i++) {
        const int row = ty * 8 + i;
        const float inv = 1.0f / l_s[row];
        float4 o;
        o.x = acc[i][0] * inv;
        o.y = acc[i][1] * inv;
        o.z = acc[i][2] * inv;
        o.w = acc[i][3] * inv;
        *(float4*)(obase + (size_t)row * HID_DIM + tx * 4) = o;
    }
}

static const int MQA_SMEM_BYTES =
    (64 * QS + 64 * KS + KBLK * KS + KBLK * QS + 3 * QB) * (int)sizeof(float);
static const int GEMM128_SMEM = (2 * 128 + 2 * 128) * 72 * (int)sizeof(bf16); // 73728
static const int GEMM64_SMEM  = (2 * 128 + 2 * 64) * 72 * (int)sizeof(bf16);  // 55296

// ---------------------------------------------------------------------------
// Launch
// ---------------------------------------------------------------------------
extern "C" void kernel_launch(void* const* d_in, const int* in_sizes, int n_in,
                              void* d_out, int out_size)
{
    const float* query = (const float*)d_in[0];
    const float* key   = (const float*)d_in[1];
    const float* value = (const float*)d_in[2];
    const float* Wq    = (const float*)d_in[3];
    const float* bq    = (const float*)d_in[4];
    const float* Wk    = (const float*)d_in[5];
    const float* bk    = (const float*)d_in[6];
    const float* Wv    = (const float*)d_in[7];
    const float* bv    = (const float*)d_in[8];
    const float* Wo    = (const float*)d_in[9];
    const float* bo    = (const float*)d_in[10];
    float* out = (float*)d_out;

    void *pQ, *pK, *pV, *pO;
    void *qh, *ql, *kh, *kl, *vh, *vl, *oh, *ol;
    void *wqh, *wql, *wkh, *wkl, *wvh, *wvl, *woh, *wol;
    cudaGetSymbolAddress(&pQ, g_Q);   cudaGetSymbolAddress(&pK, g_K);
    cudaGetSymbolAddress(&pV, g_V);   cudaGetSymbolAddress(&pO, g_O);
    cudaGetSymbolAddress(&qh, g_qhi); cudaGetSymbolAddress(&ql, g_qlo);
    cudaGetSymbolAddress(&kh, g_khi); cudaGetSymbolAddress(&kl, g_klo);
    cudaGetSymbolAddress(&vh, g_vhi); cudaGetSymbolAddress(&vl, g_vlo);
    cudaGetSymbolAddress(&oh, g_ohi); cudaGetSymbolAddress(&ol, g_olo);
    cudaGetSymbolAddress(&wqh, g_WqThi); cudaGetSymbolAddress(&wql, g_WqTlo);
    cudaGetSymbolAddress(&wkh, g_WkThi); cudaGetSymbolAddress(&wkl, g_WkTlo);
    cudaGetSymbolAddress(&wvh, g_WvThi); cudaGetSymbolAddress(&wvl, g_WvTlo);
    cudaGetSymbolAddress(&woh, g_WoThi); cudaGetSymbolAddress(&wol, g_WoTlo);

    cudaFuncSetAttribute(mqa_attn_kernel,
                         cudaFuncAttributeMaxDynamicSharedMemorySize, MQA_SMEM_BYTES);
    cudaFuncSetAttribute(gemm_mma<128>,
                         cudaFuncAttributeMaxDynamicSharedMemorySize, GEMM128_SMEM);
    cudaFuncSetAttribute(gemm_mma<64>,
                         cudaFuncAttributeMaxDynamicSharedMemorySize, GEMM64_SMEM);

    // --- prep: transpose+split weights ---
    {
        dim3 blk(32, 8);
        transpose_split_w<<<dim3(HID_DIM / 32, KDIM / 32), blk>>>(
            Wq, (bf16*)wqh, (bf16*)wql, KDIM, HID_DIM);
        transpose_split_w<<<dim3(HDIM / 32, KDIM / 32), blk>>>(
            Wk, (bf16*)wkh, (bf16*)wkl, KDIM, HDIM);
        transpose_split_w<<<dim3(HDIM / 32, KDIM / 32), blk>>>(
            Wv, (bf16*)wvh, (bf16*)wvl, KDIM, HDIM);
        transpose_split_w<<<dim3(IN_DIM / 32, KDIM / 32), blk>>>(
            Wo, (bf16*)woh, (bf16*)wol, KDIM, IN_DIM);
    }
    // --- prep: split activations ---
    {
        const int n2 = MROWS * KDIM / 2;
        const int g = (n2 + 255) / 256;
        split_rows<<<g, 256>>>((const float2*)query, (__nv_bfloat162*)qh,
                               (__nv_bfloat162*)ql, n2);
        split_rows<<<g, 256>>>((const float2*)key, (__nv_bfloat162*)kh,
                               (__nv_bfloat162*)kl, n2);
        split_rows<<<g, 256>>>((const float2*)value, (__nv_bfloat162*)vh,
                               (__nv_bfloat162*)vl, n2);
    }
    // --- projections on mma.sync bf16 split ---
    gemm_mma<128><<<dim3(HID_DIM / 128, MROWS / 128), 256, GEMM128_SMEM>>>(
        (const bf16*)qh, (const bf16*)ql, (const bf16*)wqh, (const bf16*)wql,
        bq, (float*)pQ, HID_DIM);
    gemm_mma<64><<<dim3(1, MROWS / 128), 256, GEMM64_SMEM>>>(
        (const bf16*)kh, (const bf16*)kl, (const bf16*)wkh, (const bf16*)wkl,
        bk, (float*)pK, HDIM);
    gemm_mma<64><<<dim3(1, MROWS / 128), 256, GEMM64_SMEM>>>(
        (const bf16*)vh, (const bf16*)vl, (const bf16*)wvh, (const bf16*)wvl,
        bv, (float*)pV, HDIM);

    // --- fused attention (fp32 SIMT) ---
    {
        dim3 grid(SEQ / QB, NHEAD, BATCH);
        mqa_attn_kernel<<<grid, 256, MQA_SMEM_BYTES>>>(
            (const float*)pQ, (const float*)pK, (const float*)pV, (float*)pO);
    }

    // --- split attention output, then O-projection ---
    {
        const int n2 = MROWS * KDIM / 2;
        split_rows<<<(n2 + 255) / 256, 256>>>((const float2*)pO, (__nv_bfloat162*)oh,
                                              (__nv_bfloat162*)ol, n2);
    }
    gemm_mma<128><<<dim3(IN_DIM / 128, MROWS / 128), 256, GEMM128_SMEM>>>(
        (const bf16*)oh, (const bf16*)ol, (const bf16*)woh, (const bf16*)wol,
        bo, out, IN_DIM);
}

// round 6
// speedup vs baseline: 2.6154x; 1.7405x over previous
#include <cuda_runtime.h>
#include <cuda_bf16.h>
#include <cstdint>

typedef __nv_bfloat16 bf16;

#define BATCH 2
#define SEQ 2048
#define IN_DIM 1024
#define HID_DIM 1024
#define NHEAD 16
#define HDIM 64
#define KDIM 1024
#define MROWS 4096

// ---------------------------------------------------------------------------
// Scratch (__device__ globals; allocation-free rule)
// ---------------------------------------------------------------------------
// input splits (A operands of projections)
__device__ bf16 g_qhi[MROWS * KDIM], g_qlo[MROWS * KDIM];
__device__ bf16 g_khi[MROWS * KDIM], g_klo[MROWS * KDIM];
__device__ bf16 g_vhi[MROWS * KDIM], g_vlo[MROWS * KDIM];
// transposed+split weights [N][K]
__device__ bf16 g_WqThi[HID_DIM * KDIM], g_WqTlo[HID_DIM * KDIM];
__device__ bf16 g_WkThi[HDIM * KDIM],   g_WkTlo[HDIM * KDIM];
__device__ bf16 g_WvThi[HDIM * KDIM],   g_WvTlo[HDIM * KDIM];
__device__ bf16 g_WoThi[IN_DIM * KDIM], g_WoTlo[IN_DIM * KDIM];
// projected, split: Q scaled by 1/32
__device__ bf16 g_qPhi[MROWS * HID_DIM], g_qPlo[MROWS * HID_DIM];
__device__ bf16 g_kPhi[MROWS * HDIM],   g_kPlo[MROWS * HDIM];
__device__ bf16 g_vPhi[MROWS * HDIM],   g_vPlo[MROWS * HDIM];
// attention output, split (A operand of O-projection)
__device__ bf16 g_ohi[MROWS * HID_DIM], g_olo[MROWS * HID_DIM];

// ---------------------------------------------------------------------------
// mma.sync / ldmatrix helpers (sm_80-era PTX; legal in family-generic PTX)
// ---------------------------------------------------------------------------
__device__ __forceinline__ uint32_t smem_u32(const void* p) {
    uint32_t a;
    asm("{ .reg .u64 t; cvta.to.shared.u64 t, %1; cvt.u32.u64 %0, t; }"
        : "=r"(a) : "l"(p));
    return a;
}
__device__ __forceinline__ void ldsm_x4(uint32_t* r, uint32_t addr) {
    asm volatile("ldmatrix.sync.aligned.m8n8.x4.shared.b16 {%0,%1,%2,%3}, [%4];"
                 : "=r"(r[0]), "=r"(r[1]), "=r"(r[2]), "=r"(r[3]) : "r"(addr));
}
__device__ __forceinline__ void ldsm_x4_t(uint32_t* r, uint32_t addr) {
    asm volatile("ldmatrix.sync.aligned.m8n8.x4.trans.shared.b16 {%0,%1,%2,%3}, [%4];"
                 : "=r"(r[0]), "=r"(r[1]), "=r"(r[2]), "=r"(r[3]) : "r"(addr));
}
__device__ __forceinline__ void mma_bf16(float* d, const uint32_t* a,
                                         const uint32_t* b) {
    asm volatile(
        "mma.sync.aligned.m16n8k16.row.col.f32.bf16.bf16.f32 "
        "{%0,%1,%2,%3}, {%4,%5,%6,%7}, {%8,%9}, {%0,%1,%2,%3};"
        : "+f"(d[0]), "+f"(d[1]), "+f"(d[2]), "+f"(d[3])
        : "r"(a[0]), "r"(a[1]), "r"(a[2]), "r"(a[3]), "r"(b[0]), "r"(b[1]));
}
// split two fp32 into packed bf16x2 hi-pair + lo-pair (lo half = first arg)
__device__ __forceinline__ void split_pack(float e, float o,
                                           uint32_t& hp, uint32_t& lp) {
    const bf16 he = __float2bfloat16(e), ho = __float2bfloat16(o);
    const bf16 le = __float2bfloat16(e - __bfloat162float(he));
    const bf16 lo2 = __float2bfloat16(o - __bfloat162float(ho));
    __nv_bfloat162 H(he, ho), L(le, lo2);
    hp = *reinterpret_cast<uint32_t*>(&H);
    lp = *reinterpret_cast<uint32_t*>(&L);
}

// ---------------------------------------------------------------------------
// Prep kernels
// ---------------------------------------------------------------------------
__global__ void transpose_split_w(const float* __restrict__ W,
                                  bf16* __restrict__ Thi, bf16* __restrict__ Tlo,
                                  int K, int N)
{
    __shared__ float t[32][33];
    const int n0 = blockIdx.x * 32, k0 = blockIdx.y * 32;
    const int tx = threadIdx.x, ty = threadIdx.y;  // 32 x 8
#pragma unroll
    for (int i = 0; i < 32; i += 8)
        t[ty + i][tx] = W[(size_t)(k0 + ty + i) * N + n0 + tx];
    __syncthreads();
#pragma unroll
    for (int i = 0; i < 32; i += 8) {
        const float v = t[tx][ty + i];
        const bf16 h = __float2bfloat16(v);
        const bf16 l = __float2bfloat16(v - __bfloat162float(h));
        const size_t idx = (size_t)(n0 + ty + i) * K + k0 + tx;
        Thi[idx] = h;
        Tlo[idx] = l;
    }
}

__global__ void split_rows(const float2* __restrict__ X,
                           __nv_bfloat162* __restrict__ hi,
                           __nv_bfloat162* __restrict__ lo, int n2)
{
    const int i = blockIdx.x * blockDim.x + threadIdx.x;
    if (i < n2) {
        const float2 v = X[i];
        const bf16 hx = __float2bfloat16(v.x);
        const bf16 hy = __float2bfloat16(v.y);
        const bf16 lx = __float2bfloat16(v.x - __bfloat162float(hx));
        const bf16 ly = __float2bfloat16(v.y - __bfloat162float(hy));
        hi[i] = __nv_bfloat162(hx, hy);
        lo[i] = __nv_bfloat162(lx, ly);
    }
}

// ---------------------------------------------------------------------------
// mma.sync bf16 split GEMM. EPI=0: fp32 C = acc + bias.
//                           EPI=1: split bf16 (Chi,Clo) = split((acc+bias)*scale)
// Block tile 128 x BN, K chunk 64. 8 warps: 4(m) x 2(n).
// ---------------------------------------------------------------------------
template <int BN, int EPI>
__global__ __launch_bounds__(256) void gemm_mma(
    const bf16* __restrict__ Ahi, const bf16* __restrict__ Alo,
    const bf16* __restrict__ Bhi, const bf16* __restrict__ Blo,
    const float* __restrict__ bias, float* __restrict__ C,
    bf16* __restrict__ Chi, bf16* __restrict__ Clo,
    float scale, int Ntot)
{
    constexpr int LDS_ = 72;
    constexpr int WN = BN / 2;
    constexpr int NF = WN / 8;
    extern __shared__ bf16 smem[];
    bf16* sAh = smem;
    bf16* sAl = sAh + 128 * LDS_;
    bf16* sBh = sAl + 128 * LDS_;
    bf16* sBl = sBh + BN * LDS_;

    const int tid = threadIdx.x;
    const int wid = tid >> 5, lane = tid & 31;
    const int warp_m = wid & 3, warp_n = wid >> 2;
    const int m0 = blockIdx.y * 128;
    const int n0 = blockIdx.x * BN;

    const uint32_t uAh = smem_u32(sAh), uAl = smem_u32(sAl);
    const uint32_t uBh = smem_u32(sBh), uBl = smem_u32(sBl);

    const int lrow = lane & 15;
    const int lcol = (lane >> 4) * 8;

    const bf16* a_hi = Ahi + (size_t)m0 * KDIM;
    const bf16* a_lo = Alo + (size_t)m0 * KDIM;
    const bf16* b_hi = Bhi + (size_t)n0 * KDIM;
    const bf16* b_lo = Blo + (size_t)n0 * KDIM;

    float acc[2][NF][4] = {};

    for (int ch = 0; ch < KDIM / 64; ch++) {
        const int k0 = ch * 64;
#pragma unroll
        for (int i = tid; i < 128 * 8; i += 256) {
            const int r = i >> 3, c8 = (i & 7) * 8;
            const int so = r * LDS_ + c8;
            *(uint4*)(sAh + so) = *(const uint4*)(a_hi + (size_t)r * KDIM + k0 + c8);
            *(uint4*)(sAl + so) = *(const uint4*)(a_lo + (size_t)r * KDIM + k0 + c8);
        }
#pragma unroll
        for (int i = tid; i < BN * 8; i += 256) {
            const int r = i >> 3, c8 = (i & 7) * 8;
            const int so = r * LDS_ + c8;
            *(uint4*)(sBh + so) = *(const uint4*)(b_hi + (size_t)r * KDIM + k0 + c8);
            *(uint4*)(sBl + so) = *(const uint4*)(b_lo + (size_t)r * KDIM + k0 + c8);
        }
        __syncthreads();

#pragma unroll
        for (int ks = 0; ks < 4; ks++) {
            const int kk = ks * 16 + lcol;
            uint32_t ah[2][4], al[2][4];
#pragma unroll
            for (int mf = 0; mf < 2; mf++) {
                const int row = warp_m * 32 + mf * 16 + lrow;
                const uint32_t off = (uint32_t)(row * LDS_ + kk) * 2;
                ldsm_x4(ah[mf], uAh + off);
                ldsm_x4(al[mf], uAl + off);
            }
            uint32_t bh[NF][2], bl[NF][2];
#pragma unroll
            for (int p = 0; p < NF / 2; p++) {
                const int row = warp_n * WN + p * 16 + lrow;
                const uint32_t off = (uint32_t)(row * LDS_ + kk) * 2;
                uint32_t r4[4];
                ldsm_x4(r4, uBh + off);
                bh[2 * p][0] = r4[0]; bh[2 * p][1] = r4[2];
                bh[2 * p + 1][0] = r4[1]; bh[2 * p + 1][1] = r4[3];
                ldsm_x4(r4, uBl + off);
                bl[2 * p][0] = r4[0]; bl[2 * p][1] = r4[2];
                bl[2 * p + 1][0] = r4[1]; bl[2 * p + 1][1] = r4[3];
            }
#pragma unroll
            for (int mf = 0; mf < 2; mf++)
#pragma unroll
                for (int nf = 0; nf < NF; nf++) {
                    mma_bf16(acc[mf][nf], ah[mf], bh[nf]);
                    mma_bf16(acc[mf][nf], ah[mf], bl[nf]);
                    mma_bf16(acc[mf][nf], al[mf], bh[nf]);
                }
        }
        __syncthreads();
    }

    const int gid = lane >> 2, t4 = lane & 3;
#pragma unroll
    for (int mf = 0; mf < 2; mf++) {
        const int row = m0 + warp_m * 32 + mf * 16 + gid;
#pragma unroll
        for (int nf = 0; nf < NF; nf++) {
            const int col = n0 + warp_n * WN + nf * 8 + t4 * 2;
            const float b0 = bias[col], b1 = bias[col + 1];
            if (EPI == 0) {
                float2 o0 = make_float2(acc[mf][nf][0] + b0, acc[mf][nf][1] + b1);
                float2 o1 = make_float2(acc[mf][nf][2] + b0, acc[mf][nf][3] + b1);
                *(float2*)(C + (size_t)row * Ntot + col) = o0;
                *(float2*)(C + (size_t)(row + 8) * Ntot + col) = o1;
            } else {
                uint32_t hp, lp;
                split_pack((acc[mf][nf][0] + b0) * scale,
                           (acc[mf][nf][1] + b1) * scale, hp, lp);
                *(uint32_t*)(Chi + (size_t)row * Ntot + col) = hp;
                *(uint32_t*)(Clo + (size_t)row * Ntot + col) = lp;
                split_pack((acc[mf][nf][2] + b0) * scale,
                           (acc[mf][nf][3] + b1) * scale, hp, lp);
                *(uint32_t*)(Chi + (size_t)(row + 8) * Ntot + col) = hp;
                *(uint32_t*)(Clo + (size_t)(row + 8) * Ntot + col) = lp;
            }
        }
    }
}

// ---------------------------------------------------------------------------
// Tensor-core MQA attention (flash-v2 style, bf16-split mma.sync).
// Block = 128 queries x (head, batch); 8 warps, each owns a 16-row strip.
// KBLK=64 keys/iter. Softmax + P-repack fully in registers.
// ---------------------------------------------------------------------------
#define ALDS 72

__global__ __launch_bounds__(256) void mqa_attn_mma(
    const bf16* __restrict__ Qhi, const bf16* __restrict__ Qlo,
    const bf16* __restrict__ Khi, const bf16* __restrict__ Klo,
    const bf16* __restrict__ Vhi, const bf16* __restrict__ Vlo,
    bf16* __restrict__ Ohi, bf16* __restrict__ Olo)
{
    extern __shared__ bf16 sm[];
    // Q staging: hi [128][72] @0, lo @128*72
    // loop: Khi @0, Klo @64*72, Vhi @128*72, Vlo @192*72 (elements)
    const uint32_t uS = smem_u32(sm);
    constexpr uint32_t KLO = 64 * ALDS * 2;     // byte offsets
    constexpr uint32_t VHI = 128 * ALDS * 2;
    constexpr uint32_t VLO = 192 * ALDS * 2;

    const int tid = threadIdx.x, wid = tid >> 5, lane = tid & 31;
    const int h = blockIdx.y, b = blockIdx.z;
    const int q0 = blockIdx.x * 128;
    const size_t qrow0 = (size_t)b * SEQ + q0;

    const int lrow = lane & 15;
    const int lcol = (lane >> 4) * 8;

    // ---- stage Q tile (hi/lo), extract per-warp fragments, keep in regs
    {
        const bf16* qh_g = Qhi + qrow0 * HID_DIM + h * HDIM;
        const bf16* ql_g = Qlo + qrow0 * HID_DIM + h * HDIM;
#pragma unroll
        for (int i = tid; i < 128 * 8; i += 256) {
            const int r = i >> 3, c8 = (i & 7) * 8;
            const int so = r * ALDS + c8;
            *(uint4*)(sm + so) = *(const uint4*)(qh_g + (size_t)r * HID_DIM + c8);
            *(uint4*)(sm + 128 * ALDS + so) = *(const uint4*)(ql_g + (size_t)r * HID_DIM + c8);
        }
    }
    __syncthreads();
    uint32_t qh[4][4], ql[4][4];
#pragma unroll
    for (int ks = 0; ks < 4; ks++) {
        const uint32_t off = (uint32_t)((wid * 16 + lrow) * ALDS + ks * 16 + lcol) * 2;
        ldsm_x4(qh[ks], uS + off);
        ldsm_x4(ql[ks], uS + 128 * ALDS * 2 + off);
    }

    const bf16* kh_g = Khi + (size_t)b * SEQ * HDIM;
    const bf16* kl_g = Klo + (size_t)b * SEQ * HDIM;
    const bf16* vh_g = Vhi + (size_t)b * SEQ * HDIM;
    const bf16* vl_g = Vlo + (size_t)b * SEQ * HDIM;

    float m1 = -1e30f, m2 = -1e30f, lp1 = 0.0f, lp2 = 0.0f;
    float oacc[8][4] = {};

    for (int k0 = 0; k0 < SEQ; k0 += 64) {
        __syncthreads();   // previous iter (or Q frag extraction) done with smem
#pragma unroll
        for (int i = tid; i < 64 * 8; i += 256) {
            const int r = i >> 3, c8 = (i & 7) * 8;
            const int so = r * ALDS + c8;
            const size_t g = (size_t)(k0 + r) * HDIM + c8;
            *(uint4*)(sm + so) = *(const uint4*)(kh_g + g);
            *(uint4*)(sm + 64 * ALDS + so) = *(const uint4*)(kl_g + g);
            *(uint4*)(sm + 128 * ALDS + so) = *(const uint4*)(vh_g + g);
            *(uint4*)(sm + 192 * ALDS + so) = *(const uint4*)(vl_g + g);
        }
        __syncthreads();

        // ---- scores: 16 rows x 64 keys, 3-term split
        float sc[8][4] = {};
#pragma unroll
        for (int ks = 0; ks < 4; ks++) {
#pragma unroll
            for (int p = 0; p < 4; p++) {
                const uint32_t off =
                    (uint32_t)((p * 16 + lrow) * ALDS + ks * 16 + lcol) * 2;
                uint32_t rh[4], rl[4];
                ldsm_x4(rh, uS + off);
                ldsm_x4(rl, uS + KLO + off);
                uint32_t b0h[2] = {rh[0], rh[2]}, b1h[2] = {rh[1], rh[3]};
                uint32_t b0l[2] = {rl[0], rl[2]}, b1l[2] = {rl[1], rl[3]};
                mma_bf16(sc[2 * p], qh[ks], b0h);
                mma_bf16(sc[2 * p], qh[ks], b0l);
                mma_bf16(sc[2 * p], ql[ks], b0h);
                mma_bf16(sc[2 * p + 1], qh[ks], b1h);
                mma_bf16(sc[2 * p + 1], qh[ks], b1l);
                mma_bf16(sc[2 * p + 1], ql[ks], b1h);
            }
        }

        // ---- online softmax in registers (rows r=lane/4 and r+8)
        float mx1 = m1, mx2 = m2;
#pragma unroll
        for (int nf = 0; nf < 8; nf++) {
            mx1 = fmaxf(mx1, fmaxf(sc[nf][0], sc[nf][1]));
            mx2 = fmaxf(mx2, fmaxf(sc[nf][2], sc[nf][3]));
        }
        mx1 = fmaxf(mx1, __shfl_xor_sync(0xffffffffu, mx1, 1));
        mx1 = fmaxf(mx1, __shfl_xor_sync(0xffffffffu, mx1, 2));
        mx2 = fmaxf(mx2, __shfl_xor_sync(0xffffffffu, mx2, 1));
        mx2 = fmaxf(mx2, __shfl_xor_sync(0xffffffffu, mx2, 2));
        const float a1 = __expf(m1 - mx1);
        const float a2 = __expf(m2 - mx2);
        m1 = mx1; m2 = mx2;

        float s1 = 0.0f, s2 = 0.0f;
        uint32_t phr1[8], phr2[8], plr1[8], plr2[8];
#pragma unroll
        for (int nf = 0; nf < 8; nf++) {
            const float p0 = __expf(sc[nf][0] - mx1);
            const float p1 = __expf(sc[nf][1] - mx1);
            const float p2 = __expf(sc[nf][2] - mx2);
            const float p3 = __expf(sc[nf][3] - mx2);
            s1 += p0 + p1; s2 += p2 + p3;
            split_pack(p0, p1, phr1[nf], plr1[nf]);
            split_pack(p2, p3, phr2[nf], plr2[nf]);
        }
        lp1 = lp1 * a1 + s1;
        lp2 = lp2 * a2 + s2;
#pragma unroll
        for (int nf = 0; nf < 8; nf++) {
            oacc[nf][0] *= a1; oacc[nf][1] *= a1;
            oacc[nf][2] *= a2; oacc[nf][3] *= a2;
        }

        // ---- PV: out 16 rows x 64 dims, 3-term split; P from registers
#pragma unroll
        for (int ks = 0; ks < 4; ks++) {
            uint32_t ah[4] = {phr1[2 * ks], phr2[2 * ks],
                              phr1[2 * ks + 1], phr2[2 * ks + 1]};
            uint32_t al[4] = {plr1[2 * ks], plr2[2 * ks],
                              plr1[2 * ks + 1], plr2[2 * ks + 1]};
#pragma unroll
            for (int p = 0; p < 4; p++) {
                const uint32_t off =
                    (uint32_t)((ks * 16 + lrow) * ALDS + p * 16 + lcol) * 2;
                uint32_t rh[4], rl[4];
                ldsm_x4_t(rh, uS + VHI + off);
                ldsm_x4_t(rl, uS + VLO + off);
                uint32_t b0h[2] = {rh[0], rh[1]}, b1h[2] = {rh[2], rh[3]};
                uint32_t b0l[2] = {rl[0], rl[1]}, b1l[2] = {rl[2], rl[3]};
                mma_bf16(oacc[2 * p], ah, b0h);
                mma_bf16(oacc[2 * p], ah, b0l);
                mma_bf16(oacc[2 * p], al, b0h);
                mma_bf16(oacc[2 * p + 1], ah, b1h);
                mma_bf16(oacc[2 * p + 1], ah, b1l);
                mma_bf16(oacc[2 * p + 1], al, b1h);
            }
        }
    }

    // ---- finalize: row sums, normalize, write split bf16 output
    lp1 += __shfl_xor_sync(0xffffffffu, lp1, 1);
    lp1 += __shfl_xor_sync(0xffffffffu, lp1, 2);
    lp2 += __shfl_xor_sync(0xffffffffu, lp2, 1);
    lp2 += __shfl_xor_sync(0xffffffffu, lp2, 2);
    const float i1 = 1.0f / lp1, i2 = 1.0f / lp2;

    const size_t row1 = qrow0 + wid * 16 + (lane >> 2);
    const size_t row2 = row1 + 8;
#pragma unroll
    for (int nf = 0; nf < 8; nf++) {
        const int col = h * HDIM + nf * 8 + (lane & 3) * 2;
        uint32_t hp, lp;
        split_pack(oacc[nf][0] * i1, oacc[nf][1] * i1, hp, lp);
        *(uint32_t*)(Ohi + row1 * HID_DIM + col) = hp;
        *(uint32_t*)(Olo + row1 * HID_DIM + col) = lp;
        split_pack(oacc[nf][2] * i2, oacc[nf][3] * i2, hp, lp);
        *(uint32_t*)(Ohi + row2 * HID_DIM + col) = hp;
        *(uint32_t*)(Olo + row2 * HID_DIM + col) = lp;
    }
}

static const int GEMM128_SMEM = (2 * 128 + 2 * 128) * 72 * (int)sizeof(bf16); // 73728
static const int GEMM64_SMEM  = (2 * 128 + 2 * 64) * 72 * (int)sizeof(bf16);  // 55296
static const int ATTN_SMEM    = 256 * ALDS * (int)sizeof(bf16);               // 36864

// ---------------------------------------------------------------------------
// Launch
// ---------------------------------------------------------------------------
extern "C" void kernel_launch(void* const* d_in, const int* in_sizes, int n_in,
                              void* d_out, int out_size)
{
    const float* query = (const float*)d_in[0];
    const float* key   = (const float*)d_in[1];
    const float* value = (const float*)d_in[2];
    const float* Wq    = (const float*)d_in[3];
    const float* bq    = (const float*)d_in[4];
    const float* Wk    = (const float*)d_in[5];
    const float* bk    = (const float*)d_in[6];
    const float* Wv    = (const float*)d_in[7];
    const float* bv    = (const float*)d_in[8];
    const float* Wo    = (const float*)d_in[9];
    const float* bo    = (const float*)d_in[10];
    float* out = (float*)d_out;

    void *qh, *ql, *kh, *kl, *vh, *vl;
    void *wqh, *wql, *wkh, *wkl, *wvh, *wvl, *woh, *wol;
    void *qph, *qpl, *kph, *kpl, *vph, *vpl, *oh, *ol;
    cudaGetSymbolAddress(&qh, g_qhi); cudaGetSymbolAddress(&ql, g_qlo);
    cudaGetSymbolAddress(&kh, g_khi); cudaGetSymbolAddress(&kl, g_klo);
    cudaGetSymbolAddress(&vh, g_vhi); cudaGetSymbolAddress(&vl, g_vlo);
    cudaGetSymbolAddress(&wqh, g_WqThi); cudaGetSymbolAddress(&wql, g_WqTlo);
    cudaGetSymbolAddress(&wkh, g_WkThi); cudaGetSymbolAddress(&wkl, g_WkTlo);
    cudaGetSymbolAddress(&wvh, g_WvThi); cudaGetSymbolAddress(&wvl, g_WvTlo);
    cudaGetSymbolAddress(&woh, g_WoThi); cudaGetSymbolAddress(&wol, g_WoTlo);
    cudaGetSymbolAddress(&qph, g_qPhi); cudaGetSymbolAddress(&qpl, g_qPlo);
    cudaGetSymbolAddress(&kph, g_kPhi); cudaGetSymbolAddress(&kpl, g_kPlo);
    cudaGetSymbolAddress(&vph, g_vPhi); cudaGetSymbolAddress(&vpl, g_vPlo);
    cudaGetSymbolAddress(&oh, g_ohi);   cudaGetSymbolAddress(&ol, g_olo);

    cudaFuncSetAttribute((const void*)gemm_mma<128, 0>,
                         cudaFuncAttributeMaxDynamicSharedMemorySize, GEMM128_SMEM);
    cudaFuncSetAttribute((const void*)gemm_mma<128, 1>,
                         cudaFuncAttributeMaxDynamicSharedMemorySize, GEMM128_SMEM);
    cudaFuncSetAttribute((const void*)gemm_mma<64, 1>,
                         cudaFuncAttributeMaxDynamicSharedMemorySize, GEMM64_SMEM);

    // --- prep: transpose+split weights, split inputs ---
    {
        dim3 blk(32, 8);
        transpose_split_w<<<dim3(HID_DIM / 32, KDIM / 32), blk>>>(
            Wq, (bf16*)wqh, (bf16*)wql, KDIM, HID_DIM);
        transpose_split_w<<<dim3(HDIM / 32, KDIM / 32), blk>>>(
            Wk, (bf16*)wkh, (bf16*)wkl, KDIM, HDIM);
        transpose_split_w<<<dim3(HDIM / 32, KDIM / 32), blk>>>(
            Wv, (bf16*)wvh, (bf16*)wvl, KDIM, HDIM);
        transpose_split_w<<<dim3(IN_DIM / 32, KDIM / 32), blk>>>(
            Wo, (bf16*)woh, (bf16*)wol, KDIM, IN_DIM);
        const int n2 = MROWS * KDIM / 2;
        const int g = (n2 + 255) / 256;
        split_rows<<<g, 256>>>((const float2*)query, (__nv_bfloat162*)qh,
                               (__nv_bfloat162*)ql, n2);
        split_rows<<<g, 256>>>((const float2*)key, (__nv_bfloat162*)kh,
                               (__nv_bfloat162*)kl, n2);
        split_rows<<<g, 256>>>((const float2*)value, (__nv_bfloat162*)vh,
                               (__nv_bfloat162*)vl, n2);
    }
    // --- projections (split epilogues; Q pre-scaled by 1/sqrt(1024)) ---
    gemm_mma<128, 1><<<dim3(HID_DIM / 128, MROWS / 128), 256, GEMM128_SMEM>>>(
        (const bf16*)qh, (const bf16*)ql, (const bf16*)wqh, (const bf16*)wql,
        bq, nullptr, (bf16*)qph, (bf16*)qpl, 1.0f / 32.0f, HID_DIM);
    gemm_mma<64, 1><<<dim3(1, MROWS / 128), 256, GEMM64_SMEM>>>(
        (const bf16*)kh, (const bf16*)kl, (const bf16*)wkh, (const bf16*)wkl,
        bk, nullptr, (bf16*)kph, (bf16*)kpl, 1.0f, HDIM);
    gemm_mma<64, 1><<<dim3(1, MROWS / 128), 256, GEMM64_SMEM>>>(
        (const bf16*)vh, (const bf16*)vl, (const bf16*)wvh, (const bf16*)wvl,
        bv, nullptr, (bf16*)vph, (bf16*)vpl, 1.0f, HDIM);

    // --- tensor-core attention ---
    {
        dim3 grid(SEQ / 128, NHEAD, BATCH);
        mqa_attn_mma<<<grid, 256, ATTN_SMEM>>>(
            (const bf16*)qph, (const bf16*)qpl,
            (const bf16*)kph, (const bf16*)kpl,
            (const bf16*)vph, (const bf16*)vpl,
            (bf16*)oh, (bf16*)ol);
    }

    // --- O-projection -> d_out (fp32 + bias) ---
    gemm_mma<128, 0><<<dim3(IN_DIM / 128, MROWS / 128), 256, GEMM128_SMEM>>>(
        (const bf16*)oh, (const bf16*)ol, (const bf16*)woh, (const bf16*)wol,
        bo, out, nullptr, nullptr, 1.0f, IN_DIM);
}

// round 7
// speedup vs baseline: 2.9224x; 1.1174x over previous
#include <cuda_runtime.h>
#include <cuda_bf16.h>
#include <cstdint>

typedef __nv_bfloat16 bf16;

#define BATCH 2
#define SEQ 2048
#define IN_DIM 1024
#define HID_DIM 1024
#define NHEAD 16
#define HDIM 64
#define KDIM 1024
#define MROWS 4096

// ---------------------------------------------------------------------------
// Scratch (__device__ globals; allocation-free rule)
// ---------------------------------------------------------------------------
__device__ bf16 g_qhi[MROWS * KDIM], g_qlo[MROWS * KDIM];
__device__ bf16 g_khi[MROWS * KDIM], g_klo[MROWS * KDIM];
__device__ bf16 g_vhi[MROWS * KDIM], g_vlo[MROWS * KDIM];
__device__ bf16 g_WqThi[HID_DIM * KDIM], g_WqTlo[HID_DIM * KDIM];
__device__ bf16 g_WkThi[HDIM * KDIM],   g_WkTlo[HDIM * KDIM];
__device__ bf16 g_WvThi[HDIM * KDIM],   g_WvTlo[HDIM * KDIM];
__device__ bf16 g_WoThi[IN_DIM * KDIM], g_WoTlo[IN_DIM * KDIM];
__device__ bf16 g_qPhi[MROWS * HID_DIM], g_qPlo[MROWS * HID_DIM];
__device__ bf16 g_kPhi[MROWS * HDIM],   g_kPlo[MROWS * HDIM];
__device__ bf16 g_vPhi[MROWS * HDIM],   g_vPlo[MROWS * HDIM];
__device__ bf16 g_ohi[MROWS * HID_DIM], g_olo[MROWS * HID_DIM];

// ---------------------------------------------------------------------------
// PTX helpers (all sm_80-era; legal in family-generic PTX)
// ---------------------------------------------------------------------------
__device__ __forceinline__ uint32_t smem_u32(const void* p) {
    uint32_t a;
    asm("{ .reg .u64 t; cvta.to.shared.u64 t, %1; cvt.u32.u64 %0, t; }"
        : "=r"(a) : "l"(p));
    return a;
}
__device__ __forceinline__ void ldsm_x4(uint32_t* r, uint32_t addr) {
    asm volatile("ldmatrix.sync.aligned.m8n8.x4.shared.b16 {%0,%1,%2,%3}, [%4];"
                 : "=r"(r[0]), "=r"(r[1]), "=r"(r[2]), "=r"(r[3]) : "r"(addr));
}
__device__ __forceinline__ void ldsm_x4_t(uint32_t* r, uint32_t addr) {
    asm volatile("ldmatrix.sync.aligned.m8n8.x4.trans.shared.b16 {%0,%1,%2,%3}, [%4];"
                 : "=r"(r[0]), "=r"(r[1]), "=r"(r[2]), "=r"(r[3]) : "r"(addr));
}
__device__ __forceinline__ void mma_bf16(float* d, const uint32_t* a,
                                         const uint32_t* b) {
    asm volatile(
        "mma.sync.aligned.m16n8k16.row.col.f32.bf16.bf16.f32 "
        "{%0,%1,%2,%3}, {%4,%5,%6,%7}, {%8,%9}, {%0,%1,%2,%3};"
        : "+f"(d[0]), "+f"(d[1]), "+f"(d[2]), "+f"(d[3])
        : "r"(a[0]), "r"(a[1]), "r"(a[2]), "r"(a[3]), "r"(b[0]), "r"(b[1]));
}
__device__ __forceinline__ void cp16(uint32_t smem, const void* g) {
    asm volatile("cp.async.cg.shared.global [%0], [%1], 16;"
                 :: "r"(smem), "l"(g));
}
__device__ __forceinline__ void cp_commit() {
    asm volatile("cp.async.commit_group;" ::: "memory");
}
__device__ __forceinline__ void cp_wait1() {
    asm volatile("cp.async.wait_group 1;" ::: "memory");
}
__device__ __forceinline__ void cp_wait0() {
    asm volatile("cp.async.wait_group 0;" ::: "memory");
}
__device__ __forceinline__ void split_pack(float e, float o,
                                           uint32_t& hp, uint32_t& lp) {
    const bf16 he = __float2bfloat16(e), ho = __float2bfloat16(o);
    const bf16 le = __float2bfloat16(e - __bfloat162float(he));
    const bf16 lo2 = __float2bfloat16(o - __bfloat162float(ho));
    __nv_bfloat162 H(he, ho), L(le, lo2);
    hp = *reinterpret_cast<uint32_t*>(&H);
    lp = *reinterpret_cast<uint32_t*>(&L);
}

// ---------------------------------------------------------------------------
// Prep kernels
// ---------------------------------------------------------------------------
__global__ void transpose_split_w(const float* __restrict__ W,
                                  bf16* __restrict__ Thi, bf16* __restrict__ Tlo,
                                  int K, int N)
{
    __shared__ float t[32][33];
    const int n0 = blockIdx.x * 32, k0 = blockIdx.y * 32;
    const int tx = threadIdx.x, ty = threadIdx.y;
#pragma unroll
    for (int i = 0; i < 32; i += 8)
        t[ty + i][tx] = W[(size_t)(k0 + ty + i) * N + n0 + tx];
    __syncthreads();
#pragma unroll
    for (int i = 0; i < 32; i += 8) {
        const float v = t[tx][ty + i];
        const bf16 h = __float2bfloat16(v);
        const bf16 l = __float2bfloat16(v - __bfloat162float(h));
        const size_t idx = (size_t)(n0 + ty + i) * K + k0 + tx;
        Thi[idx] = h;
        Tlo[idx] = l;
    }
}

__global__ void split_rows(const float2* __restrict__ X,
                           __nv_bfloat162* __restrict__ hi,
                           __nv_bfloat162* __restrict__ lo, int n2)
{
    const int i = blockIdx.x * blockDim.x + threadIdx.x;
    if (i < n2) {
        const float2 v = X[i];
        const bf16 hx = __float2bfloat16(v.x);
        const bf16 hy = __float2bfloat16(v.y);
        const bf16 lx = __float2bfloat16(v.x - __bfloat162float(hx));
        const bf16 ly = __float2bfloat16(v.y - __bfloat162float(hy));
        hi[i] = __nv_bfloat162(hx, hy);
        lo[i] = __nv_bfloat162(lx, ly);
    }
}

// ---------------------------------------------------------------------------
// cp.async double-buffered mma.sync bf16 split GEMM.
// EPI=0: fp32 C = acc + bias. EPI=1: split bf16 (Chi,Clo)=split((acc+bias)*scale)
// Tile BM x BN, K chunk 64. 8 warps: 4(m) x 2(n). MF = BM/64.
// ---------------------------------------------------------------------------
template <int BM, int BN, int EPI>
__global__ __launch_bounds__(256) void gemm_mma(
    const bf16* __restrict__ Ahi, const bf16* __restrict__ Alo,
    const bf16* __restrict__ Bhi, const bf16* __restrict__ Blo,
    const float* __restrict__ bias, float* __restrict__ C,
    bf16* __restrict__ Chi, bf16* __restrict__ Clo,
    float scale, int Ntot)
{
    constexpr int MF = BM / 64;
    constexpr int WN = BN / 2;
    constexpr int NF = WN / 8;
    constexpr uint32_t ROWB = 144;               // 72 bf16 per row
    constexpr uint32_t OAL = BM * ROWB;
    constexpr uint32_t OBH = 2 * BM * ROWB;
    constexpr uint32_t OBL = OBH + BN * ROWB;
    constexpr uint32_t STAGE = (2 * BM + 2 * BN) * ROWB;
    constexpr int NCH = KDIM / 64;

    extern __shared__ char smem[];
    const uint32_t uS = smem_u32(smem);

    const int tid = threadIdx.x;
    const int wid = tid >> 5, lane = tid & 31;
    const int warp_m = wid & 3, warp_n = wid >> 2;
    const int m0 = blockIdx.y * BM;
    const int n0 = blockIdx.x * BN;
    const int lrow = lane & 15;
    const int lcol = (lane >> 4) * 8;

    const bf16* a_hi = Ahi + (size_t)m0 * KDIM;
    const bf16* a_lo = Alo + (size_t)m0 * KDIM;
    const bf16* b_hi = Bhi + (size_t)n0 * KDIM;
    const bf16* b_lo = Blo + (size_t)n0 * KDIM;

    auto issue = [&](int ch, int buf) {
        const int k0 = ch * 64;
        const uint32_t base = uS + (uint32_t)buf * STAGE;
#pragma unroll
        for (int i = tid; i < BM * 8; i += 256) {
            const int r = i >> 3, c8 = (i & 7) * 8;
            const uint32_t so = (uint32_t)r * ROWB + c8 * 2;
            const size_t g = (size_t)r * KDIM + k0 + c8;
            cp16(base + so, a_hi + g);
            cp16(base + OAL + so, a_lo + g);
        }
#pragma unroll
        for (int i = tid; i < BN * 8; i += 256) {
            const int r = i >> 3, c8 = (i & 7) * 8;
            const uint32_t so = (uint32_t)r * ROWB + c8 * 2;
            const size_t g = (size_t)r * KDIM + k0 + c8;
            cp16(base + OBH + so, b_hi + g);
            cp16(base + OBL + so, b_lo + g);
        }
    };

    float acc[MF][NF][4] = {};

    issue(0, 0);
    cp_commit();

    for (int ch = 0; ch < NCH; ch++) {
        if (ch + 1 < NCH) {
            issue(ch + 1, (ch + 1) & 1);
            cp_commit();
            cp_wait1();
        } else {
            cp_wait0();
        }
        __syncthreads();

        const uint32_t base = uS + (uint32_t)(ch & 1) * STAGE;
#pragma unroll
        for (int ks = 0; ks < 4; ks++) {
            const int kk = ks * 16 + lcol;
            uint32_t ah[MF][4], al[MF][4];
#pragma unroll
            for (int mf = 0; mf < MF; mf++) {
                const int row = warp_m * (BM / 4) + mf * 16 + lrow;
                const uint32_t off = (uint32_t)row * ROWB + kk * 2;
                ldsm_x4(ah[mf], base + off);
                ldsm_x4(al[mf], base + OAL + off);
            }
            uint32_t bh[NF][2], bl[NF][2];
#pragma unroll
            for (int p = 0; p < NF / 2; p++) {
                const int row = warp_n * WN + p * 16 + lrow;
                const uint32_t off = (uint32_t)row * ROWB + kk * 2;
                uint32_t r4[4];
                ldsm_x4(r4, base + OBH + off);
                bh[2 * p][0] = r4[0]; bh[2 * p][1] = r4[2];
                bh[2 * p + 1][0] = r4[1]; bh[2 * p + 1][1] = r4[3];
                ldsm_x4(r4, base + OBL + off);
                bl[2 * p][0] = r4[0]; bl[2 * p][1] = r4[2];
                bl[2 * p + 1][0] = r4[1]; bl[2 * p + 1][1] = r4[3];
            }
#pragma unroll
            for (int mf = 0; mf < MF; mf++)
#pragma unroll
                for (int nf = 0; nf < NF; nf++) {
                    mma_bf16(acc[mf][nf], ah[mf], bh[nf]);
                    mma_bf16(acc[mf][nf], ah[mf], bl[nf]);
                    mma_bf16(acc[mf][nf], al[mf], bh[nf]);
                }
        }
        __syncthreads();
    }

    const int gid = lane >> 2, t4 = lane & 3;
#pragma unroll
    for (int mf = 0; mf < MF; mf++) {
        const int row = m0 + warp_m * (BM / 4) + mf * 16 + gid;
#pragma unroll
        for (int nf = 0; nf < NF; nf++) {
            const int col = n0 + warp_n * WN + nf * 8 + t4 * 2;
            const float b0 = bias[col], b1 = bias[col + 1];
            if (EPI == 0) {
                float2 o0 = make_float2(acc[mf][nf][0] + b0, acc[mf][nf][1] + b1);
                float2 o1 = make_float2(acc[mf][nf][2] + b0, acc[mf][nf][3] + b1);
                *(float2*)(C + (size_t)row * Ntot + col) = o0;
                *(float2*)(C + (size_t)(row + 8) * Ntot + col) = o1;
            } else {
                uint32_t hp, lp;
                split_pack((acc[mf][nf][0] + b0) * scale,
                           (acc[mf][nf][1] + b1) * scale, hp, lp);
                *(uint32_t*)(Chi + (size_t)row * Ntot + col) = hp;
                *(uint32_t*)(Clo + (size_t)row * Ntot + col) = lp;
                split_pack((acc[mf][nf][2] + b0) * scale,
                           (acc[mf][nf][3] + b1) * scale, hp, lp);
                *(uint32_t*)(Chi + (size_t)(row + 8) * Ntot + col) = hp;
                *(uint32_t*)(Clo + (size_t)(row + 8) * Ntot + col) = lp;
            }
        }
    }
}

// ---------------------------------------------------------------------------
// Tensor-core MQA attention, cp.async double-buffered K/V.
// Block = 128 queries x (head, batch); 8 warps x 16-row strips; KBLK=64.
// ---------------------------------------------------------------------------
#define ALDS 72

__global__ __launch_bounds__(256) void mqa_attn_mma(
    const bf16* __restrict__ Qhi, const bf16* __restrict__ Qlo,
    const bf16* __restrict__ Khi, const bf16* __restrict__ Klo,
    const bf16* __restrict__ Vhi, const bf16* __restrict__ Vlo,
    bf16* __restrict__ Ohi, bf16* __restrict__ Olo)
{
    // smem: Q region 36864B (hi 128x72, lo 128x72), then 2 stages of
    // 36864B each (Khi 64x72, Klo, Vhi, Vlo).
    constexpr uint32_t ROWB = 144;
    constexpr uint32_t QLO = 128 * ROWB;          // 18432
    constexpr uint32_t ST0 = 256 * ROWB;          // 36864
    constexpr uint32_t STG = 256 * ROWB;          // stage size
    constexpr uint32_t KLO = 64 * ROWB;
    constexpr uint32_t VHI = 128 * ROWB;
    constexpr uint32_t VLO = 192 * ROWB;
    constexpr int NCH = SEQ / 64;                 // 32

    extern __shared__ char smc[];
    bf16* sm = (bf16*)smc;
    const uint32_t uS = smem_u32(sm);

    const int tid = threadIdx.x, wid = tid >> 5, lane = tid & 31;
    const int h = blockIdx.y, b = blockIdx.z;
    const int q0 = blockIdx.x * 128;
    const size_t qrow0 = (size_t)b * SEQ + q0;
    const int lrow = lane & 15;
    const int lcol = (lane >> 4) * 8;

    const bf16* kh_g = Khi + (size_t)b * SEQ * HDIM;
    const bf16* kl_g = Klo + (size_t)b * SEQ * HDIM;
    const bf16* vh_g = Vhi + (size_t)b * SEQ * HDIM;
    const bf16* vl_g = Vlo + (size_t)b * SEQ * HDIM;

    auto issue = [&](int ch, int buf) {
        const int k0 = ch * 64;
        const uint32_t base = uS + ST0 + (uint32_t)buf * STG;
#pragma unroll
        for (int i = tid; i < 64 * 8; i += 256) {
            const int r = i >> 3, c8 = (i & 7) * 8;
            const uint32_t so = (uint32_t)r * ROWB + c8 * 2;
            const size_t g = (size_t)(k0 + r) * HDIM + c8;
            cp16(base + so, kh_g + g);
            cp16(base + KLO + so, kl_g + g);
            cp16(base + VHI + so, vh_g + g);
            cp16(base + VLO + so, vl_g + g);
        }
    };

    // kick off chunk 0 first, then stage Q while it flies
    issue(0, 0);
    cp_commit();
    {
        const bf16* qh_g = Qhi + qrow0 * HID_DIM + h * HDIM;
        const bf16* ql_g = Qlo + qrow0 * HID_DIM + h * HDIM;
#pragma unroll
        for (int i = tid; i < 128 * 8; i += 256) {
            const int r = i >> 3, c8 = (i & 7) * 8;
            const uint32_t so = (uint32_t)r * ROWB + c8 * 2;
            const size_t g = (size_t)r * HID_DIM + c8;
            *(uint4*)(smc + so) = *(const uint4*)(qh_g + g);
            *(uint4*)(smc + QLO + so) = *(const uint4*)(ql_g + g);
        }
    }
    __syncthreads();
    uint32_t qh[4][4], ql[4][4];
#pragma unroll
    for (int ks = 0; ks < 4; ks++) {
        const uint32_t off = (uint32_t)(wid * 16 + lrow) * ROWB + (ks * 16 + lcol) * 2;
        ldsm_x4(qh[ks], uS + off);
        ldsm_x4(ql[ks], uS + QLO + off);
    }

    float m1 = -1e30f, m2 = -1e30f, lp1 = 0.0f, lp2 = 0.0f;
    float oacc[8][4] = {};

    for (int ch = 0; ch < NCH; ch++) {
        if (ch + 1 < NCH) {
            issue(ch + 1, (ch + 1) & 1);
            cp_commit();
            cp_wait1();
        } else {
            cp_wait0();
        }
        __syncthreads();

        const uint32_t base = uS + ST0 + (uint32_t)(ch & 1) * STG;

        // ---- scores: 16 rows x 64 keys, 3-term split
        float sc[8][4] = {};
#pragma unroll
        for (int ks = 0; ks < 4; ks++) {
#pragma unroll
            for (int p = 0; p < 4; p++) {
                const uint32_t off =
                    (uint32_t)(p * 16 + lrow) * ROWB + (ks * 16 + lcol) * 2;
                uint32_t rh[4], rl[4];
                ldsm_x4(rh, base + off);
                ldsm_x4(rl, base + KLO + off);
                uint32_t b0h[2] = {rh[0], rh[2]}, b1h[2] = {rh[1], rh[3]};
                uint32_t b0l[2] = {rl[0], rl[2]}, b1l[2] = {rl[1], rl[3]};
                mma_bf16(sc[2 * p], qh[ks], b0h);
                mma_bf16(sc[2 * p], qh[ks], b0l);
                mma_bf16(sc[2 * p], ql[ks], b0h);
                mma_bf16(sc[2 * p + 1], qh[ks], b1h);
                mma_bf16(sc[2 * p + 1], qh[ks], b1l);
                mma_bf16(sc[2 * p + 1], ql[ks], b1h);
            }
        }

        // ---- online softmax in registers
        float mx1 = m1, mx2 = m2;
#pragma unroll
        for (int nf = 0; nf < 8; nf++) {
            mx1 = fmaxf(mx1, fmaxf(sc[nf][0], sc[nf][1]));
            mx2 = fmaxf(mx2, fmaxf(sc[nf][2], sc[nf][3]));
        }
        mx1 = fmaxf(mx1, __shfl_xor_sync(0xffffffffu, mx1, 1));
        mx1 = fmaxf(mx1, __shfl_xor_sync(0xffffffffu, mx1, 2));
        mx2 = fmaxf(mx2, __shfl_xor_sync(0xffffffffu, mx2, 1));
        mx2 = fmaxf(mx2, __shfl_xor_sync(0xffffffffu, mx2, 2));
        const float a1 = __expf(m1 - mx1);
        const float a2 = __expf(m2 - mx2);
        m1 = mx1; m2 = mx2;

        float s1 = 0.0f, s2 = 0.0f;
        uint32_t phr1[8], phr2[8], plr1[8], plr2[8];
#pragma unroll
        for (int nf = 0; nf < 8; nf++) {
            const float p0 = __expf(sc[nf][0] - mx1);
            const float p1 = __expf(sc[nf][1] - mx1);
            const float p2 = __expf(sc[nf][2] - mx2);
            const float p3 = __expf(sc[nf][3] - mx2);
            s1 += p0 + p1; s2 += p2 + p3;
            split_pack(p0, p1, phr1[nf], plr1[nf]);
            split_pack(p2, p3, phr2[nf], plr2[nf]);
        }
        lp1 = lp1 * a1 + s1;
        lp2 = lp2 * a2 + s2;
#pragma unroll
        for (int nf = 0; nf < 8; nf++) {
            oacc[nf][0] *= a1; oacc[nf][1] *= a1;
            oacc[nf][2] *= a2; oacc[nf][3] *= a2;
        }

        // ---- PV: 3-term split; P from registers
#pragma unroll
        for (int ks = 0; ks < 4; ks++) {
            uint32_t ah[4] = {phr1[2 * ks], phr2[2 * ks],
                              phr1[2 * ks + 1], phr2[2 * ks + 1]};
            uint32_t al[4] = {plr1[2 * ks], plr2[2 * ks],
                              plr1[2 * ks + 1], plr2[2 * ks + 1]};
#pragma unroll
            for (int p = 0; p < 4; p++) {
                const uint32_t off =
                    (uint32_t)(ks * 16 + lrow) * ROWB + (p * 16 + lcol) * 2;
                uint32_t rh[4], rl[4];
                ldsm_x4_t(rh, base + VHI + off);
                ldsm_x4_t(rl, base + VLO + off);
                uint32_t b0h[2] = {rh[0], rh[1]}, b1h[2] = {rh[2], rh[3]};
                uint32_t b0l[2] = {rl[0], rl[1]}, b1l[2] = {rl[2], rl[3]};
                mma_bf16(oacc[2 * p], ah, b0h);
                mma_bf16(oacc[2 * p], ah, b0l);
                mma_bf16(oacc[2 * p], al, b0h);
                mma_bf16(oacc[2 * p + 1], ah, b1h);
                mma_bf16(oacc[2 * p + 1], ah, b1l);
                mma_bf16(oacc[2 * p + 1], al, b1h);
            }
        }
        __syncthreads();
    }

    lp1 += __shfl_xor_sync(0xffffffffu, lp1, 1);
    lp1 += __shfl_xor_sync(0xffffffffu, lp1, 2);
    lp2 += __shfl_xor_sync(0xffffffffu, lp2, 1);
    lp2 += __shfl_xor_sync(0xffffffffu, lp2, 2);
    const float i1 = 1.0f / lp1, i2 = 1.0f / lp2;

    const size_t row1 = qrow0 + wid * 16 + (lane >> 2);
    const size_t row2 = row1 + 8;
#pragma unroll
    for (int nf = 0; nf < 8; nf++) {
        const int col = h * HDIM + nf * 8 + (lane & 3) * 2;
        uint32_t hp, lp;
        split_pack(oacc[nf][0] * i1, oacc[nf][1] * i1, hp, lp);
        *(uint32_t*)(Ohi + row1 * HID_DIM + col) = hp;
        *(uint32_t*)(Olo + row1 * HID_DIM + col) = lp;
        split_pack(oacc[nf][2] * i2, oacc[nf][3] * i2, hp, lp);
        *(uint32_t*)(Ohi + row2 * HID_DIM + col) = hp;
        *(uint32_t*)(Olo + row2 * HID_DIM + col) = lp;
    }
}

static const int GEMM128_SMEM = 2 * (2 * 128 + 2 * 128) * 144;  // 147456
static const int GEMM64_SMEM  = 2 * (2 * 64 + 2 * 64) * 144;    // 73728
static const int ATTN_SMEM    = 3 * 256 * 144;                  // 110592

// ---------------------------------------------------------------------------
// Launch
// ---------------------------------------------------------------------------
extern "C" void kernel_launch(void* const* d_in, const int* in_sizes, int n_in,
                              void* d_out, int out_size)
{
    const float* query = (const float*)d_in[0];
    const float* key   = (const float*)d_in[1];
    const float* value = (const float*)d_in[2];
    const float* Wq    = (const float*)d_in[3];
    const float* bq    = (const float*)d_in[4];
    const float* Wk    = (const float*)d_in[5];
    const float* bk    = (const float*)d_in[6];
    const float* Wv    = (const float*)d_in[7];
    const float* bv    = (const float*)d_in[8];
    const float* Wo    = (const float*)d_in[9];
    const float* bo    = (const float*)d_in[10];
    float* out = (float*)d_out;

    void *qh, *ql, *kh, *kl, *vh, *vl;
    void *wqh, *wql, *wkh, *wkl, *wvh, *wvl, *woh, *wol;
    void *qph, *qpl, *kph, *kpl, *vph, *vpl, *oh, *ol;
    cudaGetSymbolAddress(&qh, g_qhi); cudaGetSymbolAddress(&ql, g_qlo);
    cudaGetSymbolAddress(&kh, g_khi); cudaGetSymbolAddress(&kl, g_klo);
    cudaGetSymbolAddress(&vh, g_vhi); cudaGetSymbolAddress(&vl, g_vlo);
    cudaGetSymbolAddress(&wqh, g_WqThi); cudaGetSymbolAddress(&wql, g_WqTlo);
    cudaGetSymbolAddress(&wkh, g_WkThi); cudaGetSymbolAddress(&wkl, g_WkTlo);
    cudaGetSymbolAddress(&wvh, g_WvThi); cudaGetSymbolAddress(&wvl, g_WvTlo);
    cudaGetSymbolAddress(&woh, g_WoThi); cudaGetSymbolAddress(&wol, g_WoTlo);
    cudaGetSymbolAddress(&qph, g_qPhi); cudaGetSymbolAddress(&qpl, g_qPlo);
    cudaGetSymbolAddress(&kph, g_kPhi); cudaGetSymbolAddress(&kpl, g_kPlo);
    cudaGetSymbolAddress(&vph, g_vPhi); cudaGetSymbolAddress(&vpl, g_vPlo);
    cudaGetSymbolAddress(&oh, g_ohi);   cudaGetSymbolAddress(&ol, g_olo);

    cudaFuncSetAttribute((const void*)gemm_mma<128, 128, 0>,
                         cudaFuncAttributeMaxDynamicSharedMemorySize, GEMM128_SMEM);
    cudaFuncSetAttribute((const void*)gemm_mma<128, 128, 1>,
                         cudaFuncAttributeMaxDynamicSharedMemorySize, GEMM128_SMEM);
    cudaFuncSetAttribute((const void*)gemm_mma<64, 64, 1>,
                         cudaFuncAttributeMaxDynamicSharedMemorySize, GEMM64_SMEM);
    cudaFuncSetAttribute((const void*)mqa_attn_mma,
                         cudaFuncAttributeMaxDynamicSharedMemorySize, ATTN_SMEM);

    // --- prep ---
    {
        dim3 blk(32, 8);
        transpose_split_w<<<dim3(HID_DIM / 32, KDIM / 32), blk>>>(
            Wq, (bf16*)wqh, (bf16*)wql, KDIM, HID_DIM);
        transpose_split_w<<<dim3(HDIM / 32, KDIM / 32), blk>>>(
            Wk, (bf16*)wkh, (bf16*)wkl, KDIM, HDIM);
        transpose_split_w<<<dim3(HDIM / 32, KDIM / 32), blk>>>(
            Wv, (bf16*)wvh, (bf16*)wvl, KDIM, HDIM);
        transpose_split_w<<<dim3(IN_DIM / 32, KDIM / 32), blk>>>(
            Wo, (bf16*)woh, (bf16*)wol, KDIM, IN_DIM);
        const int n2 = MROWS * KDIM / 2;
        const int g = (n2 + 255) / 256;
        split_rows<<<g, 256>>>((const float2*)query, (__nv_bfloat162*)qh,
                               (__nv_bfloat162*)ql, n2);
        split_rows<<<g, 256>>>((const float2*)key, (__nv_bfloat162*)kh,
                               (__nv_bfloat162*)kl, n2);
        split_rows<<<g, 256>>>((const float2*)value, (__nv_bfloat162*)vh,
                               (__nv_bfloat162*)vl, n2);
    }
    // --- projections (split epilogues; Q pre-scaled by 1/sqrt(1024)) ---
    gemm_mma<128, 128, 1><<<dim3(HID_DIM / 128, MROWS / 128), 256, GEMM128_SMEM>>>(
        (const bf16*)qh, (const bf16*)ql, (const bf16*)wqh, (const bf16*)wql,
        bq, nullptr, (bf16*)qph, (bf16*)qpl, 1.0f / 32.0f, HID_DIM);
    gemm_mma<64, 64, 1><<<dim3(1, MROWS / 64), 256, GEMM64_SMEM>>>(
        (const bf16*)kh, (const bf16*)kl, (const bf16*)wkh, (const bf16*)wkl,
        bk, nullptr, (bf16*)kph, (bf16*)kpl, 1.0f, HDIM);
    gemm_mma<64, 64, 1><<<dim3(1, MROWS / 64), 256, GEMM64_SMEM>>>(
        (const bf16*)vh, (const bf16*)vl, (const bf16*)wvh, (const bf16*)wvl,
        bv, nullptr, (bf16*)vph, (bf16*)vpl, 1.0f, HDIM);

    // --- tensor-core attention ---
    {
        dim3 grid(SEQ / 128, NHEAD, BATCH);
        mqa_attn_mma<<<grid, 256, ATTN_SMEM>>>(
            (const bf16*)qph, (const bf16*)qpl,
            (const bf16*)kph, (const bf16*)kpl,
            (const bf16*)vph, (const bf16*)vpl,
            (bf16*)oh, (bf16*)ol);
    }

    // --- O-projection -> d_out (fp32 + bias) ---
    gemm_mma<128, 128, 0><<<dim3(IN_DIM / 128, MROWS / 128), 256, GEMM128_SMEM>>>(
        (const bf16*)oh, (const bf16*)ol, (const bf16*)woh, (const bf16*)wol,
        bo, out, nullptr, nullptr, 1.0f, IN_DIM);
}

// round 8
// speedup vs baseline: 3.6146x; 1.2369x over previous
#include <cuda_runtime.h>
#include <cuda_bf16.h>
#include <cuda_fp16.h>
#include <cstdint>

typedef __nv_bfloat16 bf16;

#define BATCH 2
#define SEQ 2048
#define IN_DIM 1024
#define HID_DIM 1024
#define NHEAD 16
#define HDIM 64
#define KDIM 1024
#define MROWS 4096

// ---------------------------------------------------------------------------
// Scratch (__device__ globals; allocation-free rule)
// ---------------------------------------------------------------------------
__device__ bf16 g_qhi[MROWS * KDIM], g_qlo[MROWS * KDIM];
__device__ bf16 g_khi[MROWS * KDIM], g_klo[MROWS * KDIM];
__device__ bf16 g_vhi[MROWS * KDIM], g_vlo[MROWS * KDIM];
__device__ bf16 g_WqThi[HID_DIM * KDIM], g_WqTlo[HID_DIM * KDIM];
__device__ bf16 g_WkThi[HDIM * KDIM],   g_WkTlo[HDIM * KDIM];
__device__ bf16 g_WvThi[HDIM * KDIM],   g_WvTlo[HDIM * KDIM];
__device__ bf16 g_WoThi[IN_DIM * KDIM], g_WoTlo[IN_DIM * KDIM];
// projected (fp16 for attention): Q scaled by 1/32, split; K hi only; V split
__device__ __half g_qPhi[MROWS * HID_DIM], g_qPlo[MROWS * HID_DIM];
__device__ __half g_kPhi[MROWS * HDIM],   g_kPlo[MROWS * HDIM];
__device__ __half g_vPhi[MROWS * HDIM],   g_vPlo[MROWS * HDIM];
// attention output, bf16 split (A operand of O-projection)
__device__ bf16 g_ohi[MROWS * HID_DIM], g_olo[MROWS * HID_DIM];

// ---------------------------------------------------------------------------
// PTX helpers (all sm_80-era; legal in family-generic PTX)
// ---------------------------------------------------------------------------
__device__ __forceinline__ uint32_t smem_u32(const void* p) {
    uint32_t a;
    asm("{ .reg .u64 t; cvta.to.shared.u64 t, %1; cvt.u32.u64 %0, t; }"
        : "=r"(a) : "l"(p));
    return a;
}
__device__ __forceinline__ void ldsm_x4(uint32_t* r, uint32_t addr) {
    asm volatile("ldmatrix.sync.aligned.m8n8.x4.shared.b16 {%0,%1,%2,%3}, [%4];"
                 : "=r"(r[0]), "=r"(r[1]), "=r"(r[2]), "=r"(r[3]) : "r"(addr));
}
__device__ __forceinline__ void ldsm_x4_t(uint32_t* r, uint32_t addr) {
    asm volatile("ldmatrix.sync.aligned.m8n8.x4.trans.shared.b16 {%0,%1,%2,%3}, [%4];"
                 : "=r"(r[0]), "=r"(r[1]), "=r"(r[2]), "=r"(r[3]) : "r"(addr));
}
__device__ __forceinline__ void mma_bf16(float* d, const uint32_t* a,
                                         const uint32_t* b) {
    asm volatile(
        "mma.sync.aligned.m16n8k16.row.col.f32.bf16.bf16.f32 "
        "{%0,%1,%2,%3}, {%4,%5,%6,%7}, {%8,%9}, {%0,%1,%2,%3};"
        : "+f"(d[0]), "+f"(d[1]), "+f"(d[2]), "+f"(d[3])
        : "r"(a[0]), "r"(a[1]), "r"(a[2]), "r"(a[3]), "r"(b[0]), "r"(b[1]));
}
__device__ __forceinline__ void mma_f16(float* d, const uint32_t* a,
                                        const uint32_t* b) {
    asm volatile(
        "mma.sync.aligned.m16n8k16.row.col.f32.f16.f16.f32 "
        "{%0,%1,%2,%3}, {%4,%5,%6,%7}, {%8,%9}, {%0,%1,%2,%3};"
        : "+f"(d[0]), "+f"(d[1]), "+f"(d[2]), "+f"(d[3])
        : "r"(a[0]), "r"(a[1]), "r"(a[2]), "r"(a[3]), "r"(b[0]), "r"(b[1]));
}
__device__ __forceinline__ void cp16(uint32_t smem, const void* g) {
    asm volatile("cp.async.cg.shared.global [%0], [%1], 16;"
                 :: "r"(smem), "l"(g));
}
__device__ __forceinline__ void cp_commit() {
    asm volatile("cp.async.commit_group;" ::: "memory");
}
__device__ __forceinline__ void cp_wait1() {
    asm volatile("cp.async.wait_group 1;" ::: "memory");
}
__device__ __forceinline__ void cp_wait0() {
    asm volatile("cp.async.wait_group 0;" ::: "memory");
}
// bf16 split pack (for O-projection input path)
__device__ __forceinline__ void split_pack(float e, float o,
                                           uint32_t& hp, uint32_t& lp) {
    const bf16 he = __float2bfloat16(e), ho = __float2bfloat16(o);
    const bf16 le = __float2bfloat16(e - __bfloat162float(he));
    const bf16 lo2 = __float2bfloat16(o - __bfloat162float(ho));
    __nv_bfloat162 H(he, ho), L(le, lo2);
    hp = *reinterpret_cast<uint32_t*>(&H);
    lp = *reinterpret_cast<uint32_t*>(&L);
}
// fp16 split pack (for attention operand path)
__device__ __forceinline__ void split_pack_h(float e, float o,
                                             uint32_t& hp, uint32_t& lp) {
    const __half he = __float2half_rn(e), ho = __float2half_rn(o);
    const __half le = __float2half_rn(e - __half2float(he));
    const __half lo2 = __float2half_rn(o - __half2float(ho));
    __half2 H(he, ho), L(le, lo2);
    hp = *reinterpret_cast<uint32_t*>(&H);
    lp = *reinterpret_cast<uint32_t*>(&L);
}
__device__ __forceinline__ uint32_t pack_h2(float e, float o) {
    __half2 P(__float2half_rn(e), __float2half_rn(o));
    return *reinterpret_cast<uint32_t*>(&P);
}

// ---------------------------------------------------------------------------
// Prep kernels
// ---------------------------------------------------------------------------
__global__ void transpose_split_w(const float* __restrict__ W,
                                  bf16* __restrict__ Thi, bf16* __restrict__ Tlo,
                                  int K, int N)
{
    __shared__ float t[32][33];
    const int n0 = blockIdx.x * 32, k0 = blockIdx.y * 32;
    const int tx = threadIdx.x, ty = threadIdx.y;
#pragma unroll
    for (int i = 0; i < 32; i += 8)
        t[ty + i][tx] = W[(size_t)(k0 + ty + i) * N + n0 + tx];
    __syncthreads();
#pragma unroll
    for (int i = 0; i < 32; i += 8) {
        const float v = t[tx][ty + i];
        const bf16 h = __float2bfloat16(v);
        const bf16 l = __float2bfloat16(v - __bfloat162float(h));
        const size_t idx = (size_t)(n0 + ty + i) * K + k0 + tx;
        Thi[idx] = h;
        Tlo[idx] = l;
    }
}

__global__ void split_rows(const float2* __restrict__ X,
                           __nv_bfloat162* __restrict__ hi,
                           __nv_bfloat162* __restrict__ lo, int n2)
{
    const int i = blockIdx.x * blockDim.x + threadIdx.x;
    if (i < n2) {
        const float2 v = X[i];
        const bf16 hx = __float2bfloat16(v.x);
        const bf16 hy = __float2bfloat16(v.y);
        const bf16 lx = __float2bfloat16(v.x - __bfloat162float(hx));
        const bf16 ly = __float2bfloat16(v.y - __bfloat162float(hy));
        hi[i] = __nv_bfloat162(hx, hy);
        lo[i] = __nv_bfloat162(lx, ly);
    }
}

// ---------------------------------------------------------------------------
// cp.async double-buffered mma.sync bf16 3-term split GEMM.
// EPI=0: fp32 C = acc + bias.   EPI=1: fp16 split (Chi,Clo)=split((acc+b)*scale)
// ---------------------------------------------------------------------------
template <int BM, int BN, int EPI>
__global__ __launch_bounds__(256) void gemm_mma(
    const bf16* __restrict__ Ahi, const bf16* __restrict__ Alo,
    const bf16* __restrict__ Bhi, const bf16* __restrict__ Blo,
    const float* __restrict__ bias, float* __restrict__ C,
    __half* __restrict__ Chi, __half* __restrict__ Clo,
    float scale, int Ntot)
{
    constexpr int MF = BM / 64;
    constexpr int WN = BN / 2;
    constexpr int NF = WN / 8;
    constexpr uint32_t ROWB = 144;
    constexpr uint32_t OAL = BM * ROWB;
    constexpr uint32_t OBH = 2 * BM * ROWB;
    constexpr uint32_t OBL = OBH + BN * ROWB;
    constexpr uint32_t STAGE = (2 * BM + 2 * BN) * ROWB;
    constexpr int NCH = KDIM / 64;

    extern __shared__ char smem[];
    const uint32_t uS = smem_u32(smem);

    const int tid = threadIdx.x;
    const int wid = tid >> 5, lane = tid & 31;
    const int warp_m = wid & 3, warp_n = wid >> 2;
    const int m0 = blockIdx.y * BM;
    const int n0 = blockIdx.x * BN;
    const int lrow = lane & 15;
    const int lcol = (lane >> 4) * 8;

    const bf16* a_hi = Ahi + (size_t)m0 * KDIM;
    const bf16* a_lo = Alo + (size_t)m0 * KDIM;
    const bf16* b_hi = Bhi + (size_t)n0 * KDIM;
    const bf16* b_lo = Blo + (size_t)n0 * KDIM;

    auto issue = [&](int ch, int buf) {
        const int k0 = ch * 64;
        const uint32_t base = uS + (uint32_t)buf * STAGE;
#pragma unroll
        for (int i = tid; i < BM * 8; i += 256) {
            const int r = i >> 3, c8 = (i & 7) * 8;
            const uint32_t so = (uint32_t)r * ROWB + c8 * 2;
            const size_t g = (size_t)r * KDIM + k0 + c8;
            cp16(base + so, a_hi + g);
            cp16(base + OAL + so, a_lo + g);
        }
#pragma unroll
        for (int i = tid; i < BN * 8; i += 256) {
            const int r = i >> 3, c8 = (i & 7) * 8;
            const uint32_t so = (uint32_t)r * ROWB + c8 * 2;
            const size_t g = (size_t)r * KDIM + k0 + c8;
            cp16(base + OBH + so, b_hi + g);
            cp16(base + OBL + so, b_lo + g);
        }
    };

    float acc[MF][NF][4] = {};

    issue(0, 0);
    cp_commit();

    for (int ch = 0; ch < NCH; ch++) {
        if (ch + 1 < NCH) {
            issue(ch + 1, (ch + 1) & 1);
            cp_commit();
            cp_wait1();
        } else {
            cp_wait0();
        }
        __syncthreads();

        const uint32_t base = uS + (uint32_t)(ch & 1) * STAGE;
#pragma unroll
        for (int ks = 0; ks < 4; ks++) {
            const int kk = ks * 16 + lcol;
            uint32_t ah[MF][4], al[MF][4];
#pragma unroll
            for (int mf = 0; mf < MF; mf++) {
                const int row = warp_m * (BM / 4) + mf * 16 + lrow;
                const uint32_t off = (uint32_t)row * ROWB + kk * 2;
                ldsm_x4(ah[mf], base + off);
                ldsm_x4(al[mf], base + OAL + off);
            }
            uint32_t bh[NF][2], bl[NF][2];
#pragma unroll
            for (int p = 0; p < NF / 2; p++) {
                const int row = warp_n * WN + p * 16 + lrow;
                const uint32_t off = (uint32_t)row * ROWB + kk * 2;
                uint32_t r4[4];
                ldsm_x4(r4, base + OBH + off);
                bh[2 * p][0] = r4[0]; bh[2 * p][1] = r4[2];
                bh[2 * p + 1][0] = r4[1]; bh[2 * p + 1][1] = r4[3];
                ldsm_x4(r4, base + OBL + off);
                bl[2 * p][0] = r4[0]; bl[2 * p][1] = r4[2];
                bl[2 * p + 1][0] = r4[1]; bl[2 * p + 1][1] = r4[3];
            }
#pragma unroll
            for (int mf = 0; mf < MF; mf++)
#pragma unroll
                for (int nf = 0; nf < NF; nf++) {
                    mma_bf16(acc[mf][nf], ah[mf], bh[nf]);
                    mma_bf16(acc[mf][nf], ah[mf], bl[nf]);
                    mma_bf16(acc[mf][nf], al[mf], bh[nf]);
                }
        }
        __syncthreads();
    }

    const int gid = lane >> 2, t4 = lane & 3;
#pragma unroll
    for (int mf = 0; mf < MF; mf++) {
        const int row = m0 + warp_m * (BM / 4) + mf * 16 + gid;
#pragma unroll
        for (int nf = 0; nf < NF; nf++) {
            const int col = n0 + warp_n * WN + nf * 8 + t4 * 2;
            const float b0 = bias[col], b1 = bias[col + 1];
            if (EPI == 0) {
                float2 o0 = make_float2(acc[mf][nf][0] + b0, acc[mf][nf][1] + b1);
                float2 o1 = make_float2(acc[mf][nf][2] + b0, acc[mf][nf][3] + b1);
                *(float2*)(C + (size_t)row * Ntot + col) = o0;
                *(float2*)(C + (size_t)(row + 8) * Ntot + col) = o1;
            } else {
                uint32_t hp, lp;
                split_pack_h((acc[mf][nf][0] + b0) * scale,
                             (acc[mf][nf][1] + b1) * scale, hp, lp);
                *(uint32_t*)(Chi + (size_t)row * Ntot + col) = hp;
                *(uint32_t*)(Clo + (size_t)row * Ntot + col) = lp;
                split_pack_h((acc[mf][nf][2] + b0) * scale,
                             (acc[mf][nf][3] + b1) * scale, hp, lp);
                *(uint32_t*)(Chi + (size_t)(row + 8) * Ntot + col) = hp;
                *(uint32_t*)(Clo + (size_t)(row + 8) * Ntot + col) = lp;
            }
        }
    }
}

// ---------------------------------------------------------------------------
// Tensor-core MQA attention, fp16 reduced-term split.
// scores = (Qh + Ql)·Khi  (2 terms);  PV = P·(Vh + Vl)  (2 terms, P single fp16)
// Block = 128 queries x (head, batch); 8 warps x 16-row strips; KBLK=64.
// cp.async double-buffered stages of {Khi, Vhi, Vlo}.
// ---------------------------------------------------------------------------
__global__ __launch_bounds__(256) void mqa_attn_mma(
    const __half* __restrict__ Qhi, const __half* __restrict__ Qlo,
    const __half* __restrict__ Khi,
    const __half* __restrict__ Vhi, const __half* __restrict__ Vlo,
    bf16* __restrict__ Ohi, bf16* __restrict__ Olo)
{
    constexpr uint32_t ROWB = 144;
    constexpr uint32_t QLO = 128 * ROWB;          // Q lo region offset
    constexpr uint32_t ST0 = 256 * ROWB;          // 36864: end of Q region
    constexpr uint32_t STG = 192 * ROWB;          // 27648: stage {Khi,Vhi,Vlo}
    constexpr uint32_t VHI = 64 * ROWB;
    constexpr uint32_t VLO = 128 * ROWB;
    constexpr int NCH = SEQ / 64;                 // 32

    extern __shared__ char smc[];
    const uint32_t uS = smem_u32(smc);

    const int tid = threadIdx.x, wid = tid >> 5, lane = tid & 31;
    const int h = blockIdx.y, b = blockIdx.z;
    const int q0 = blockIdx.x * 128;
    const size_t qrow0 = (size_t)b * SEQ + q0;
    const int lrow = lane & 15;
    const int lcol = (lane >> 4) * 8;

    const __half* kh_g = Khi + (size_t)b * SEQ * HDIM;
    const __half* vh_g = Vhi + (size_t)b * SEQ * HDIM;
    const __half* vl_g = Vlo + (size_t)b * SEQ * HDIM;

    auto issue = [&](int ch, int buf) {
        const int k0 = ch * 64;
        const uint32_t base = uS + ST0 + (uint32_t)buf * STG;
#pragma unroll
        for (int i = tid; i < 64 * 8; i += 256) {
            const int r = i >> 3, c8 = (i & 7) * 8;
            const uint32_t so = (uint32_t)r * ROWB + c8 * 2;
            const size_t g = (size_t)(k0 + r) * HDIM + c8;
            cp16(base + so, kh_g + g);
            cp16(base + VHI + so, vh_g + g);
            cp16(base + VLO + so, vl_g + g);
        }
    };

    issue(0, 0);
    cp_commit();
    {
        const __half* qh_g = Qhi + qrow0 * HID_DIM + h * HDIM;
        const __half* ql_g = Qlo + qrow0 * HID_DIM + h * HDIM;
#pragma unroll
        for (int i = tid; i < 128 * 8; i += 256) {
            const int r = i >> 3, c8 = (i & 7) * 8;
            const uint32_t so = (uint32_t)r * ROWB + c8 * 2;
            const size_t g = (size_t)r * HID_DIM + c8;
            *(uint4*)(smc + so) = *(const uint4*)(qh_g + g);
            *(uint4*)(smc + QLO + so) = *(const uint4*)(ql_g + g);
        }
    }
    __syncthreads();
    uint32_t qh[4][4], ql[4][4];
#pragma unroll
    for (int ks = 0; ks < 4; ks++) {
        const uint32_t off = (uint32_t)(wid * 16 + lrow) * ROWB + (ks * 16 + lcol) * 2;
        ldsm_x4(qh[ks], uS + off);
        ldsm_x4(ql[ks], uS + QLO + off);
    }

    float m1 = -1e30f, m2 = -1e30f, lp1 = 0.0f, lp2 = 0.0f;
    float oacc[8][4] = {};

    for (int ch = 0; ch < NCH; ch++) {
        if (ch + 1 < NCH) {
            issue(ch + 1, (ch + 1) & 1);
            cp_commit();
            cp_wait1();
        } else {
            cp_wait0();
        }
        __syncthreads();

        const uint32_t base = uS + ST0 + (uint32_t)(ch & 1) * STG;

        // ---- scores: 16 rows x 64 keys; 2 terms (Qh + Ql) x Khi
        float sc[8][4] = {};
#pragma unroll
        for (int ks = 0; ks < 4; ks++) {
#pragma unroll
            for (int p = 0; p < 4; p++) {
                const uint32_t off =
                    (uint32_t)(p * 16 + lrow) * ROWB + (ks * 16 + lcol) * 2;
                uint32_t rh[4];
                ldsm_x4(rh, base + off);
                uint32_t b0[2] = {rh[0], rh[2]}, b1[2] = {rh[1], rh[3]};
                mma_f16(sc[2 * p], qh[ks], b0);
                mma_f16(sc[2 * p], ql[ks], b0);
                mma_f16(sc[2 * p + 1], qh[ks], b1);
                mma_f16(sc[2 * p + 1], ql[ks], b1);
            }
        }

        // ---- online softmax in registers
        float mx1 = m1, mx2 = m2;
#pragma unroll
        for (int nf = 0; nf < 8; nf++) {
            mx1 = fmaxf(mx1, fmaxf(sc[nf][0], sc[nf][1]));
            mx2 = fmaxf(mx2, fmaxf(sc[nf][2], sc[nf][3]));
        }
        mx1 = fmaxf(mx1, __shfl_xor_sync(0xffffffffu, mx1, 1));
        mx1 = fmaxf(mx1, __shfl_xor_sync(0xffffffffu, mx1, 2));
        mx2 = fmaxf(mx2, __shfl_xor_sync(0xffffffffu, mx2, 1));
        mx2 = fmaxf(mx2, __shfl_xor_sync(0xffffffffu, mx2, 2));
        const float a1 = __expf(m1 - mx1);
        const float a2 = __expf(m2 - mx2);
        m1 = mx1; m2 = mx2;

        float s1 = 0.0f, s2 = 0.0f;
        uint32_t pr1[8], pr2[8];
#pragma unroll
        for (int nf = 0; nf < 8; nf++) {
            const float p0 = __expf(sc[nf][0] - mx1);
            const float p1 = __expf(sc[nf][1] - mx1);
            const float p2 = __expf(sc[nf][2] - mx2);
            const float p3 = __expf(sc[nf][3] - mx2);
            s1 += p0 + p1; s2 += p2 + p3;
            pr1[nf] = pack_h2(p0, p1);
            pr2[nf] = pack_h2(p2, p3);
        }
        lp1 = lp1 * a1 + s1;
        lp2 = lp2 * a2 + s2;
#pragma unroll
        for (int nf = 0; nf < 8; nf++) {
            oacc[nf][0] *= a1; oacc[nf][1] *= a1;
            oacc[nf][2] *= a2; oacc[nf][3] *= a2;
        }

        // ---- PV: P single fp16, V 2-term split
#pragma unroll
        for (int ks = 0; ks < 4; ks++) {
            uint32_t pa[4] = {pr1[2 * ks], pr2[2 * ks],
                              pr1[2 * ks + 1], pr2[2 * ks + 1]};
#pragma unroll
            for (int p = 0; p < 4; p++) {
                const uint32_t off =
                    (uint32_t)(ks * 16 + lrow) * ROWB + (p * 16 + lcol) * 2;
                uint32_t rh[4], rl[4];
                ldsm_x4_t(rh, base + VHI + off);
                ldsm_x4_t(rl, base + VLO + off);
                uint32_t b0h[2] = {rh[0], rh[1]}, b1h[2] = {rh[2], rh[3]};
                uint32_t b0l[2] = {rl[0], rl[1]}, b1l[2] = {rl[2], rl[3]};
                mma_f16(oacc[2 * p], pa, b0h);
                mma_f16(oacc[2 * p], pa, b0l);
                mma_f16(oacc[2 * p + 1], pa, b1h);
                mma_f16(oacc[2 * p + 1], pa, b1l);
            }
        }
        __syncthreads();
    }

    lp1 += __shfl_xor_sync(0xffffffffu, lp1, 1);
    lp1 += __shfl_xor_sync(0xffffffffu, lp1, 2);
    lp2 += __shfl_xor_sync(0xffffffffu, lp2, 1);
    lp2 += __shfl_xor_sync(0xffffffffu, lp2, 2);
    const float i1 = 1.0f / lp1, i2 = 1.0f / lp2;

    const size_t row1 = qrow0 + wid * 16 + (lane >> 2);
    const size_t row2 = row1 + 8;
#pragma unroll
    for (int nf = 0; nf < 8; nf++) {
        const int col = h * HDIM + nf * 8 + (lane & 3) * 2;
        uint32_t hp, lp;
        split_pack(oacc[nf][0] * i1, oacc[nf][1] * i1, hp, lp);
        *(uint32_t*)(Ohi + row1 * HID_DIM + col) = hp;
        *(uint32_t*)(Olo + row1 * HID_DIM + col) = lp;
        split_pack(oacc[nf][2] * i2, oacc[nf][3] * i2, hp, lp);
        *(uint32_t*)(Ohi + row2 * HID_DIM + col) = hp;
        *(uint32_t*)(Olo + row2 * HID_DIM + col) = lp;
    }
}

static const int GEMM128_SMEM = 2 * (2 * 128 + 2 * 128) * 144;  // 147456
static const int GEMM64_SMEM  = 2 * (2 * 64 + 2 * 64) * 144;    // 73728
static const int ATTN_SMEM    = 256 * 144 + 2 * 192 * 144;      // 92160

// ---------------------------------------------------------------------------
// Launch
// ---------------------------------------------------------------------------
extern "C" void kernel_launch(void* const* d_in, const int* in_sizes, int n_in,
                              void* d_out, int out_size)
{
    const float* query = (const float*)d_in[0];
    const float* key   = (const float*)d_in[1];
    const float* value = (const float*)d_in[2];
    const float* Wq    = (const float*)d_in[3];
    const float* bq    = (const float*)d_in[4];
    const float* Wk    = (const float*)d_in[5];
    const float* bk    = (const float*)d_in[6];
    const float* Wv    = (const float*)d_in[7];
    const float* bv    = (const float*)d_in[8];
    const float* Wo    = (const float*)d_in[9];
    const float* bo    = (const float*)d_in[10];
    float* out = (float*)d_out;

    void *qh, *ql, *kh, *kl, *vh, *vl;
    void *wqh, *wql, *wkh, *wkl, *wvh, *wvl, *woh, *wol;
    void *qph, *qpl, *kph, *kpl, *vph, *vpl, *oh, *ol;
    cudaGetSymbolAddress(&qh, g_qhi); cudaGetSymbolAddress(&ql, g_qlo);
    cudaGetSymbolAddress(&kh, g_khi); cudaGetSymbolAddress(&kl, g_klo);
    cudaGetSymbolAddress(&vh, g_vhi); cudaGetSymbolAddress(&vl, g_vlo);
    cudaGetSymbolAddress(&wqh, g_WqThi); cudaGetSymbolAddress(&wql, g_WqTlo);
    cudaGetSymbolAddress(&wkh, g_WkThi); cudaGetSymbolAddress(&wkl, g_WkTlo);
    cudaGetSymbolAddress(&wvh, g_WvThi); cudaGetSymbolAddress(&wvl, g_WvTlo);
    cudaGetSymbolAddress(&woh, g_WoThi); cudaGetSymbolAddress(&wol, g_WoTlo);
    cudaGetSymbolAddress(&qph, g_qPhi); cudaGetSymbolAddress(&qpl, g_qPlo);
    cudaGetSymbolAddress(&kph, g_kPhi); cudaGetSymbolAddress(&kpl, g_kPlo);
    cudaGetSymbolAddress(&vph, g_vPhi); cudaGetSymbolAddress(&vpl, g_vPlo);
    cudaGetSymbolAddress(&oh, g_ohi);   cudaGetSymbolAddress(&ol, g_olo);

    cudaFuncSetAttribute((const void*)gemm_mma<128, 128, 0>,
                         cudaFuncAttributeMaxDynamicSharedMemorySize, GEMM128_SMEM);
    cudaFuncSetAttribute((const void*)gemm_mma<128, 128, 1>,
                         cudaFuncAttributeMaxDynamicSharedMemorySize, GEMM128_SMEM);
    cudaFuncSetAttribute((const void*)gemm_mma<64, 64, 1>,
                         cudaFuncAttributeMaxDynamicSharedMemorySize, GEMM64_SMEM);
    cudaFuncSetAttribute((const void*)mqa_attn_mma,
                         cudaFuncAttributeMaxDynamicSharedMemorySize, ATTN_SMEM);

    // --- prep ---
    {
        dim3 blk(32, 8);
        transpose_split_w<<<dim3(HID_DIM / 32, KDIM / 32), blk>>>(
            Wq, (bf16*)wqh, (bf16*)wql, KDIM, HID_DIM);
        transpose_split_w<<<dim3(HDIM / 32, KDIM / 32), blk>>>(
            Wk, (bf16*)wkh, (bf16*)wkl, KDIM, HDIM);
        transpose_split_w<<<dim3(HDIM / 32, KDIM / 32), blk>>>(
            Wv, (bf16*)wvh, (bf16*)wvl, KDIM, HDIM);
        transpose_split_w<<<dim3(IN_DIM / 32, KDIM / 32), blk>>>(
            Wo, (bf16*)woh, (bf16*)wol, KDIM, IN_DIM);
        const int n2 = MROWS * KDIM / 2;
        const int g = (n2 + 255) / 256;
        split_rows<<<g, 256>>>((const float2*)query, (__nv_bfloat162*)qh,
                               (__nv_bfloat162*)ql, n2);
        split_rows<<<g, 256>>>((const float2*)key, (__nv_bfloat162*)kh,
                               (__nv_bfloat162*)kl, n2);
        split_rows<<<g, 256>>>((const float2*)value, (__nv_bfloat162*)vh,
                               (__nv_bfloat162*)vl, n2);
    }
    // --- projections (fp16 split epilogues; Q pre-scaled by 1/32) ---
    gemm_mma<128, 128, 1><<<dim3(HID_DIM / 128, MROWS / 128), 256, GEMM128_SMEM>>>(
        (const bf16*)qh, (const bf16*)ql, (const bf16*)wqh, (const bf16*)wql,
        bq, nullptr, (__half*)qph, (__half*)qpl, 1.0f / 32.0f, HID_DIM);
    gemm_mma<64, 64, 1><<<dim3(1, MROWS / 64), 256, GEMM64_SMEM>>>(
        (const bf16*)kh, (const bf16*)kl, (const bf16*)wkh, (const bf16*)wkl,
        bk, nullptr, (__half*)kph, (__half*)kpl, 1.0f, HDIM);
    gemm_mma<64, 64, 1><<<dim3(1, MROWS / 64), 256, GEMM64_SMEM>>>(
        (const bf16*)vh, (const bf16*)vl, (const bf16*)wvh, (const bf16*)wvl,
        bv, nullptr, (__half*)vph, (__half*)vpl, 1.0f, HDIM);

    // --- tensor-core attention (fp16 reduced-term) ---
    {
        dim3 grid(SEQ / 128, NHEAD, BATCH);
        mqa_attn_mma<<<grid, 256, ATTN_SMEM>>>(
            (const __half*)qph, (const __half*)qpl,
            (const __half*)kph,
            (const __half*)vph, (const __half*)vpl,
            (bf16*)oh, (bf16*)ol);
    }

    // --- O-projection -> d_out (fp32 + bias) ---
    gemm_mma<128, 128, 0><<<dim3(IN_DIM / 128, MROWS / 128), 256, GEMM128_SMEM>>>(
        (const bf16*)oh, (const bf16*)ol, (const bf16*)woh, (const bf16*)wol,
        bo, out, nullptr, nullptr, 1.0f, IN_DIM);
}

// round 9
// speedup vs baseline: 4.0354x; 1.1164x over previous
#include <cuda_runtime.h>
#include <cuda_bf16.h>
#include <cuda_fp16.h>
#include <cstdint>

typedef __nv_bfloat16 bf16;

#define BATCH 2
#define SEQ 2048
#define IN_DIM 1024
#define HID_DIM 1024
#define NHEAD 16
#define HDIM 64
#define KDIM 1024
#define MROWS 4096

// ---------------------------------------------------------------------------
// Scratch (__device__ globals; allocation-free rule)
// ---------------------------------------------------------------------------
__device__ bf16 g_qhi[MROWS * KDIM], g_qlo[MROWS * KDIM];
__device__ bf16 g_khi[MROWS * KDIM], g_klo[MROWS * KDIM];
__device__ bf16 g_vhi[MROWS * KDIM], g_vlo[MROWS * KDIM];
__device__ bf16 g_WqThi[HID_DIM * KDIM], g_WqTlo[HID_DIM * KDIM];
__device__ bf16 g_WkThi[HDIM * KDIM],   g_WkTlo[HDIM * KDIM];
__device__ bf16 g_WvThi[HDIM * KDIM],   g_WvTlo[HDIM * KDIM];
__device__ bf16 g_WoThi[IN_DIM * KDIM], g_WoTlo[IN_DIM * KDIM];
// projected fp16 operands for attention: Q (scaled 1/32) split; K,V hi only
__device__ __half g_qPhi[MROWS * HID_DIM], g_qPlo[MROWS * HID_DIM];
__device__ __half g_kPhi[MROWS * HDIM];
__device__ __half g_vPhi[MROWS * HDIM];
// attention output, bf16 split (A operand of O-projection)
__device__ bf16 g_ohi[MROWS * HID_DIM], g_olo[MROWS * HID_DIM];

// ---------------------------------------------------------------------------
// PTX helpers (all sm_80-era; legal in family-generic PTX)
// ---------------------------------------------------------------------------
__device__ __forceinline__ uint32_t smem_u32(const void* p) {
    uint32_t a;
    asm("{ .reg .u64 t; cvta.to.shared.u64 t, %1; cvt.u32.u64 %0, t; }"
        : "=r"(a) : "l"(p));
    return a;
}
__device__ __forceinline__ void ldsm_x4(uint32_t* r, uint32_t addr) {
    asm volatile("ldmatrix.sync.aligned.m8n8.x4.shared.b16 {%0,%1,%2,%3}, [%4];"
                 : "=r"(r[0]), "=r"(r[1]), "=r"(r[2]), "=r"(r[3]) : "r"(addr));
}
__device__ __forceinline__ void ldsm_x4_t(uint32_t* r, uint32_t addr) {
    asm volatile("ldmatrix.sync.aligned.m8n8.x4.trans.shared.b16 {%0,%1,%2,%3}, [%4];"
                 : "=r"(r[0]), "=r"(r[1]), "=r"(r[2]), "=r"(r[3]) : "r"(addr));
}
__device__ __forceinline__ void mma_bf16(float* d, const uint32_t* a,
                                         const uint32_t* b) {
    asm volatile(
        "mma.sync.aligned.m16n8k16.row.col.f32.bf16.bf16.f32 "
        "{%0,%1,%2,%3}, {%4,%5,%6,%7}, {%8,%9}, {%0,%1,%2,%3};"
        : "+f"(d[0]), "+f"(d[1]), "+f"(d[2]), "+f"(d[3])
        : "r"(a[0]), "r"(a[1]), "r"(a[2]), "r"(a[3]), "r"(b[0]), "r"(b[1]));
}
__device__ __forceinline__ void mma_f16(float* d, const uint32_t* a,
                                        const uint32_t* b) {
    asm volatile(
        "mma.sync.aligned.m16n8k16.row.col.f32.f16.f16.f32 "
        "{%0,%1,%2,%3}, {%4,%5,%6,%7}, {%8,%9}, {%0,%1,%2,%3};"
        : "+f"(d[0]), "+f"(d[1]), "+f"(d[2]), "+f"(d[3])
        : "r"(a[0]), "r"(a[1]), "r"(a[2]), "r"(a[3]), "r"(b[0]), "r"(b[1]));
}
__device__ __forceinline__ void cp16(uint32_t smem, const void* g) {
    asm volatile("cp.async.cg.shared.global [%0], [%1], 16;"
                 :: "r"(smem), "l"(g));
}
__device__ __forceinline__ void cp_commit() {
    asm volatile("cp.async.commit_group;" ::: "memory");
}
__device__ __forceinline__ void cp_wait1() {
    asm volatile("cp.async.wait_group 1;" ::: "memory");
}
__device__ __forceinline__ void cp_wait0() {
    asm volatile("cp.async.wait_group 0;" ::: "memory");
}
__device__ __forceinline__ void split_pack(float e, float o,
                                           uint32_t& hp, uint32_t& lp) {
    const bf16 he = __float2bfloat16(e), ho = __float2bfloat16(o);
    const bf16 le = __float2bfloat16(e - __bfloat162float(he));
    const bf16 lo2 = __float2bfloat16(o - __bfloat162float(ho));
    __nv_bfloat162 H(he, ho), L(le, lo2);
    hp = *reinterpret_cast<uint32_t*>(&H);
    lp = *reinterpret_cast<uint32_t*>(&L);
}
__device__ __forceinline__ void split_pack_h(float e, float o,
                                             uint32_t& hp, uint32_t& lp) {
    const __half he = __float2half_rn(e), ho = __float2half_rn(o);
    const __half le = __float2half_rn(e - __half2float(he));
    const __half lo2 = __float2half_rn(o - __half2float(ho));
    __half2 H(he, ho), L(le, lo2);
    hp = *reinterpret_cast<uint32_t*>(&H);
    lp = *reinterpret_cast<uint32_t*>(&L);
}
__device__ __forceinline__ uint32_t pack_h2(float e, float o) {
    __half2 P(__float2half_rn(e), __float2half_rn(o));
    return *reinterpret_cast<uint32_t*>(&P);
}

// ---------------------------------------------------------------------------
// Prep kernels
// ---------------------------------------------------------------------------
__device__ __forceinline__ void tsw_body(const float* W, bf16* Thi, bf16* Tlo,
                                         int K, int N)
{
    __shared__ float t[32][33];
    const int n0 = blockIdx.x * 32, k0 = blockIdx.y * 32;
    const int tx = threadIdx.x, ty = threadIdx.y;
#pragma unroll
    for (int i = 0; i < 32; i += 8)
        t[ty + i][tx] = W[(size_t)(k0 + ty + i) * N + n0 + tx];
    __syncthreads();
#pragma unroll
    for (int i = 0; i < 32; i += 8) {
        const float v = t[tx][ty + i];
        const bf16 h = __float2bfloat16(v);
        const bf16 l = __float2bfloat16(v - __bfloat162float(h));
        const size_t idx = (size_t)(n0 + ty + i) * K + k0 + tx;
        Thi[idx] = h;
        Tlo[idx] = l;
    }
}
__global__ void transpose_split_w(const float* __restrict__ W,
                                  bf16* __restrict__ Thi, bf16* __restrict__ Tlo,
                                  int K, int N)
{
    tsw_body(W, Thi, Tlo, K, N);
}
struct TW2 { const float* W[2]; bf16* Thi[2]; bf16* Tlo[2]; };
__global__ void transpose_split_w2(TW2 a, int K, int N)
{
    const int z = blockIdx.z;
    tsw_body(a.W[z], a.Thi[z], a.Tlo[z], K, N);
}

struct SR3 { const float2* X[3]; __nv_bfloat162* hi[3]; __nv_bfloat162* lo[3]; };
__global__ void split_rows3(SR3 a, int n2)
{
    const int z = blockIdx.y;
    const int i = blockIdx.x * blockDim.x + threadIdx.x;
    if (i < n2) {
        const float2 v = a.X[z][i];
        const bf16 hx = __float2bfloat16(v.x);
        const bf16 hy = __float2bfloat16(v.y);
        const bf16 lx = __float2bfloat16(v.x - __bfloat162float(hx));
        const bf16 ly = __float2bfloat16(v.y - __bfloat162float(hy));
        a.hi[z][i] = __nv_bfloat162(hx, hy);
        a.lo[z][i] = __nv_bfloat162(lx, ly);
    }
}

// ---------------------------------------------------------------------------
// cp.async double-buffered mma.sync bf16 3-term split GEMM core.
// EPI=0: fp32 C=acc+bias.  EPI=1: fp16 split (Chi,Clo).  EPI=2: fp16 hi only.
// ---------------------------------------------------------------------------
template <int BM, int BN, int EPI>
__device__ __forceinline__ void gemm_core(
    const bf16* Ahi, const bf16* Alo, const bf16* Bhi, const bf16* Blo,
    const float* bias, float* C, __half* Chi, __half* Clo,
    float scale, int Ntot, int m0, int n0, char* smem)
{
    constexpr int MF = BM / 64;
    constexpr int WN = BN / 2;
    constexpr int NF = WN / 8;
    constexpr uint32_t ROWB = 144;
    constexpr uint32_t OAL = BM * ROWB;
    constexpr uint32_t OBH = 2 * BM * ROWB;
    constexpr uint32_t OBL = OBH + BN * ROWB;
    constexpr uint32_t STAGE = (2 * BM + 2 * BN) * ROWB;
    constexpr int NCH = KDIM / 64;

    const uint32_t uS = smem_u32(smem);
    const int tid = threadIdx.x;
    const int wid = tid >> 5, lane = tid & 31;
    const int warp_m = wid & 3, warp_n = wid >> 2;
    const int lrow = lane & 15;
    const int lcol = (lane >> 4) * 8;

    const bf16* a_hi = Ahi + (size_t)m0 * KDIM;
    const bf16* a_lo = Alo + (size_t)m0 * KDIM;
    const bf16* b_hi = Bhi + (size_t)n0 * KDIM;
    const bf16* b_lo = Blo + (size_t)n0 * KDIM;

    auto issue = [&](int ch, int buf) {
        const int k0 = ch * 64;
        const uint32_t base = uS + (uint32_t)buf * STAGE;
#pragma unroll
        for (int i = tid; i < BM * 8; i += 256) {
            const int r = i >> 3, c8 = (i & 7) * 8;
            const uint32_t so = (uint32_t)r * ROWB + c8 * 2;
            const size_t g = (size_t)r * KDIM + k0 + c8;
            cp16(base + so, a_hi + g);
            cp16(base + OAL + so, a_lo + g);
        }
#pragma unroll
        for (int i = tid; i < BN * 8; i += 256) {
            const int r = i >> 3, c8 = (i & 7) * 8;
            const uint32_t so = (uint32_t)r * ROWB + c8 * 2;
            const size_t g = (size_t)r * KDIM + k0 + c8;
            cp16(base + OBH + so, b_hi + g);
            cp16(base + OBL + so, b_lo + g);
        }
    };

    float acc[MF][NF][4] = {};

    issue(0, 0);
    cp_commit();

    for (int ch = 0; ch < NCH; ch++) {
        if (ch + 1 < NCH) {
            issue(ch + 1, (ch + 1) & 1);
            cp_commit();
            cp_wait1();
        } else {
            cp_wait0();
        }
        __syncthreads();

        const uint32_t base = uS + (uint32_t)(ch & 1) * STAGE;
#pragma unroll
        for (int ks = 0; ks < 4; ks++) {
            const int kk = ks * 16 + lcol;
            uint32_t ah[MF][4], al[MF][4];
#pragma unroll
            for (int mf = 0; mf < MF; mf++) {
                const int row = warp_m * (BM / 4) + mf * 16 + lrow;
                const uint32_t off = (uint32_t)row * ROWB + kk * 2;
                ldsm_x4(ah[mf], base + off);
                ldsm_x4(al[mf], base + OAL + off);
            }
            uint32_t bh[NF][2], bl[NF][2];
#pragma unroll
            for (int p = 0; p < NF / 2; p++) {
                const int row = warp_n * WN + p * 16 + lrow;
                const uint32_t off = (uint32_t)row * ROWB + kk * 2;
                uint32_t r4[4];
                ldsm_x4(r4, base + OBH + off);
                bh[2 * p][0] = r4[0]; bh[2 * p][1] = r4[2];
                bh[2 * p + 1][0] = r4[1]; bh[2 * p + 1][1] = r4[3];
                ldsm_x4(r4, base + OBL + off);
                bl[2 * p][0] = r4[0]; bl[2 * p][1] = r4[2];
                bl[2 * p + 1][0] = r4[1]; bl[2 * p + 1][1] = r4[3];
            }
#pragma unroll
            for (int mf = 0; mf < MF; mf++)
#pragma unroll
                for (int nf = 0; nf < NF; nf++) {
                    mma_bf16(acc[mf][nf], ah[mf], bh[nf]);
                    mma_bf16(acc[mf][nf], ah[mf], bl[nf]);
                    mma_bf16(acc[mf][nf], al[mf], bh[nf]);
                }
        }
        __syncthreads();
    }

    const int gid = lane >> 2, t4 = lane & 3;
#pragma unroll
    for (int mf = 0; mf < MF; mf++) {
        const int row = m0 + warp_m * (BM / 4) + mf * 16 + gid;
#pragma unroll
        for (int nf = 0; nf < NF; nf++) {
            const int col = n0 + warp_n * WN + nf * 8 + t4 * 2;
            const float b0 = bias[col], b1 = bias[col + 1];
            if (EPI == 0) {
                float2 o0 = make_float2(acc[mf][nf][0] + b0, acc[mf][nf][1] + b1);
                float2 o1 = make_float2(acc[mf][nf][2] + b0, acc[mf][nf][3] + b1);
                *(float2*)(C + (size_t)row * Ntot + col) = o0;
                *(float2*)(C + (size_t)(row + 8) * Ntot + col) = o1;
            } else if (EPI == 1) {
                uint32_t hp, lp;
                split_pack_h((acc[mf][nf][0] + b0) * scale,
                             (acc[mf][nf][1] + b1) * scale, hp, lp);
                *(uint32_t*)(Chi + (size_t)row * Ntot + col) = hp;
                *(uint32_t*)(Clo + (size_t)row * Ntot + col) = lp;
                split_pack_h((acc[mf][nf][2] + b0) * scale,
                             (acc[mf][nf][3] + b1) * scale, hp, lp);
                *(uint32_t*)(Chi + (size_t)(row + 8) * Ntot + col) = hp;
                *(uint32_t*)(Clo + (size_t)(row + 8) * Ntot + col) = lp;
            } else {
                *(uint32_t*)(Chi + (size_t)row * Ntot + col) =
                    pack_h2(acc[mf][nf][0] + b0, acc[mf][nf][1] + b1);
                *(uint32_t*)(Chi + (size_t)(row + 8) * Ntot + col) =
                    pack_h2(acc[mf][nf][2] + b0, acc[mf][nf][3] + b1);
            }
        }
    }
}

template <int BM, int BN, int EPI>
__global__ __launch_bounds__(256) void gemm_mma(
    const bf16* __restrict__ Ahi, const bf16* __restrict__ Alo,
    const bf16* __restrict__ Bhi, const bf16* __restrict__ Blo,
    const float* __restrict__ bias, float* __restrict__ C,
    __half* __restrict__ Chi, __half* __restrict__ Clo,
    float scale, int Ntot)
{
    extern __shared__ char smem[];
    gemm_core<BM, BN, EPI>(Ahi, Alo, Bhi, Blo, bias, C, Chi, Clo, scale, Ntot,
                           blockIdx.y * BM, blockIdx.x * BN, smem);
}

// fused K+V projection (identical shapes): grid.z selects operand set
struct KVArgs {
    const bf16* Ahi[2]; const bf16* Alo[2];
    const bf16* Bhi[2]; const bf16* Blo[2];
    const float* bias[2]; __half* Chi[2];
};
__global__ __launch_bounds__(256) void gemm_mma_kv(KVArgs a)
{
    extern __shared__ char smem[];
    const int z = blockIdx.z;
    gemm_core<64, 64, 2>(a.Ahi[z], a.Alo[z], a.Bhi[z], a.Blo[z], a.bias[z],
                         nullptr, a.Chi[z], nullptr, 1.0f, HDIM,
                         blockIdx.y * 64, blockIdx.x * 64, smem);
}

// ---------------------------------------------------------------------------
// Tensor-core MQA attention, fp16 3-term:
//   scores = (Qh + Ql)·K (2 terms);  PV = P·V (1 term; P,V single fp16)
// Block = 128 queries x (head, batch); 8 warps x 16-row strips; KBLK=64.
// cp.async double-buffered stages of {K, V}.
// ---------------------------------------------------------------------------
__global__ __launch_bounds__(256) void mqa_attn_mma(
    const __half* __restrict__ Qhi, const __half* __restrict__ Qlo,
    const __half* __restrict__ Khi, const __half* __restrict__ Vhi,
    bf16* __restrict__ Ohi, bf16* __restrict__ Olo)
{
    constexpr uint32_t ROWB = 144;
    constexpr uint32_t QLO = 128 * ROWB;
    constexpr uint32_t ST0 = 256 * ROWB;          // 36864: end of Q region
    constexpr uint32_t STG = 128 * ROWB;          // 18432: stage {K, V}
    constexpr uint32_t VHI = 64 * ROWB;
    constexpr int NCH = SEQ / 64;                 // 32

    extern __shared__ char smc[];
    const uint32_t uS = smem_u32(smc);

    const int tid = threadIdx.x, wid = tid >> 5, lane = tid & 31;
    const int h = blockIdx.y, b = blockIdx.z;
    const int q0 = blockIdx.x * 128;
    const size_t qrow0 = (size_t)b * SEQ + q0;
    const int lrow = lane & 15;
    const int lcol = (lane >> 4) * 8;

    const __half* kh_g = Khi + (size_t)b * SEQ * HDIM;
    const __half* vh_g = Vhi + (size_t)b * SEQ * HDIM;

    auto issue = [&](int ch, int buf) {
        const int k0 = ch * 64;
        const uint32_t base = uS + ST0 + (uint32_t)buf * STG;
#pragma unroll
        for (int i = tid; i < 64 * 8; i += 256) {
            const int r = i >> 3, c8 = (i & 7) * 8;
            const uint32_t so = (uint32_t)r * ROWB + c8 * 2;
            const size_t g = (size_t)(k0 + r) * HDIM + c8;
            cp16(base + so, kh_g + g);
            cp16(base + VHI + so, vh_g + g);
        }
    };

    issue(0, 0);
    cp_commit();
    {
        const __half* qh_g = Qhi + qrow0 * HID_DIM + h * HDIM;
        const __half* ql_g = Qlo + qrow0 * HID_DIM + h * HDIM;
#pragma unroll
        for (int i = tid; i < 128 * 8; i += 256) {
            const int r = i >> 3, c8 = (i & 7) * 8;
            const uint32_t so = (uint32_t)r * ROWB + c8 * 2;
            const size_t g = (size_t)r * HID_DIM + c8;
            *(uint4*)(smc + so) = *(const uint4*)(qh_g + g);
            *(uint4*)(smc + QLO + so) = *(const uint4*)(ql_g + g);
        }
    }
    __syncthreads();
    uint32_t qh[4][4], ql[4][4];
#pragma unroll
    for (int ks = 0; ks < 4; ks++) {
        const uint32_t off = (uint32_t)(wid * 16 + lrow) * ROWB + (ks * 16 + lcol) * 2;
        ldsm_x4(qh[ks], uS + off);
        ldsm_x4(ql[ks], uS + QLO + off);
    }

    float m1 = -1e30f, m2 = -1e30f, lp1 = 0.0f, lp2 = 0.0f;
    float oacc[8][4] = {};

    for (int ch = 0; ch < NCH; ch++) {
        if (ch + 1 < NCH) {
            issue(ch + 1, (ch + 1) & 1);
            cp_commit();
            cp_wait1();
        } else {
            cp_wait0();
        }
        __syncthreads();

        const uint32_t base = uS + ST0 + (uint32_t)(ch & 1) * STG;

        // ---- scores: 16 rows x 64 keys; 2 terms (Qh + Ql) x K
        float sc[8][4] = {};
#pragma unroll
        for (int ks = 0; ks < 4; ks++) {
#pragma unroll
            for (int p = 0; p < 4; p++) {
                const uint32_t off =
                    (uint32_t)(p * 16 + lrow) * ROWB + (ks * 16 + lcol) * 2;
                uint32_t rh[4];
                ldsm_x4(rh, base + off);
                uint32_t b0[2] = {rh[0], rh[2]}, b1[2] = {rh[1], rh[3]};
                mma_f16(sc[2 * p], qh[ks], b0);
                mma_f16(sc[2 * p], ql[ks], b0);
                mma_f16(sc[2 * p + 1], qh[ks], b1);
                mma_f16(sc[2 * p + 1], ql[ks], b1);
            }
        }

        // ---- online softmax in registers
        float mx1 = m1, mx2 = m2;
#pragma unroll
        for (int nf = 0; nf < 8; nf++) {
            mx1 = fmaxf(mx1, fmaxf(sc[nf][0], sc[nf][1]));
            mx2 = fmaxf(mx2, fmaxf(sc[nf][2], sc[nf][3]));
        }
        mx1 = fmaxf(mx1, __shfl_xor_sync(0xffffffffu, mx1, 1));
        mx1 = fmaxf(mx1, __shfl_xor_sync(0xffffffffu, mx1, 2));
        mx2 = fmaxf(mx2, __shfl_xor_sync(0xffffffffu, mx2, 1));
        mx2 = fmaxf(mx2, __shfl_xor_sync(0xffffffffu, mx2, 2));
        const float a1 = __expf(m1 - mx1);
        const float a2 = __expf(m2 - mx2);
        m1 = mx1; m2 = mx2;

        float s1 = 0.0f, s2 = 0.0f;
        uint32_t pr1[8], pr2[8];
#pragma unroll
        for (int nf = 0; nf < 8; nf++) {
            const float p0 = __expf(sc[nf][0] - mx1);
            const float p1 = __expf(sc[nf][1] - mx1);
            const float p2 = __expf(sc[nf][2] - mx2);
            const float p3 = __expf(sc[nf][3] - mx2);
            s1 += p0 + p1; s2 += p2 + p3;
            pr1[nf] = pack_h2(p0, p1);
            pr2[nf] = pack_h2(p2, p3);
        }
        lp1 = lp1 * a1 + s1;
        lp2 = lp2 * a2 + s2;
#pragma unroll
        for (int nf = 0; nf < 8; nf++) {
            oacc[nf][0] *= a1; oacc[nf][1] *= a1;
            oacc[nf][2] *= a2; oacc[nf][3] *= a2;
        }

        // ---- PV: single term (P fp16 x V fp16)
#pragma unroll
        for (int ks = 0; ks < 4; ks++) {
            uint32_t pa[4] = {pr1[2 * ks], pr2[2 * ks],
                              pr1[2 * ks + 1], pr2[2 * ks + 1]};
#pragma unroll
            for (int p = 0; p < 4; p++) {
                const uint32_t off =
                    (uint32_t)(ks * 16 + lrow) * ROWB + (p * 16 + lcol) * 2;
                uint32_t rh[4];
                ldsm_x4_t(rh, base + VHI + off);
                uint32_t b0[2] = {rh[0], rh[1]}, b1[2] = {rh[2], rh[3]};
                mma_f16(oacc[2 * p], pa, b0);
                mma_f16(oacc[2 * p + 1], pa, b1);
            }
        }
        __syncthreads();
    }

    lp1 += __shfl_xor_sync(0xffffffffu, lp1, 1);
    lp1 += __shfl_xor_sync(0xffffffffu, lp1, 2);
    lp2 += __shfl_xor_sync(0xffffffffu, lp2, 1);
    lp2 += __shfl_xor_sync(0xffffffffu, lp2, 2);
    const float i1 = 1.0f / lp1, i2 = 1.0f / lp2;

    const size_t row1 = qrow0 + wid * 16 + (lane >> 2);
    const size_t row2 = row1 + 8;
#pragma unroll
    for (int nf = 0; nf < 8; nf++) {
        const int col = h * HDIM + nf * 8 + (lane & 3) * 2;
        uint32_t hp, lp;
        split_pack(oacc[nf][0] * i1, oacc[nf][1] * i1, hp, lp);
        *(uint32_t*)(Ohi + row1 * HID_DIM + col) = hp;
        *(uint32_t*)(Olo + row1 * HID_DIM + col) = lp;
        split_pack(oacc[nf][2] * i2, oacc[nf][3] * i2, hp, lp);
        *(uint32_t*)(Ohi + row2 * HID_DIM + col) = hp;
        *(uint32_t*)(Olo + row2 * HID_DIM + col) = lp;
    }
}

static const int GEMM128_SMEM = 2 * (2 * 128 + 2 * 128) * 144;  // 147456
static const int GEMM64_SMEM  = 2 * (2 * 64 + 2 * 64) * 144;    // 73728
static const int ATTN_SMEM    = 256 * 144 + 2 * 128 * 144;      // 73728

// ---------------------------------------------------------------------------
// Launch
// ---------------------------------------------------------------------------
extern "C" void kernel_launch(void* const* d_in, const int* in_sizes, int n_in,
                              void* d_out, int out_size)
{
    const float* query = (const float*)d_in[0];
    const float* key   = (const float*)d_in[1];
    const float* value = (const float*)d_in[2];
    const float* Wq    = (const float*)d_in[3];
    const float* bq    = (const float*)d_in[4];
    const float* Wk    = (const float*)d_in[5];
    const float* bk    = (const float*)d_in[6];
    const float* Wv    = (const float*)d_in[7];
    const float* bv    = (const float*)d_in[8];
    const float* Wo    = (const float*)d_in[9];
    const float* bo    = (const float*)d_in[10];
    float* out = (float*)d_out;

    void *qh, *ql, *kh, *kl, *vh, *vl;
    void *wqh, *wql, *wkh, *wkl, *wvh, *wvl, *woh, *wol;
    void *qph, *qpl, *kph, *vph, *oh, *ol;
    cudaGetSymbolAddress(&qh, g_qhi); cudaGetSymbolAddress(&ql, g_qlo);
    cudaGetSymbolAddress(&kh, g_khi); cudaGetSymbolAddress(&kl, g_klo);
    cudaGetSymbolAddress(&vh, g_vhi); cudaGetSymbolAddress(&vl, g_vlo);
    cudaGetSymbolAddress(&wqh, g_WqThi); cudaGetSymbolAddress(&wql, g_WqTlo);
    cudaGetSymbolAddress(&wkh, g_WkThi); cudaGetSymbolAddress(&wkl, g_WkTlo);
    cudaGetSymbolAddress(&wvh, g_WvThi); cudaGetSymbolAddress(&wvl, g_WvTlo);
    cudaGetSymbolAddress(&woh, g_WoThi); cudaGetSymbolAddress(&wol, g_WoTlo);
    cudaGetSymbolAddress(&qph, g_qPhi); cudaGetSymbolAddress(&qpl, g_qPlo);
    cudaGetSymbolAddress(&kph, g_kPhi);
    cudaGetSymbolAddress(&vph, g_vPhi);
    cudaGetSymbolAddress(&oh, g_ohi);   cudaGetSymbolAddress(&ol, g_olo);

    cudaFuncSetAttribute((const void*)gemm_mma<128, 128, 0>,
                         cudaFuncAttributeMaxDynamicSharedMemorySize, GEMM128_SMEM);
    cudaFuncSetAttribute((const void*)gemm_mma<128, 128, 1>,
                         cudaFuncAttributeMaxDynamicSharedMemorySize, GEMM128_SMEM);
    cudaFuncSetAttribute((const void*)gemm_mma_kv,
                         cudaFuncAttributeMaxDynamicSharedMemorySize, GEMM64_SMEM);
    cudaFuncSetAttribute((const void*)mqa_attn_mma,
                         cudaFuncAttributeMaxDynamicSharedMemorySize, ATTN_SMEM);

    // --- prep ---
    {
        dim3 blk(32, 8);
        transpose_split_w<<<dim3(HID_DIM / 32, KDIM / 32), blk>>>(
            Wq, (bf16*)wqh, (bf16*)wql, KDIM, HID_DIM);
        TW2 tw;
        tw.W[0] = Wk; tw.Thi[0] = (bf16*)wkh; tw.Tlo[0] = (bf16*)wkl;
        tw.W[1] = Wv; tw.Thi[1] = (bf16*)wvh; tw.Tlo[1] = (bf16*)wvl;
        transpose_split_w2<<<dim3(HDIM / 32, KDIM / 32, 2), blk>>>(tw, KDIM, HDIM);
        transpose_split_w<<<dim3(IN_DIM / 32, KDIM / 32), blk>>>(
            Wo, (bf16*)woh, (bf16*)wol, KDIM, IN_DIM);

        const int n2 = MROWS * KDIM / 2;
        SR3 sr;
        sr.X[0] = (const float2*)query; sr.hi[0] = (__nv_bfloat162*)qh; sr.lo[0] = (__nv_bfloat162*)ql;
        sr.X[1] = (const float2*)key;   sr.hi[1] = (__nv_bfloat162*)kh; sr.lo[1] = (__nv_bfloat162*)kl;
        sr.X[2] = (const float2*)value; sr.hi[2] = (__nv_bfloat162*)vh; sr.lo[2] = (__nv_bfloat162*)vl;
        split_rows3<<<dim3((n2 + 255) / 256, 3), 256>>>(sr, n2);
    }
    // --- projections ---
    gemm_mma<128, 128, 1><<<dim3(HID_DIM / 128, MROWS / 128), 256, GEMM128_SMEM>>>(
        (const bf16*)qh, (const bf16*)ql, (const bf16*)wqh, (const bf16*)wql,
        bq, nullptr, (__half*)qph, (__half*)qpl, 1.0f / 32.0f, HID_DIM);
    {
        KVArgs a;
        a.Ahi[0] = (const bf16*)kh; a.Alo[0] = (const bf16*)kl;
        a.Bhi[0] = (const bf16*)wkh; a.Blo[0] = (const bf16*)wkl;
        a.bias[0] = bk; a.Chi[0] = (__half*)kph;
        a.Ahi[1] = (const bf16*)vh; a.Alo[1] = (const bf16*)vl;
        a.Bhi[1] = (const bf16*)wvh; a.Blo[1] = (const bf16*)wvl;
        a.bias[1] = bv; a.Chi[1] = (__half*)vph;
        gemm_mma_kv<<<dim3(1, MROWS / 64, 2), 256, GEMM64_SMEM>>>(a);
    }

    // --- tensor-core attention (fp16 3-term) ---
    {
        dim3 grid(SEQ / 128, NHEAD, BATCH);
        mqa_attn_mma<<<grid, 256, ATTN_SMEM>>>(
            (const __half*)qph, (const __half*)qpl,
            (const __half*)kph, (const __half*)vph,
            (bf16*)oh, (bf16*)ol);
    }

    // --- O-projection -> d_out (fp32 + bias) ---
    gemm_mma<128, 128, 0><<<dim3(IN_DIM / 128, MROWS / 128), 256, GEMM128_SMEM>>>(
        (const bf16*)oh, (const bf16*)ol, (const bf16*)woh, (const bf16*)wol,
        bo, out, nullptr, nullptr, 1.0f, IN_DIM);
}

// round 11
// speedup vs baseline: 4.7286x; 1.1718x over previous
#include <cuda_runtime.h>
#include <cuda_bf16.h>
#include <cuda_fp16.h>
#include <cstdint>

typedef __nv_bfloat16 bf16;

#define BATCH 2
#define SEQ 2048
#define IN_DIM 1024
#define HID_DIM 1024
#define NHEAD 16
#define HDIM 64
#define KDIM 1024
#define MROWS 4096

// ---------------------------------------------------------------------------
// Scratch (__device__ globals; allocation-free rule)
// ---------------------------------------------------------------------------
__device__ bf16 g_qhi[MROWS * KDIM], g_qlo[MROWS * KDIM];
__device__ bf16 g_khi[MROWS * KDIM], g_klo[MROWS * KDIM];
__device__ bf16 g_vhi[MROWS * KDIM], g_vlo[MROWS * KDIM];
__device__ bf16 g_WqThi[HID_DIM * KDIM], g_WqTlo[HID_DIM * KDIM];
__device__ bf16 g_WkThi[HDIM * KDIM],   g_WkTlo[HDIM * KDIM];
__device__ bf16 g_WvThi[HDIM * KDIM],   g_WvTlo[HDIM * KDIM];
__device__ bf16 g_WoThi[IN_DIM * KDIM], g_WoTlo[IN_DIM * KDIM];
// projected fp16 operands for attention (all single fp16): Q scaled by 1/32
__device__ __half g_qPhi[MROWS * HID_DIM];
__device__ __half g_kPhi[MROWS * HDIM];
__device__ __half g_vPhi[MROWS * HDIM];
// attention output, bf16 split (A operand of O-projection)
__device__ bf16 g_ohi[MROWS * HID_DIM], g_olo[MROWS * HID_DIM];

// ---------------------------------------------------------------------------
// PTX helpers (all sm_80-era; legal in family-generic PTX)
// ---------------------------------------------------------------------------
__device__ __forceinline__ uint32_t smem_u32(const void* p) {
    uint32_t a;
    asm("{ .reg .u64 t; cvta.to.shared.u64 t, %1; cvt.u32.u64 %0, t; }"
        : "=r"(a) : "l"(p));
    return a;
}
__device__ __forceinline__ void ldsm_x4(uint32_t* r, uint32_t addr) {
    asm volatile("ldmatrix.sync.aligned.m8n8.x4.shared.b16 {%0,%1,%2,%3}, [%4];"
                 : "=r"(r[0]), "=r"(r[1]), "=r"(r[2]), "=r"(r[3]) : "r"(addr));
}
__device__ __forceinline__ void ldsm_x4_t(uint32_t* r, uint32_t addr) {
    asm volatile("ldmatrix.sync.aligned.m8n8.x4.trans.shared.b16 {%0,%1,%2,%3}, [%4];"
                 : "=r"(r[0]), "=r"(r[1]), "=r"(r[2]), "=r"(r[3]) : "r"(addr));
}
__device__ __forceinline__ void mma_bf16(float* d, const uint32_t* a,
                                         const uint32_t* b) {
    asm volatile(
        "mma.sync.aligned.m16n8k16.row.col.f32.bf16.bf16.f32 "
        "{%0,%1,%2,%3}, {%4,%5,%6,%7}, {%8,%9}, {%0,%1,%2,%3};"
        : "+f"(d[0]), "+f"(d[1]), "+f"(d[2]), "+f"(d[3])
        : "r"(a[0]), "r"(a[1]), "r"(a[2]), "r"(a[3]), "r"(b[0]), "r"(b[1]));
}
__device__ __forceinline__ void mma_f16(float* d, const uint32_t* a,
                                        const uint32_t* b) {
    asm volatile(
        "mma.sync.aligned.m16n8k16.row.col.f32.f16.f16.f32 "
        "{%0,%1,%2,%3}, {%4,%5,%6,%7}, {%8,%9}, {%0,%1,%2,%3};"
        : "+f"(d[0]), "+f"(d[1]), "+f"(d[2]), "+f"(d[3])
        : "r"(a[0]), "r"(a[1]), "r"(a[2]), "r"(a[3]), "r"(b[0]), "r"(b[1]));
}
__device__ __forceinline__ void cp16(uint32_t smem, const void* g) {
    asm volatile("cp.async.cg.shared.global [%0], [%1], 16;"
                 :: "r"(smem), "l"(g));
}
__device__ __forceinline__ void cp_commit() {
    asm volatile("cp.async.commit_group;" ::: "memory");
}
__device__ __forceinline__ void cp_wait1() {
    asm volatile("cp.async.wait_group 1;" ::: "memory");
}
__device__ __forceinline__ void cp_wait0() {
    asm volatile("cp.async.wait_group 0;" ::: "memory");
}
__device__ __forceinline__ void split_pack(float e, float o,
                                           uint32_t& hp, uint32_t& lp) {
    const bf16 he = __float2bfloat16(e), ho = __float2bfloat16(o);
    const bf16 le = __float2bfloat16(e - __bfloat162float(he));
    const bf16 lo2 = __float2bfloat16(o - __bfloat162float(ho));
    __nv_bfloat162 H(he, ho), L(le, lo2);
    hp = *reinterpret_cast<uint32_t*>(&H);
    lp = *reinterpret_cast<uint32_t*>(&L);
}
__device__ __forceinline__ uint32_t pack_h2(float e, float o) {
    __half2 P(__float2half_rn(e), __float2half_rn(o));
    return *reinterpret_cast<uint32_t*>(&P);
}
__device__ __forceinline__ uint32_t pack_b2(float e, float o) {
    __nv_bfloat162 P(__float2bfloat16(e), __float2bfloat16(o));
    return *reinterpret_cast<uint32_t*>(&P);
}

// ---------------------------------------------------------------------------
// Prep kernels
// ---------------------------------------------------------------------------
__device__ __forceinline__ void tsw_body(const float* W, bf16* Thi, bf16* Tlo,
                                         int K, int N)
{
    __shared__ float t[32][33];
    const int n0 = blockIdx.x * 32, k0 = blockIdx.y * 32;
    const int tx = threadIdx.x, ty = threadIdx.y;
#pragma unroll
    for (int i = 0; i < 32; i += 8)
        t[ty + i][tx] = W[(size_t)(k0 + ty + i) * N + n0 + tx];
    __syncthreads();
#pragma unroll
    for (int i = 0; i < 32; i += 8) {
        const float v = t[tx][ty + i];
        const bf16 h = __float2bfloat16(v);
        const bf16 l = __float2bfloat16(v - __bfloat162float(h));
        const size_t idx = (size_t)(n0 + ty + i) * K + k0 + tx;
        Thi[idx] = h;
        Tlo[idx] = l;
    }
}
__global__ void transpose_split_w(const float* __restrict__ W,
                                  bf16* __restrict__ Thi, bf16* __restrict__ Tlo,
                                  int K, int N)
{
    tsw_body(W, Thi, Tlo, K, N);
}
struct TW2 { const float* W[2]; bf16* Thi[2]; bf16* Tlo[2]; };
__global__ void transpose_split_w2(TW2 a, int K, int N)
{
    const int z = blockIdx.z;
    tsw_body(a.W[z], a.Thi[z], a.Tlo[z], K, N);
}

// vectorized hi/lo split: float4 in, uint2 (4x bf16) hi + lo out
struct SR3 { const float4* X[3]; uint2* hi[3]; uint2* lo[3]; };
__global__ void split_rows3(SR3 a, int n4)
{
    const int z = blockIdx.y;
    const int i = blockIdx.x * blockDim.x + threadIdx.x;
    if (i < n4) {
        const float4 v = a.X[z][i];
        const bf16 h0 = __float2bfloat16(v.x), h1 = __float2bfloat16(v.y);
        const bf16 h2 = __float2bfloat16(v.z), h3 = __float2bfloat16(v.w);
        uint2 H, L;
        H.x = pack_b2(v.x, v.y);
        H.y = pack_b2(v.z, v.w);
        L.x = pack_b2(v.x - __bfloat162float(h0), v.y - __bfloat162float(h1));
        L.y = pack_b2(v.z - __bfloat162float(h2), v.w - __bfloat162float(h3));
        a.hi[z][i] = H;
        a.lo[z][i] = L;
    }
}

// ---------------------------------------------------------------------------
// cp.async double-buffered mma.sync bf16 3-term split GEMM core.
// EPI=0: fp32 C=acc+bias.  EPI=2: fp16 hi-only Chi=(acc+bias)*scale.
// ---------------------------------------------------------------------------
template <int BM, int BN, int EPI>
__device__ __forceinline__ void gemm_core(
    const bf16* Ahi, const bf16* Alo, const bf16* Bhi, const bf16* Blo,
    const float* bias, float* C, __half* Chi,
    float scale, int Ntot, int m0, int n0, char* smem)
{
    constexpr int MF = BM / 64;
    constexpr int WN = BN / 2;
    constexpr int NF = WN / 8;
    constexpr uint32_t ROWB = 144;
    constexpr uint32_t OAL = BM * ROWB;
    constexpr uint32_t OBH = 2 * BM * ROWB;
    constexpr uint32_t OBL = OBH + BN * ROWB;
    constexpr uint32_t STAGE = (2 * BM + 2 * BN) * ROWB;
    constexpr int NCH = KDIM / 64;

    const uint32_t uS = smem_u32(smem);
    const int tid = threadIdx.x;
    const int wid = tid >> 5, lane = tid & 31;
    const int warp_m = wid & 3, warp_n = wid >> 2;
    const int lrow = lane & 15;
    const int lcol = (lane >> 4) * 8;

    const bf16* a_hi = Ahi + (size_t)m0 * KDIM;
    const bf16* a_lo = Alo + (size_t)m0 * KDIM;
    const bf16* b_hi = Bhi + (size_t)n0 * KDIM;
    const bf16* b_lo = Blo + (size_t)n0 * KDIM;

    auto issue = [&](int ch, int buf) {
        const int k0 = ch * 64;
        const uint32_t base = uS + (uint32_t)buf * STAGE;
#pragma unroll
        for (int i = tid; i < BM * 8; i += 256) {
            const int r = i >> 3, c8 = (i & 7) * 8;
            const uint32_t so = (uint32_t)r * ROWB + c8 * 2;
            const size_t g = (size_t)r * KDIM + k0 + c8;
            cp16(base + so, a_hi + g);
            cp16(base + OAL + so, a_lo + g);
        }
#pragma unroll
        for (int i = tid; i < BN * 8; i += 256) {
            const int r = i >> 3, c8 = (i & 7) * 8;
            const uint32_t so = (uint32_t)r * ROWB + c8 * 2;
            const size_t g = (size_t)r * KDIM + k0 + c8;
            cp16(base + OBH + so, b_hi + g);
            cp16(base + OBL + so, b_lo + g);
        }
    };

    float acc[MF][NF][4] = {};

    issue(0, 0);
    cp_commit();

    for (int ch = 0; ch < NCH; ch++) {
        if (ch + 1 < NCH) {
            issue(ch + 1, (ch + 1) & 1);
            cp_commit();
            cp_wait1();
        } else {
            cp_wait0();
        }
        __syncthreads();

        const uint32_t base = uS + (uint32_t)(ch & 1) * STAGE;
#pragma unroll
        for (int ks = 0; ks < 4; ks++) {
            const int kk = ks * 16 + lcol;
            uint32_t ah[MF][4], al[MF][4];
#pragma unroll
            for (int mf = 0; mf < MF; mf++) {
                const int row = warp_m * (BM / 4) + mf * 16 + lrow;
                const uint32_t off = (uint32_t)row * ROWB + kk * 2;
                ldsm_x4(ah[mf], base + off);
                ldsm_x4(al[mf], base + OAL + off);
            }
            uint32_t bh[NF][2], bl[NF][2];
#pragma unroll
            for (int p = 0; p < NF / 2; p++) {
                const int row = warp_n * WN + p * 16 + lrow;
                const uint32_t off = (uint32_t)row * ROWB + kk * 2;
                uint32_t r4[4];
                ldsm_x4(r4, base + OBH + off);
                bh[2 * p][0] = r4[0]; bh[2 * p][1] = r4[2];
                bh[2 * p + 1][0] = r4[1]; bh[2 * p + 1][1] = r4[3];
                ldsm_x4(r4, base + OBL + off);
                bl[2 * p][0] = r4[0]; bl[2 * p][1] = r4[2];
                bl[2 * p + 1][0] = r4[1]; bl[2 * p + 1][1] = r4[3];
            }
#pragma unroll
            for (int mf = 0; mf < MF; mf++)
#pragma unroll
                for (int nf = 0; nf < NF; nf++) {
                    mma_bf16(acc[mf][nf], ah[mf], bh[nf]);
                    mma_bf16(acc[mf][nf], ah[mf], bl[nf]);
                    mma_bf16(acc[mf][nf], al[mf], bh[nf]);
                }
        }
        __syncthreads();
    }

    const int gid = lane >> 2, t4 = lane & 3;
#pragma unroll
    for (int mf = 0; mf < MF; mf++) {
        const int row = m0 + warp_m * (BM / 4) + mf * 16 + gid;
#pragma unroll
        for (int nf = 0; nf < NF; nf++) {
            const int col = n0 + warp_n * WN + nf * 8 + t4 * 2;
            const float b0 = bias[col], b1 = bias[col + 1];
            if (EPI == 0) {
                float2 o0 = make_float2(acc[mf][nf][0] + b0, acc[mf][nf][1] + b1);
                float2 o1 = make_float2(acc[mf][nf][2] + b0, acc[mf][nf][3] + b1);
                *(float2*)(C + (size_t)row * Ntot + col) = o0;
                *(float2*)(C + (size_t)(row + 8) * Ntot + col) = o1;
            } else {
                *(uint32_t*)(Chi + (size_t)row * Ntot + col) =
                    pack_h2((acc[mf][nf][0] + b0) * scale,
                            (acc[mf][nf][1] + b1) * scale);
                *(uint32_t*)(Chi + (size_t)(row + 8) * Ntot + col) =
                    pack_h2((acc[mf][nf][2] + b0) * scale,
                            (acc[mf][nf][3] + b1) * scale);
            }
        }
    }
}

template <int BM, int BN, int EPI>
__global__ __launch_bounds__(256) void gemm_mma(
    const bf16* __restrict__ Ahi, const bf16* __restrict__ Alo,
    const bf16* __restrict__ Bhi, const bf16* __restrict__ Blo,
    const float* __restrict__ bias, float* __restrict__ C,
    __half* __restrict__ Chi, float scale, int Ntot)
{
    extern __shared__ char smem[];
    gemm_core<BM, BN, EPI>(Ahi, Alo, Bhi, Blo, bias, C, Chi, scale, Ntot,
                           blockIdx.y * BM, blockIdx.x * BN, smem);
}

// fused K+V projection (identical shapes): grid.z selects operand set
struct KVArgs {
    const bf16* Ahi[2]; const bf16* Alo[2];
    const bf16* Bhi[2]; const bf16* Blo[2];
    const float* bias[2]; __half* Chi[2];
};
__global__ __launch_bounds__(256) void gemm_mma_kv(KVArgs a)
{
    extern __shared__ char smem[];
    const int z = blockIdx.z;
    gemm_core<64, 64, 2>(a.Ahi[z], a.Alo[z], a.Bhi[z], a.Blo[z], a.bias[z],
                         nullptr, a.Chi[z], 1.0f, HDIM,
                         blockIdx.y * 64, blockIdx.x * 64, smem);
}

// ---------------------------------------------------------------------------
// Tensor-core MQA attention, pure single-fp16:
//   scores = Q·K (1 term);  PV = P·V (1 term)
// Block = 128 queries x (head, batch); 8 warps x 16-row strips; KBLK=64.
// cp.async double-buffered stages of {K, V}.
// ---------------------------------------------------------------------------
__global__ __launch_bounds__(256) void mqa_attn_mma(
    const __half* __restrict__ Qhi,
    const __half* __restrict__ Khi, const __half* __restrict__ Vhi,
    bf16* __restrict__ Ohi, bf16* __restrict__ Olo)
{
    constexpr uint32_t ROWB = 144;
    constexpr uint32_t ST0 = 128 * ROWB;          // 18432: end of Q region
    constexpr uint32_t STG = 128 * ROWB;          // 18432: stage {K, V}
    constexpr uint32_t VHI = 64 * ROWB;
    constexpr int NCH = SEQ / 64;                 // 32

    extern __shared__ char smc[];
    const uint32_t uS = smem_u32(smc);

    const int tid = threadIdx.x, wid = tid >> 5, lane = tid & 31;
    const int h = blockIdx.y, b = blockIdx.z;
    const int q0 = blockIdx.x * 128;
    const size_t qrow0 = (size_t)b * SEQ + q0;
    const int lrow = lane & 15;
    const int lcol = (lane >> 4) * 8;

    const __half* kh_g = Khi + (size_t)b * SEQ * HDIM;
    const __half* vh_g = Vhi + (size_t)b * SEQ * HDIM;

    auto issue = [&](int ch, int buf) {
        const int k0 = ch * 64;
        const uint32_t base = uS + ST0 + (uint32_t)buf * STG;
#pragma unroll
        for (int i = tid; i < 64 * 8; i += 256) {
            const int r = i >> 3, c8 = (i & 7) * 8;
            const uint32_t so = (uint32_t)r * ROWB + c8 * 2;
            const size_t g = (size_t)(k0 + r) * HDIM + c8;
            cp16(base + so, kh_g + g);
            cp16(base + VHI + so, vh_g + g);
        }
    };

    issue(0, 0);
    cp_commit();
    {
        const __half* qh_g = Qhi + qrow0 * HID_DIM + h * HDIM;
#pragma unroll
        for (int i = tid; i < 128 * 8; i += 256) {
            const int r = i >> 3, c8 = (i & 7) * 8;
            const uint32_t so = (uint32_t)r * ROWB + c8 * 2;
            *(uint4*)(smc + so) = *(const uint4*)(qh_g + (size_t)r * HID_DIM + c8);
        }
    }
    __syncthreads();
    uint32_t qh[4][4];
#pragma unroll
    for (int ks = 0; ks < 4; ks++) {
        const uint32_t off = (uint32_t)(wid * 16 + lrow) * ROWB + (ks * 16 + lcol) * 2;
        ldsm_x4(qh[ks], uS + off);
    }

    float m1 = -1e30f, m2 = -1e30f, lp1 = 0.0f, lp2 = 0.0f;
    float oacc[8][4] = {};

    for (int ch = 0; ch < NCH; ch++) {
        if (ch + 1 < NCH) {
            issue(ch + 1, (ch + 1) & 1);
            cp_commit();
            cp_wait1();
        } else {
            cp_wait0();
        }
        __syncthreads();

        const uint32_t base = uS + ST0 + (uint32_t)(ch & 1) * STG;

        // ---- scores: 16 rows x 64 keys; single term Q x K
        float sc[8][4] = {};
#pragma unroll
        for (int ks = 0; ks < 4; ks++) {
#pragma unroll
            for (int p = 0; p < 4; p++) {
                const uint32_t off =
                    (uint32_t)(p * 16 + lrow) * ROWB + (ks * 16 + lcol) * 2;
                uint32_t rh[4];
                ldsm_x4(rh, base + off);
                uint32_t b0[2] = {rh[0], rh[2]}, b1[2] = {rh[1], rh[3]};
                mma_f16(sc[2 * p], qh[ks], b0);
                mma_f16(sc[2 * p + 1], qh[ks], b1);
            }
        }

        // ---- online softmax in registers
        float mx1 = m1, mx2 = m2;
#pragma unroll
        for (int nf = 0; nf < 8; nf++) {
            mx1 = fmaxf(mx1, fmaxf(sc[nf][0], sc[nf][1]));
            mx2 = fmaxf(mx2, fmaxf(sc[nf][2], sc[nf][3]));
        }
        mx1 = fmaxf(mx1, __shfl_xor_sync(0xffffffffu, mx1, 1));
        mx1 = fmaxf(mx1, __shfl_xor_sync(0xffffffffu, mx1, 2));
        mx2 = fmaxf(mx2, __shfl_xor_sync(0xffffffffu, mx2, 1));
        mx2 = fmaxf(mx2, __shfl_xor_sync(0xffffffffu, mx2, 2));
        const float a1 = __expf(m1 - mx1);
        const float a2 = __expf(m2 - mx2);
        m1 = mx1; m2 = mx2;

        float s1 = 0.0f, s2 = 0.0f;
        uint32_t pr1[8], pr2[8];
#pragma unroll
        for (int nf = 0; nf < 8; nf++) {
            const float p0 = __expf(sc[nf][0] - mx1);
            const float p1 = __expf(sc[nf][1] - mx1);
            const float p2 = __expf(sc[nf][2] - mx2);
            const float p3 = __expf(sc[nf][3] - mx2);
            s1 += p0 + p1; s2 += p2 + p3;
            pr1[nf] = pack_h2(p0, p1);
            pr2[nf] = pack_h2(p2, p3);
        }
        lp1 = lp1 * a1 + s1;
        lp2 = lp2 * a2 + s2;
#pragma unroll
        for (int nf = 0; nf < 8; nf++) {
            oacc[nf][0] *= a1; oacc[nf][1] *= a1;
            oacc[nf][2] *= a2; oacc[nf][3] *= a2;
        }

        // ---- PV: single term (P fp16 x V fp16)
#pragma unroll
        for (int ks = 0; ks < 4; ks++) {
            uint32_t pa[4] = {pr1[2 * ks], pr2[2 * ks],
                              pr1[2 * ks + 1], pr2[2 * ks + 1]};
#pragma unroll
            for (int p = 0; p < 4; p++) {
                const uint32_t off =
                    (uint32_t)(ks * 16 + lrow) * ROWB + (p * 16 + lcol) * 2;
                uint32_t rh[4];
                ldsm_x4_t(rh, base + VHI + off);
                uint32_t b0[2] = {rh[0], rh[1]}, b1[2] = {rh[2], rh[3]};
                mma_f16(oacc[2 * p], pa, b0);
                mma_f16(oacc[2 * p + 1], pa, b1);
            }
        }
        __syncthreads();
    }

    lp1 += __shfl_xor_sync(0xffffffffu, lp1, 1);
    lp1 += __shfl_xor_sync(0xffffffffu, lp1, 2);
    lp2 += __shfl_xor_sync(0xffffffffu, lp2, 1);
    lp2 += __shfl_xor_sync(0xffffffffu, lp2, 2);
    const float i1 = 1.0f / lp1, i2 = 1.0f / lp2;

    const size_t row1 = qrow0 + wid * 16 + (lane >> 2);
    const size_t row2 = row1 + 8;
#pragma unroll
    for (int nf = 0; nf < 8; nf++) {
        const int col = h * HDIM + nf * 8 + (lane & 3) * 2;
        uint32_t hp, lp;
        split_pack(oacc[nf][0] * i1, oacc[nf][1] * i1, hp, lp);
        *(uint32_t*)(Ohi + row1 * HID_DIM + col) = hp;
        *(uint32_t*)(Olo + row1 * HID_DIM + col) = lp;
        split_pack(oacc[nf][2] * i2, oacc[nf][3] * i2, hp, lp);
        *(uint32_t*)(Ohi + row2 * HID_DIM + col) = hp;
        *(uint32_t*)(Olo + row2 * HID_DIM + col) = lp;
    }
}

static const int GEMM128_SMEM = 2 * (2 * 128 + 2 * 128) * 144;  // 147456
static const int GEMM64_SMEM  = 2 * (2 * 64 + 2 * 64) * 144;    // 73728
static const int ATTN_SMEM    = 128 * 144 + 2 * 128 * 144;      // 55296

// ---------------------------------------------------------------------------
// Launch
// ---------------------------------------------------------------------------
extern "C" void kernel_launch(void* const* d_in, const int* in_sizes, int n_in,
                              void* d_out, int out_size)
{
    const float* query = (const float*)d_in[0];
    const float* key   = (const float*)d_in[1];
    const float* value = (const float*)d_in[2];
    const float* Wq    = (const float*)d_in[3];
    const float* bq    = (const float*)d_in[4];
    const float* Wk    = (const float*)d_in[5];
    const float* bk    = (const float*)d_in[6];
    const float* Wv    = (const float*)d_in[7];
    const float* bv    = (const float*)d_in[8];
    const float* Wo    = (const float*)d_in[9];
    const float* bo    = (const float*)d_in[10];
    float* out = (float*)d_out;

    void *qh, *ql, *kh, *kl, *vh, *vl;
    void *wqh, *wql, *wkh, *wkl, *wvh, *wvl, *woh, *wol;
    void *qph, *kph, *vph, *oh, *ol;
    cudaGetSymbolAddress(&qh, g_qhi); cudaGetSymbolAddress(&ql, g_qlo);
    cudaGetSymbolAddress(&kh, g_khi); cudaGetSymbolAddress(&kl, g_klo);
    cudaGetSymbolAddress(&vh, g_vhi); cudaGetSymbolAddress(&vl, g_vlo);
    cudaGetSymbolAddress(&wqh, g_WqThi); cudaGetSymbolAddress(&wql, g_WqTlo);
    cudaGetSymbolAddress(&wkh, g_WkThi); cudaGetSymbolAddress(&wkl, g_WkTlo);
    cudaGetSymbolAddress(&wvh, g_WvThi); cudaGetSymbolAddress(&wvl, g_WvTlo);
    cudaGetSymbolAddress(&woh, g_WoThi); cudaGetSymbolAddress(&wol, g_WoTlo);
    cudaGetSymbolAddress(&qph, g_qPhi);
    cudaGetSymbolAddress(&kph, g_kPhi);
    cudaGetSymbolAddress(&vph, g_vPhi);
    cudaGetSymbolAddress(&oh, g_ohi);   cudaGetSymbolAddress(&ol, g_olo);

    cudaFuncSetAttribute((const void*)gemm_mma<128, 128, 0>,
                         cudaFuncAttributeMaxDynamicSharedMemorySize, GEMM128_SMEM);
    cudaFuncSetAttribute((const void*)gemm_mma<128, 128, 2>,
                         cudaFuncAttributeMaxDynamicSharedMemorySize, GEMM128_SMEM);
    cudaFuncSetAttribute((const void*)gemm_mma_kv,
                         cudaFuncAttributeMaxDynamicSharedMemorySize, GEMM64_SMEM);
    cudaFuncSetAttribute((const void*)mqa_attn_mma,
                         cudaFuncAttributeMaxDynamicSharedMemorySize, ATTN_SMEM);

    // --- prep ---
    {
        dim3 blk(32, 8);
        transpose_split_w<<<dim3(HID_DIM / 32, KDIM / 32), blk>>>(
            Wq, (bf16*)wqh, (bf16*)wql, KDIM, HID_DIM);
        TW2 tw;
        tw.W[0] = Wk; tw.Thi[0] = (bf16*)wkh; tw.Tlo[0] = (bf16*)wkl;
        tw.W[1] = Wv; tw.Thi[1] = (bf16*)wvh; tw.Tlo[1] = (bf16*)wvl;
        transpose_split_w2<<<dim3(HDIM / 32, KDIM / 32, 2), blk>>>(tw, KDIM, HDIM);
        transpose_split_w<<<dim3(IN_DIM / 32, KDIM / 32), blk>>>(
            Wo, (bf16*)woh, (bf16*)wol, KDIM, IN_DIM);

        const int n4 = MROWS * KDIM / 4;
        SR3 sr;
        sr.X[0] = (const float4*)query; sr.hi[0] = (uint2*)qh; sr.lo[0] = (uint2*)ql;
        sr.X[1] = (const float4*)key;   sr.hi[1] = (uint2*)kh; sr.lo[1] = (uint2*)kl;
        sr.X[2] = (const float4*)value; sr.hi[2] = (uint2*)vh; sr.lo[2] = (uint2*)vl;
        split_rows3<<<dim3((n4 + 255) / 256, 3), 256>>>(sr, n4);
    }
    // --- projections (fp16 hi-only epilogues; Q pre-scaled by 1/32) ---
    gemm_mma<128, 128, 2><<<dim3(HID_DIM / 128, MROWS / 128), 256, GEMM128_SMEM>>>(
        (const bf16*)qh, (const bf16*)ql, (const bf16*)wqh, (const bf16*)wql,
        bq, nullptr, (__half*)qph, 1.0f / 32.0f, HID_DIM);
    {
        KVArgs a;
        a.Ahi[0] = (const bf16*)kh; a.Alo[0] = (const bf16*)kl;
        a.Bhi[0] = (const bf16*)wkh; a.Blo[0] = (const bf16*)wkl;
        a.bias[0] = bk; a.Chi[0] = (__half*)kph;
        a.Ahi[1] = (const bf16*)vh; a.Alo[1] = (const bf16*)vl;
        a.Bhi[1] = (const bf16*)wvh; a.Blo[1] = (const bf16*)wvl;
        a.bias[1] = bv; a.Chi[1] = (__half*)vph;
        gemm_mma_kv<<<dim3(1, MROWS / 64, 2), 256, GEMM64_SMEM>>>(a);
    }

    // --- tensor-core attention (pure fp16) ---
    {
        dim3 grid(SEQ / 128, NHEAD, BATCH);
        mqa_attn_mma<<<grid, 256, ATTN_SMEM>>>(
            (const __half*)qph, (const __half*)kph, (const __half*)vph,
            (bf16*)oh, (bf16*)ol);
    }

    // --- O-projection -> d_out (fp32 + bias) ---
    gemm_mma<128, 128, 0><<<dim3(IN_DIM / 128, MROWS / 128), 256, GEMM128_SMEM>>>(
        (const bf16*)oh, (const bf16*)ol, (const bf16*)woh, (const bf16*)wol,
        bo, out, nullptr, 1.0f, IN_DIM);
}

// round 12
// speedup vs baseline: 5.0056x; 1.0586x over previous
#include <cuda_runtime.h>
#include <cuda_bf16.h>
#include <cuda_fp16.h>
#include <cstdint>

typedef __nv_bfloat16 bf16;

#define BATCH 2
#define SEQ 2048
#define IN_DIM 1024
#define HID_DIM 1024
#define NHEAD 16
#define HDIM 64
#define KDIM 1024
#define MROWS 4096

// ---------------------------------------------------------------------------
// Scratch (__device__ globals; allocation-free rule)
// ---------------------------------------------------------------------------
__device__ bf16 g_qhi[MROWS * KDIM], g_qlo[MROWS * KDIM];
__device__ bf16 g_khi[MROWS * KDIM], g_klo[MROWS * KDIM];
__device__ bf16 g_vhi[MROWS * KDIM], g_vlo[MROWS * KDIM];
__device__ bf16 g_WqThi[HID_DIM * KDIM], g_WqTlo[HID_DIM * KDIM];
__device__ bf16 g_WkThi[HDIM * KDIM],   g_WkTlo[HDIM * KDIM];
__device__ bf16 g_WvThi[HDIM * KDIM],   g_WvTlo[HDIM * KDIM];
__device__ bf16 g_WoThi[IN_DIM * KDIM], g_WoTlo[IN_DIM * KDIM];
// projected fp16 operands for attention (all single fp16): Q scaled by 1/32
__device__ __half g_qPhi[MROWS * HID_DIM];
__device__ __half g_kPhi[MROWS * HDIM];
__device__ __half g_vPhi[MROWS * HDIM];
// attention output, bf16 split (A operand of O-projection)
__device__ bf16 g_ohi[MROWS * HID_DIM], g_olo[MROWS * HID_DIM];

// ---------------------------------------------------------------------------
// PTX helpers (all sm_80-era; legal in family-generic PTX)
// ---------------------------------------------------------------------------
__device__ __forceinline__ uint32_t smem_u32(const void* p) {
    uint32_t a;
    asm("{ .reg .u64 t; cvta.to.shared.u64 t, %1; cvt.u32.u64 %0, t; }"
        : "=r"(a) : "l"(p));
    return a;
}
__device__ __forceinline__ void ldsm_x4(uint32_t* r, uint32_t addr) {
    asm volatile("ldmatrix.sync.aligned.m8n8.x4.shared.b16 {%0,%1,%2,%3}, [%4];"
                 : "=r"(r[0]), "=r"(r[1]), "=r"(r[2]), "=r"(r[3]) : "r"(addr));
}
__device__ __forceinline__ void ldsm_x4_t(uint32_t* r, uint32_t addr) {
    asm volatile("ldmatrix.sync.aligned.m8n8.x4.trans.shared.b16 {%0,%1,%2,%3}, [%4];"
                 : "=r"(r[0]), "=r"(r[1]), "=r"(r[2]), "=r"(r[3]) : "r"(addr));
}
__device__ __forceinline__ void mma_bf16(float* d, const uint32_t* a,
                                         const uint32_t* b) {
    asm volatile(
        "mma.sync.aligned.m16n8k16.row.col.f32.bf16.bf16.f32 "
        "{%0,%1,%2,%3}, {%4,%5,%6,%7}, {%8,%9}, {%0,%1,%2,%3};"
        : "+f"(d[0]), "+f"(d[1]), "+f"(d[2]), "+f"(d[3])
        : "r"(a[0]), "r"(a[1]), "r"(a[2]), "r"(a[3]), "r"(b[0]), "r"(b[1]));
}
__device__ __forceinline__ void mma_f16(float* d, const uint32_t* a,
                                        const uint32_t* b) {
    asm volatile(
        "mma.sync.aligned.m16n8k16.row.col.f32.f16.f16.f32 "
        "{%0,%1,%2,%3}, {%4,%5,%6,%7}, {%8,%9}, {%0,%1,%2,%3};"
        : "+f"(d[0]), "+f"(d[1]), "+f"(d[2]), "+f"(d[3])
        : "r"(a[0]), "r"(a[1]), "r"(a[2]), "r"(a[3]), "r"(b[0]), "r"(b[1]));
}
__device__ __forceinline__ void cp16(uint32_t smem, const void* g) {
    asm volatile("cp.async.cg.shared.global [%0], [%1], 16;"
                 :: "r"(smem), "l"(g));
}
__device__ __forceinline__ void cp_commit() {
    asm volatile("cp.async.commit_group;" ::: "memory");
}
__device__ __forceinline__ void cp_wait1() {
    asm volatile("cp.async.wait_group 1;" ::: "memory");
}
__device__ __forceinline__ void cp_wait0() {
    asm volatile("cp.async.wait_group 0;" ::: "memory");
}
__device__ __forceinline__ void split_pack(float e, float o,
                                           uint32_t& hp, uint32_t& lp) {
    const bf16 he = __float2bfloat16(e), ho = __float2bfloat16(o);
    const bf16 le = __float2bfloat16(e - __bfloat162float(he));
    const bf16 lo2 = __float2bfloat16(o - __bfloat162float(ho));
    __nv_bfloat162 H(he, ho), L(le, lo2);
    hp = *reinterpret_cast<uint32_t*>(&H);
    lp = *reinterpret_cast<uint32_t*>(&L);
}
__device__ __forceinline__ uint32_t pack_h2(float e, float o) {
    __half2 P(__float2half_rn(e), __float2half_rn(o));
    return *reinterpret_cast<uint32_t*>(&P);
}
__device__ __forceinline__ uint32_t pack_b2(float e, float o) {
    __nv_bfloat162 P(__float2bfloat16(e), __float2bfloat16(o));
    return *reinterpret_cast<uint32_t*>(&P);
}

// ---------------------------------------------------------------------------
// Prep kernels
// ---------------------------------------------------------------------------
__device__ __forceinline__ void tsw_body(const float* W, bf16* Thi, bf16* Tlo,
                                         int K, int N)
{
    __shared__ float t[32][33];
    const int n0 = blockIdx.x * 32, k0 = blockIdx.y * 32;
    const int tx = threadIdx.x, ty = threadIdx.y;
#pragma unroll
    for (int i = 0; i < 32; i += 8)
        t[ty + i][tx] = W[(size_t)(k0 + ty + i) * N + n0 + tx];
    __syncthreads();
#pragma unroll
    for (int i = 0; i < 32; i += 8) {
        const float v = t[tx][ty + i];
        const bf16 h = __float2bfloat16(v);
        const bf16 l = __float2bfloat16(v - __bfloat162float(h));
        const size_t idx = (size_t)(n0 + ty + i) * K + k0 + tx;
        Thi[idx] = h;
        Tlo[idx] = l;
    }
}
struct TW2 { const float* W[2]; bf16* Thi[2]; bf16* Tlo[2]; };
__global__ void transpose_split_w2(TW2 a, int K, int N)
{
    const int z = blockIdx.z;
    tsw_body(a.W[z], a.Thi[z], a.Tlo[z], K, N);
}

// vectorized hi/lo split: 8 fp32 in (2x float4), uint4 hi + uint4 lo out
struct SR3 { const float4* X[3]; uint4* hi[3]; uint4* lo[3]; };
__global__ void split_rows3(SR3 a, int n8)
{
    const int z = blockIdx.y;
    const int i = blockIdx.x * blockDim.x + threadIdx.x;
    if (i < n8) {
        const float4 v0 = a.X[z][2 * i];
        const float4 v1 = a.X[z][2 * i + 1];
        const bf16 h0 = __float2bfloat16(v0.x), h1 = __float2bfloat16(v0.y);
        const bf16 h2 = __float2bfloat16(v0.z), h3 = __float2bfloat16(v0.w);
        const bf16 h4 = __float2bfloat16(v1.x), h5 = __float2bfloat16(v1.y);
        const bf16 h6 = __float2bfloat16(v1.z), h7 = __float2bfloat16(v1.w);
        uint4 H, L;
        H.x = pack_b2(v0.x, v0.y);
        H.y = pack_b2(v0.z, v0.w);
        H.z = pack_b2(v1.x, v1.y);
        H.w = pack_b2(v1.z, v1.w);
        L.x = pack_b2(v0.x - __bfloat162float(h0), v0.y - __bfloat162float(h1));
        L.y = pack_b2(v0.z - __bfloat162float(h2), v0.w - __bfloat162float(h3));
        L.z = pack_b2(v1.x - __bfloat162float(h4), v1.y - __bfloat162float(h5));
        L.w = pack_b2(v1.z - __bfloat162float(h6), v1.w - __bfloat162float(h7));
        a.hi[z][i] = H;
        a.lo[z][i] = L;
    }
}

// ---------------------------------------------------------------------------
// cp.async double-buffered mma.sync bf16 3-term split GEMM core.
// EPI=0: fp32 C=acc+bias.  EPI=2: fp16 hi-only Chi=(acc+bias)*scale.
// ---------------------------------------------------------------------------
template <int BM, int BN, int EPI>
__device__ __forceinline__ void gemm_core(
    const bf16* Ahi, const bf16* Alo, const bf16* Bhi, const bf16* Blo,
    const float* bias, float* C, __half* Chi,
    float scale, int Ntot, int m0, int n0, char* smem)
{
    constexpr int MF = BM / 64;
    constexpr int WN = BN / 2;
    constexpr int NF = WN / 8;
    constexpr uint32_t ROWB = 144;
    constexpr uint32_t OAL = BM * ROWB;
    constexpr uint32_t OBH = 2 * BM * ROWB;
    constexpr uint32_t OBL = OBH + BN * ROWB;
    constexpr uint32_t STAGE = (2 * BM + 2 * BN) * ROWB;
    constexpr int NCH = KDIM / 64;

    const uint32_t uS = smem_u32(smem);
    const int tid = threadIdx.x;
    const int wid = tid >> 5, lane = tid & 31;
    const int warp_m = wid & 3, warp_n = wid >> 2;
    const int lrow = lane & 15;
    const int lcol = (lane >> 4) * 8;

    const bf16* a_hi = Ahi + (size_t)m0 * KDIM;
    const bf16* a_lo = Alo + (size_t)m0 * KDIM;
    const bf16* b_hi = Bhi + (size_t)n0 * KDIM;
    const bf16* b_lo = Blo + (size_t)n0 * KDIM;

    auto issue = [&](int ch, int buf) {
        const int k0 = ch * 64;
        const uint32_t base = uS + (uint32_t)buf * STAGE;
#pragma unroll
        for (int i = tid; i < BM * 8; i += 256) {
            const int r = i >> 3, c8 = (i & 7) * 8;
            const uint32_t so = (uint32_t)r * ROWB + c8 * 2;
            const size_t g = (size_t)r * KDIM + k0 + c8;
            cp16(base + so, a_hi + g);
            cp16(base + OAL + so, a_lo + g);
        }
#pragma unroll
        for (int i = tid; i < BN * 8; i += 256) {
            const int r = i >> 3, c8 = (i & 7) * 8;
            const uint32_t so = (uint32_t)r * ROWB + c8 * 2;
            const size_t g = (size_t)r * KDIM + k0 + c8;
            cp16(base + OBH + so, b_hi + g);
            cp16(base + OBL + so, b_lo + g);
        }
    };

    float acc[MF][NF][4] = {};

    issue(0, 0);
    cp_commit();

    for (int ch = 0; ch < NCH; ch++) {
        if (ch + 1 < NCH) {
            issue(ch + 1, (ch + 1) & 1);
            cp_commit();
            cp_wait1();
        } else {
            cp_wait0();
        }
        __syncthreads();

        const uint32_t base = uS + (uint32_t)(ch & 1) * STAGE;
#pragma unroll
        for (int ks = 0; ks < 4; ks++) {
            const int kk = ks * 16 + lcol;
            uint32_t ah[MF][4], al[MF][4];
#pragma unroll
            for (int mf = 0; mf < MF; mf++) {
                const int row = warp_m * (BM / 4) + mf * 16 + lrow;
                const uint32_t off = (uint32_t)row * ROWB + kk * 2;
                ldsm_x4(ah[mf], base + off);
                ldsm_x4(al[mf], base + OAL + off);
            }
            uint32_t bh[NF][2], bl[NF][2];
#pragma unroll
            for (int p = 0; p < NF / 2; p++) {
                const int row = warp_n * WN + p * 16 + lrow;
                const uint32_t off = (uint32_t)row * ROWB + kk * 2;
                uint32_t r4[4];
                ldsm_x4(r4, base + OBH + off);
                bh[2 * p][0] = r4[0]; bh[2 * p][1] = r4[2];
                bh[2 * p + 1][0] = r4[1]; bh[2 * p + 1][1] = r4[3];
                ldsm_x4(r4, base + OBL + off);
                bl[2 * p][0] = r4[0]; bl[2 * p][1] = r4[2];
                bl[2 * p + 1][0] = r4[1]; bl[2 * p + 1][1] = r4[3];
            }
#pragma unroll
            for (int mf = 0; mf < MF; mf++)
#pragma unroll
                for (int nf = 0; nf < NF; nf++) {
                    mma_bf16(acc[mf][nf], ah[mf], bh[nf]);
                    mma_bf16(acc[mf][nf], ah[mf], bl[nf]);
                    mma_bf16(acc[mf][nf], al[mf], bh[nf]);
                }
        }
        __syncthreads();
    }

    const int gid = lane >> 2, t4 = lane & 3;
#pragma unroll
    for (int mf = 0; mf < MF; mf++) {
        const int row = m0 + warp_m * (BM / 4) + mf * 16 + gid;
#pragma unroll
        for (int nf = 0; nf < NF; nf++) {
            const int col = n0 + warp_n * WN + nf * 8 + t4 * 2;
            const float b0 = bias[col], b1 = bias[col + 1];
            if (EPI == 0) {
                float2 o0 = make_float2(acc[mf][nf][0] + b0, acc[mf][nf][1] + b1);
                float2 o1 = make_float2(acc[mf][nf][2] + b0, acc[mf][nf][3] + b1);
                *(float2*)(C + (size_t)row * Ntot + col) = o0;
                *(float2*)(C + (size_t)(row + 8) * Ntot + col) = o1;
            } else {
                *(uint32_t*)(Chi + (size_t)row * Ntot + col) =
                    pack_h2((acc[mf][nf][0] + b0) * scale,
                            (acc[mf][nf][1] + b1) * scale);
                *(uint32_t*)(Chi + (size_t)(row + 8) * Ntot + col) =
                    pack_h2((acc[mf][nf][2] + b0) * scale,
                            (acc[mf][nf][3] + b1) * scale);
            }
        }
    }
}

template <int BM, int BN, int EPI>
__global__ __launch_bounds__(256) void gemm_mma(
    const bf16* __restrict__ Ahi, const bf16* __restrict__ Alo,
    const bf16* __restrict__ Bhi, const bf16* __restrict__ Blo,
    const float* __restrict__ bias, float* __restrict__ C,
    __half* __restrict__ Chi, float scale, int Ntot)
{
    extern __shared__ char smem[];
    gemm_core<BM, BN, EPI>(Ahi, Alo, Bhi, Blo, bias, C, Chi, scale, Ntot,
                           blockIdx.y * BM, blockIdx.x * BN, smem);
}

// ---------------------------------------------------------------------------
// Merged Q/K/V projection launch. grid (8, 32, 3):
//   z=0: Q-proj 128x128 tiles (all 256 x-y CTAs active)
//   z=1: K-proj 64x64 tiles (first 64 linearized CTAs active)
//   z=2: V-proj likewise
// ---------------------------------------------------------------------------
struct ProjArgs {
    const bf16 *qAhi, *qAlo, *qBhi, *qBlo; const float* qb; __half* qC;
    const bf16 *kvAhi[2], *kvAlo[2], *kvBhi[2], *kvBlo[2];
    const float* kvb[2]; __half* kvC[2];
};
__global__ __launch_bounds__(256) void gemm_proj_all(ProjArgs a)
{
    extern __shared__ char smem[];
    const int z = blockIdx.z;
    if (z == 0) {
        gemm_core<128, 128, 2>(a.qAhi, a.qAlo, a.qBhi, a.qBlo, a.qb,
                               nullptr, a.qC, 1.0f / 32.0f, HID_DIM,
                               blockIdx.y * 128, blockIdx.x * 128, smem);
    } else {
        const int id = blockIdx.y * 8 + blockIdx.x;   // 0..255
        if (id >= MROWS / 64) return;                 // 64 active
        const int s = z - 1;
        gemm_core<64, 64, 2>(a.kvAhi[s], a.kvAlo[s], a.kvBhi[s], a.kvBlo[s],
                             a.kvb[s], nullptr, a.kvC[s], 1.0f, HDIM,
                             id * 64, 0, smem);
    }
}

// ---------------------------------------------------------------------------
// Tensor-core MQA attention, pure single-fp16:
//   scores = Q·K (1 term);  PV = P·V (1 term)
// Block = 128 queries x (head, batch); 8 warps x 16-row strips; KBLK=64.
// cp.async double-buffered stages of {K, V}.
// ---------------------------------------------------------------------------
__global__ __launch_bounds__(256) void mqa_attn_mma(
    const __half* __restrict__ Qhi,
    const __half* __restrict__ Khi, const __half* __restrict__ Vhi,
    bf16* __restrict__ Ohi, bf16* __restrict__ Olo)
{
    constexpr uint32_t ROWB = 144;
    constexpr uint32_t ST0 = 128 * ROWB;          // end of Q region
    constexpr uint32_t STG = 128 * ROWB;          // stage {K, V}
    constexpr uint32_t VHI = 64 * ROWB;
    constexpr int NCH = SEQ / 64;                 // 32

    extern __shared__ char smc[];
    const uint32_t uS = smem_u32(smc);

    const int tid = threadIdx.x, wid = tid >> 5, lane = tid & 31;
    const int h = blockIdx.y, b = blockIdx.z;
    const int q0 = blockIdx.x * 128;
    const size_t qrow0 = (size_t)b * SEQ + q0;
    const int lrow = lane & 15;
    const int lcol = (lane >> 4) * 8;

    const __half* kh_g = Khi + (size_t)b * SEQ * HDIM;
    const __half* vh_g = Vhi + (size_t)b * SEQ * HDIM;

    auto issue = [&](int ch, int buf) {
        const int k0 = ch * 64;
        const uint32_t base = uS + ST0 + (uint32_t)buf * STG;
#pragma unroll
        for (int i = tid; i < 64 * 8; i += 256) {
            const int r = i >> 3, c8 = (i & 7) * 8;
            const uint32_t so = (uint32_t)r * ROWB + c8 * 2;
            const size_t g = (size_t)(k0 + r) * HDIM + c8;
            cp16(base + so, kh_g + g);
            cp16(base + VHI + so, vh_g + g);
        }
    };

    issue(0, 0);
    cp_commit();
    {
        const __half* qh_g = Qhi + qrow0 * HID_DIM + h * HDIM;
#pragma unroll
        for (int i = tid; i < 128 * 8; i += 256) {
            const int r = i >> 3, c8 = (i & 7) * 8;
            const uint32_t so = (uint32_t)r * ROWB + c8 * 2;
            *(uint4*)(smc + so) = *(const uint4*)(qh_g + (size_t)r * HID_DIM + c8);
        }
    }
    __syncthreads();
    uint32_t qh[4][4];
#pragma unroll
    for (int ks = 0; ks < 4; ks++) {
        const uint32_t off = (uint32_t)(wid * 16 + lrow) * ROWB + (ks * 16 + lcol) * 2;
        ldsm_x4(qh[ks], uS + off);
    }

    float m1 = -1e30f, m2 = -1e30f, lp1 = 0.0f, lp2 = 0.0f;
    float oacc[8][4] = {};

    for (int ch = 0; ch < NCH; ch++) {
        if (ch + 1 < NCH) {
            issue(ch + 1, (ch + 1) & 1);
            cp_commit();
            cp_wait1();
        } else {
            cp_wait0();
        }
        __syncthreads();

        const uint32_t base = uS + ST0 + (uint32_t)(ch & 1) * STG;

        // ---- scores: 16 rows x 64 keys; single term Q x K
        float sc[8][4] = {};
#pragma unroll
        for (int ks = 0; ks < 4; ks++) {
#pragma unroll
            for (int p = 0; p < 4; p++) {
                const uint32_t off =
                    (uint32_t)(p * 16 + lrow) * ROWB + (ks * 16 + lcol) * 2;
                uint32_t rh[4];
                ldsm_x4(rh, base + off);
                uint32_t b0[2] = {rh[0], rh[2]}, b1[2] = {rh[1], rh[3]};
                mma_f16(sc[2 * p], qh[ks], b0);
                mma_f16(sc[2 * p + 1], qh[ks], b1);
            }
        }

        // ---- online softmax in registers
        float mx1 = m1, mx2 = m2;
#pragma unroll
        for (int nf = 0; nf < 8; nf++) {
            mx1 = fmaxf(mx1, fmaxf(sc[nf][0], sc[nf][1]));
            mx2 = fmaxf(mx2, fmaxf(sc[nf][2], sc[nf][3]));
        }
        mx1 = fmaxf(mx1, __shfl_xor_sync(0xffffffffu, mx1, 1));
        mx1 = fmaxf(mx1, __shfl_xor_sync(0xffffffffu, mx1, 2));
        mx2 = fmaxf(mx2, __shfl_xor_sync(0xffffffffu, mx2, 1));
        mx2 = fmaxf(mx2, __shfl_xor_sync(0xffffffffu, mx2, 2));
        const float a1 = __expf(m1 - mx1);
        const float a2 = __expf(m2 - mx2);
        m1 = mx1; m2 = mx2;

        float s1 = 0.0f, s2 = 0.0f;
        uint32_t pr1[8], pr2[8];
#pragma unroll
        for (int nf = 0; nf < 8; nf++) {
            const float p0 = __expf(sc[nf][0] - mx1);
            const float p1 = __expf(sc[nf][1] - mx1);
            const float p2 = __expf(sc[nf][2] - mx2);
            const float p3 = __expf(sc[nf][3] - mx2);
            s1 += p0 + p1; s2 += p2 + p3;
            pr1[nf] = pack_h2(p0, p1);
            pr2[nf] = pack_h2(p2, p3);
        }
        lp1 = lp1 * a1 + s1;
        lp2 = lp2 * a2 + s2;
#pragma unroll
        for (int nf = 0; nf < 8; nf++) {
            oacc[nf][0] *= a1; oacc[nf][1] *= a1;
            oacc[nf][2] *= a2; oacc[nf][3] *= a2;
        }

        // ---- PV: single term (P fp16 x V fp16)
#pragma unroll
        for (int ks = 0; ks < 4; ks++) {
            uint32_t pa[4] = {pr1[2 * ks], pr2[2 * ks],
                              pr1[2 * ks + 1], pr2[2 * ks + 1]};
#pragma unroll
            for (int p = 0; p < 4; p++) {
                const uint32_t off =
                    (uint32_t)(ks * 16 + lrow) * ROWB + (p * 16 + lcol) * 2;
                uint32_t rh[4];
                ldsm_x4_t(rh, base + VHI + off);
                uint32_t b0[2] = {rh[0], rh[1]}, b1[2] = {rh[2], rh[3]};
                mma_f16(oacc[2 * p], pa, b0);
                mma_f16(oacc[2 * p + 1], pa, b1);
            }
        }
        __syncthreads();
    }

    lp1 += __shfl_xor_sync(0xffffffffu, lp1, 1);
    lp1 += __shfl_xor_sync(0xffffffffu, lp1, 2);
    lp2 += __shfl_xor_sync(0xffffffffu, lp2, 1);
    lp2 += __shfl_xor_sync(0xffffffffu, lp2, 2);
    const float i1 = 1.0f / lp1, i2 = 1.0f / lp2;

    const size_t row1 = qrow0 + wid * 16 + (lane >> 2);
    const size_t row2 = row1 + 8;
#pragma unroll
    for (int nf = 0; nf < 8; nf++) {
        const int col = h * HDIM + nf * 8 + (lane & 3) * 2;
        uint32_t hp, lp;
        split_pack(oacc[nf][0] * i1, oacc[nf][1] * i1, hp, lp);
        *(uint32_t*)(Ohi + row1 * HID_DIM + col) = hp;
        *(uint32_t*)(Olo + row1 * HID_DIM + col) = lp;
        split_pack(oacc[nf][2] * i2, oacc[nf][3] * i2, hp, lp);
        *(uint32_t*)(Ohi + row2 * HID_DIM + col) = hp;
        *(uint32_t*)(Olo + row2 * HID_DIM + col) = lp;
    }
}

static const int GEMM128_SMEM = 2 * (2 * 128 + 2 * 128) * 144;  // 147456
static const int ATTN_SMEM    = 128 * 144 + 2 * 128 * 144;      // 55296

// ---------------------------------------------------------------------------
// Launch
// ---------------------------------------------------------------------------
extern "C" void kernel_launch(void* const* d_in, const int* in_sizes, int n_in,
                              void* d_out, int out_size)
{
    const float* query = (const float*)d_in[0];
    const float* key   = (const float*)d_in[1];
    const float* value = (const float*)d_in[2];
    const float* Wq    = (const float*)d_in[3];
    const float* bq    = (const float*)d_in[4];
    const float* Wk    = (const float*)d_in[5];
    const float* bk    = (const float*)d_in[6];
    const float* Wv    = (const float*)d_in[7];
    const float* bv    = (const float*)d_in[8];
    const float* Wo    = (const float*)d_in[9];
    const float* bo    = (const float*)d_in[10];
    float* out = (float*)d_out;

    void *qh, *ql, *kh, *kl, *vh, *vl;
    void *wqh, *wql, *wkh, *wkl, *wvh, *wvl, *woh, *wol;
    void *qph, *kph, *vph, *oh, *ol;
    cudaGetSymbolAddress(&qh, g_qhi); cudaGetSymbolAddress(&ql, g_qlo);
    cudaGetSymbolAddress(&kh, g_khi); cudaGetSymbolAddress(&kl, g_klo);
    cudaGetSymbolAddress(&vh, g_vhi); cudaGetSymbolAddress(&vl, g_vlo);
    cudaGetSymbolAddress(&wqh, g_WqThi); cudaGetSymbolAddress(&wql, g_WqTlo);
    cudaGetSymbolAddress(&wkh, g_WkThi); cudaGetSymbolAddress(&wkl, g_WkTlo);
    cudaGetSymbolAddress(&wvh, g_WvThi); cudaGetSymbolAddress(&wvl, g_WvTlo);
    cudaGetSymbolAddress(&woh, g_WoThi); cudaGetSymbolAddress(&wol, g_WoTlo);
    cudaGetSymbolAddress(&qph, g_qPhi);
    cudaGetSymbolAddress(&kph, g_kPhi);
    cudaGetSymbolAddress(&vph, g_vPhi);
    cudaGetSymbolAddress(&oh, g_ohi);   cudaGetSymbolAddress(&ol, g_olo);

    cudaFuncSetAttribute((const void*)gemm_mma<128, 128, 0>,
                         cudaFuncAttributeMaxDynamicSharedMemorySize, GEMM128_SMEM);
    cudaFuncSetAttribute((const void*)gemm_proj_all,
                         cudaFuncAttributeMaxDynamicSharedMemorySize, GEMM128_SMEM);
    cudaFuncSetAttribute((const void*)mqa_attn_mma,
                         cudaFuncAttributeMaxDynamicSharedMemorySize, ATTN_SMEM);

    // --- prep ---
    {
        dim3 blk(32, 8);
        TW2 tqo;
        tqo.W[0] = Wq; tqo.Thi[0] = (bf16*)wqh; tqo.Tlo[0] = (bf16*)wql;
        tqo.W[1] = Wo; tqo.Thi[1] = (bf16*)woh; tqo.Tlo[1] = (bf16*)wol;
        transpose_split_w2<<<dim3(HID_DIM / 32, KDIM / 32, 2), blk>>>(tqo, KDIM, HID_DIM);
        TW2 tkv;
        tkv.W[0] = Wk; tkv.Thi[0] = (bf16*)wkh; tkv.Tlo[0] = (bf16*)wkl;
        tkv.W[1] = Wv; tkv.Thi[1] = (bf16*)wvh; tkv.Tlo[1] = (bf16*)wvl;
        transpose_split_w2<<<dim3(HDIM / 32, KDIM / 32, 2), blk>>>(tkv, KDIM, HDIM);

        const int n8 = MROWS * KDIM / 8;
        SR3 sr;
        sr.X[0] = (const float4*)query; sr.hi[0] = (uint4*)qh; sr.lo[0] = (uint4*)ql;
        sr.X[1] = (const float4*)key;   sr.hi[1] = (uint4*)kh; sr.lo[1] = (uint4*)kl;
        sr.X[2] = (const float4*)value; sr.hi[2] = (uint4*)vh; sr.lo[2] = (uint4*)vl;
        split_rows3<<<dim3((n8 + 255) / 256, 3), 256>>>(sr, n8);
    }
    // --- merged Q/K/V projections (fp16 hi-only epilogues; Q scaled 1/32) ---
    {
        ProjArgs a;
        a.qAhi = (const bf16*)qh; a.qAlo = (const bf16*)ql;
        a.qBhi = (const bf16*)wqh; a.qBlo = (const bf16*)wql;
        a.qb = bq; a.qC = (__half*)qph;
        a.kvAhi[0] = (const bf16*)kh; a.kvAlo[0] = (const bf16*)kl;
        a.kvBhi[0] = (const bf16*)wkh; a.kvBlo[0] = (const bf16*)wkl;
        a.kvb[0] = bk; a.kvC[0] = (__half*)kph;
        a.kvAhi[1] = (const bf16*)vh; a.kvAlo[1] = (const bf16*)vl;
        a.kvBhi[1] = (const bf16*)wvh; a.kvBlo[1] = (const bf16*)wvl;
        a.kvb[1] = bv; a.kvC[1] = (__half*)vph;
        gemm_proj_all<<<dim3(HID_DIM / 128, MROWS / 128, 3), 256, GEMM128_SMEM>>>(a);
    }

    // --- tensor-core attention (pure fp16) ---
    {
        dim3 grid(SEQ / 128, NHEAD, BATCH);
        mqa_attn_mma<<<grid, 256, ATTN_SMEM>>>(
            (const __half*)qph, (const __half*)kph, (const __half*)vph,
            (bf16*)oh, (bf16*)ol);
    }

    // --- O-projection -> d_out (fp32 + bias) ---
    gemm_mma<128, 128, 0><<<dim3(IN_DIM / 128, MROWS / 128), 256, GEMM128_SMEM>>>(
        (const bf16*)oh, (const bf16*)ol, (const bf16*)woh, (const bf16*)wol,
        bo, out, nullptr, 1.0f, IN_DIM);
}